// round 13
// baseline (speedup 1.0000x reference)
#include <cuda_runtime.h>
#include <cuda_fp16.h>
#include <math.h>
#include <cstdint>

// Problem constants
#define DD   1024
#define NTOK 8192      // B*T*H*W
#define NBT  32        // B*T
#define NSEQ 512       // B*H*W
#define TT   16
#define MODW 15360     // 6*DD + 6*DD + 3*DD combined ada width

// ---------------- scratch (device globals; no allocations allowed) ----------------
__device__ __half g_csh[NBT * DD];
__device__ float  g_modall[NBT * MODW];
__device__ float  g_adab[MODW];
__device__ __half g_xbufh[NTOK * DD];
__device__ __half g_h1h[NTOK * DD];
__device__ __half g_qkvh[NTOK * 3 * DD];
__device__ __half g_deltah[NTOK * DD];
__device__ __half g_mlph[NTOK * 4 * DD];
__device__ __half g_gatesxh[NTOK * 4 * DD];
__device__ __half g_hstateh[NSEQ * DD];
__device__ __half g_hstate2h[NSEQ * DD];
__device__ float  g_cstate[NSEQ * DD];
__device__ float  g_lstmbias[4 * DD];
__device__ unsigned int g_lstm_bar;
__device__ __half g_wTh[47u * 1048576u];   // transposed fp16 weights

__device__ __forceinline__ float tanh_fast(float x) {
    float r; asm("tanh.approx.f32 %0, %1;" : "=f"(r) : "f"(x)); return r;
}
__device__ __forceinline__ float gelu_tanh(float x) {
    return 0.5f * x * (1.f + tanh_fast(0.7978845608028654f * (x + 0.044715f * x * x * x)));
}
__device__ __forceinline__ float sigm(float x) { return 0.5f * (1.f + tanh_fast(0.5f * x)); }
__device__ __forceinline__ uint32_t h2_as_u32(__half2 h) {
    uint32_t u; *reinterpret_cast<__half2*>(&u) = h; return u;
}
__device__ __forceinline__ void mma_f16(float d[4], uint32_t a0, uint32_t a1, uint32_t a2,
                                        uint32_t a3, uint32_t b0, uint32_t b1) {
    asm volatile(
        "mma.sync.aligned.m16n8k16.row.col.f32.f16.f16.f32 "
        "{%0,%1,%2,%3}, {%4,%5,%6,%7}, {%8,%9}, {%0,%1,%2,%3};\n"
        : "+f"(d[0]), "+f"(d[1]), "+f"(d[2]), "+f"(d[3])
        : "r"(a0), "r"(a1), "r"(a2), "r"(a3), "r"(b0), "r"(b1));
}
__device__ __forceinline__ void cp_async16(uint32_t dst, const void* src, int szvalid) {
    asm volatile("cp.async.cg.shared.global [%0], [%1], 16, %2;"
                 :: "r"(dst), "l"(src), "r"(szvalid));
}
__device__ __forceinline__ void cp_commit() { asm volatile("cp.async.commit_group;"); }

// ================== fp16 tensor-core GEMM: C[M,N] = A[M,K] @ BT[N,K]^T ==================
// 128 threads = 4 warps (2x2), warp tile 64x64, block tile 128x128x32, 4-stage cp.async.
#define GPITCH_B   80
#define GOP_BYTES  (128 * GPITCH_B)
#define GSTAGE_B   (2 * GOP_BYTES)       // 20480 per stage
#define GTC_NSTAGE 4
#define GTC_SMEM_TOTAL (GTC_NSTAGE * GSTAGE_B)   // 81920 bytes

template<int EPI, int OUTH>
__global__ __launch_bounds__(128, 2)
void gemm_tc(const __half* __restrict__ A, const __half* __restrict__ BT,
             const float* __restrict__ bias, void* __restrict__ Cout,
             int M, int N, int K) {
    extern __shared__ char smem[];
    const uint32_t sb = (uint32_t)__cvta_generic_to_shared(smem);
    const int tid = threadIdx.x;
    const int lane = tid & 31;
    const int wid = tid >> 5;
    const int wr = wid >> 1;
    const int wc = wid & 1;
    const int g4 = lane >> 2, t4 = lane & 3;
    const int bx = blockIdx.x, by = blockIdx.y;
    const int gra = by * 128;
    const int gnb = bx * 128;

    float acc[4][8][4];
#pragma unroll
    for (int mt = 0; mt < 4; mt++)
#pragma unroll
        for (int nt = 0; nt < 8; nt++)
#pragma unroll
            for (int q = 0; q < 4; q++) acc[mt][nt][q] = 0.f;

    const int nk = K >> 5;

    auto load_stage = [&](int kc, int s) {
        const uint32_t sbase = sb + s * GSTAGE_B;
#pragma unroll
        for (int i = 0; i < 4; i++) {
            const int c = tid + i * 128;
            const int row = c >> 2, seg = c & 3;
            const int ga = gra + row;
            const bool ok = ga < M;
            cp_async16(sbase + row * GPITCH_B + seg * 16,
                       A + (size_t)(ok ? ga : 0) * K + kc * 32 + seg * 8, ok ? 16 : 0);
            cp_async16(sbase + GOP_BYTES + row * GPITCH_B + seg * 16,
                       BT + (size_t)(gnb + row) * K + kc * 32 + seg * 8, 16);
        }
    };

    load_stage(0, 0); cp_commit();
    load_stage(1, 1); cp_commit();
    load_stage(2, 2); cp_commit();

    for (int kc = 0; kc < nk; kc++) {
        if (kc < nk - 2)       asm volatile("cp.async.wait_group 2;");
        else if (kc == nk - 2) asm volatile("cp.async.wait_group 1;");
        else                   asm volatile("cp.async.wait_group 0;");
        __syncthreads();
        if (kc + 3 < nk) { load_stage(kc + 3, (kc + 3) & (GTC_NSTAGE - 1)); cp_commit(); }

        const char* sA = smem + (kc & (GTC_NSTAGE - 1)) * GSTAGE_B;
        const char* sB = sA + GOP_BYTES;
#pragma unroll
        for (int ks = 0; ks < 2; ks++) {
            const int kb = ks * 32 + t4 * 4;
            uint32_t af[4][4];
            uint32_t bf[8][2];
#pragma unroll
            for (int mt = 0; mt < 4; mt++) {
                const int r = wr * 64 + mt * 16 + g4;
                af[mt][0] = *(const uint32_t*)(sA + r * GPITCH_B + kb);
                af[mt][1] = *(const uint32_t*)(sA + (r + 8) * GPITCH_B + kb);
                af[mt][2] = *(const uint32_t*)(sA + r * GPITCH_B + kb + 16);
                af[mt][3] = *(const uint32_t*)(sA + (r + 8) * GPITCH_B + kb + 16);
            }
#pragma unroll
            for (int nt = 0; nt < 8; nt++) {
                const int n = wc * 64 + nt * 8 + g4;
                bf[nt][0] = *(const uint32_t*)(sB + n * GPITCH_B + kb);
                bf[nt][1] = *(const uint32_t*)(sB + n * GPITCH_B + kb + 16);
            }
#pragma unroll
            for (int mt = 0; mt < 4; mt++)
#pragma unroll
                for (int nt = 0; nt < 8; nt++)
                    mma_f16(acc[mt][nt], af[mt][0], af[mt][1], af[mt][2], af[mt][3],
                            bf[nt][0], bf[nt][1]);
        }
    }

#pragma unroll
    for (int mt = 0; mt < 4; mt++) {
        const int r0 = by * 128 + wr * 64 + mt * 16 + g4;
#pragma unroll
        for (int nt = 0; nt < 8; nt++) {
            const int col = bx * 128 + wc * 64 + nt * 8 + t4 * 2;
            float b0 = 0.f, b1 = 0.f;
            if (bias) { b0 = __ldg(bias + col); b1 = __ldg(bias + col + 1); }
            float v0 = acc[mt][nt][0] + b0;
            float v1 = acc[mt][nt][1] + b1;
            float v2 = acc[mt][nt][2] + b0;
            float v3 = acc[mt][nt][3] + b1;
            if (EPI == 1) {
                v0 = gelu_tanh(v0); v1 = gelu_tanh(v1);
                v2 = gelu_tanh(v2); v3 = gelu_tanh(v3);
            }
            if (OUTH) {
                __half* Ch = (__half*)Cout;
                if (r0 < M) *(__half2*)(Ch + (size_t)r0 * N + col) = __floats2half2_rn(v0, v1);
                if (r0 + 8 < M) *(__half2*)(Ch + (size_t)(r0 + 8) * N + col) = __floats2half2_rn(v2, v3);
            } else {
                float* Cf = (float*)Cout;
                if (r0 < M) *(float2*)(Cf + (size_t)r0 * N + col) = make_float2(v0, v1);
                if (r0 + 8 < M) *(float2*)(Cf + (size_t)(r0 + 8) * N + col) = make_float2(v2, v3);
            }
        }
    }
}

// ============ persistent fused LSTM: all 16 steps in one launch ============
#define LSA_OP   (64 * GPITCH_B)
#define LSB_OP   (128 * GPITCH_B)
#define LSTAGE_B (LSA_OP + LSB_OP)
#define LSTM_SMEM_TOTAL (2 * LSTAGE_B)

__global__ __launch_bounds__(128, 2)
void lstm_persist_tc(__half* __restrict__ h0buf, __half* __restrict__ h1buf,
                     const __half* __restrict__ BT, const __half* __restrict__ gx,
                     float* __restrict__ cst, const __half* __restrict__ xbuf,
                     const float* __restrict__ rmod, float* __restrict__ outp) {
    extern __shared__ char smem[];
    const uint32_t sb = (uint32_t)__cvta_generic_to_shared(smem);
    const int tid = threadIdx.x;
    const int lane = tid & 31;
    const int wid = tid >> 5;
    const int wr = wid >> 1;
    const int wc = wid & 1;
    const int g4 = lane >> 2, t4 = lane & 3;
    const int bx = blockIdx.x, by = blockIdx.y;
    const int gra = by * 64;
    const int gnb = bx * 128;
    const int K = 1024, nk = 32;

    for (int t = 0; t < TT; t++) {
        const __half* A = (t & 1) ? h1buf : h0buf;
        __half* hnext = (t & 1) ? h0buf : h1buf;

        float acc[2][8][4];
#pragma unroll
        for (int mt = 0; mt < 2; mt++)
#pragma unroll
            for (int nt = 0; nt < 8; nt++)
#pragma unroll
                for (int q = 0; q < 4; q++) acc[mt][nt][q] = 0.f;

        if (t > 0) {
            auto load_stage = [&](int kc, int p) {
                const uint32_t sbase = sb + p * LSTAGE_B;
#pragma unroll
                for (int i = 0; i < 2; i++) {
                    const int c = tid + i * 128;
                    const int row = c >> 2, seg = c & 3;
                    cp_async16(sbase + row * GPITCH_B + seg * 16,
                               A + (size_t)(gra + row) * K + kc * 32 + seg * 8, 16);
                }
#pragma unroll
                for (int i = 0; i < 4; i++) {
                    const int c = tid + i * 128;
                    const int row = c >> 2, seg = c & 3;
                    cp_async16(sbase + LSA_OP + row * GPITCH_B + seg * 16,
                               BT + (size_t)(gnb + row) * K + kc * 32 + seg * 8, 16);
                }
            };

            load_stage(0, 0);
            cp_commit();

            for (int kc = 0; kc < nk; kc++) {
                const int p = kc & 1;
                if (kc + 1 < nk) {
                    load_stage(kc + 1, p ^ 1);
                    cp_commit();
                    asm volatile("cp.async.wait_group 1;");
                } else {
                    asm volatile("cp.async.wait_group 0;");
                }
                __syncthreads();
                const char* sA = smem + p * LSTAGE_B;
                const char* sB = sA + LSA_OP;
#pragma unroll
                for (int ks = 0; ks < 2; ks++) {
                    const int kb = ks * 32 + t4 * 4;
                    uint32_t af[2][4];
                    uint32_t bf[8][2];
#pragma unroll
                    for (int mt = 0; mt < 2; mt++) {
                        const int r = wr * 32 + mt * 16 + g4;
                        af[mt][0] = *(const uint32_t*)(sA + r * GPITCH_B + kb);
                        af[mt][1] = *(const uint32_t*)(sA + (r + 8) * GPITCH_B + kb);
                        af[mt][2] = *(const uint32_t*)(sA + r * GPITCH_B + kb + 16);
                        af[mt][3] = *(const uint32_t*)(sA + (r + 8) * GPITCH_B + kb + 16);
                    }
#pragma unroll
                    for (int nt = 0; nt < 8; nt++) {
                        const int n = wc * 64 + nt * 8 + g4;
                        bf[nt][0] = *(const uint32_t*)(sB + n * GPITCH_B + kb);
                        bf[nt][1] = *(const uint32_t*)(sB + n * GPITCH_B + kb + 16);
                    }
#pragma unroll
                    for (int mt = 0; mt < 2; mt++)
#pragma unroll
                        for (int nt = 0; nt < 8; nt++)
                            mma_f16(acc[mt][nt], af[mt][0], af[mt][1], af[mt][2], af[mt][3],
                                    bf[nt][0], bf[nt][1]);
                }
                __syncthreads();
            }
        }

#pragma unroll
        for (int mt = 0; mt < 2; mt++) {
            const int r0 = by * 64 + wr * 32 + mt * 16 + g4;
            const int r1 = r0 + 8;
            const int tok0 = ((r0 >> 8) << 12) + (t << 8) + (r0 & 255);
            const int tok1 = ((r1 >> 8) << 12) + (t << 8) + (r1 & 255);
            const int bt0 = tok0 >> 8, bt1 = tok1 >> 8;
#pragma unroll
            for (int nt = 0; nt < 8; nt++) {
                const int col = bx * 128 + wc * 64 + nt * 8 + t4 * 2;
                __half2 gx0 = *(const __half2*)(gx + (size_t)tok0 * 4096 + col);
                __half2 gx1 = *(const __half2*)(gx + (size_t)tok1 * 4096 + col);
                float v0 = acc[mt][nt][0] + __half2float(__low2half(gx0));
                float v1 = acc[mt][nt][1] + __half2float(__high2half(gx0));
                float v2 = acc[mt][nt][2] + __half2float(__low2half(gx1));
                float v3 = acc[mt][nt][3] + __half2float(__high2half(gx1));
                float p0 = __shfl_xor_sync(0xffffffffu, v0, 1);
                float p1 = __shfl_xor_sync(0xffffffffu, v1, 1);
                float p2 = __shfl_xor_sync(0xffffffffu, v2, 1);
                float p3 = __shfl_xor_sync(0xffffffffu, v3, 1);
                if (!(lane & 1)) {
                    const int j = col >> 2;
                    {
                        float cprev = (t == 0) ? 0.f : cst[r0 * 1024 + j];
                        float cc = sigm(v1) * cprev + sigm(v0) * tanh_fast(p0);
                        float hh = sigm(p1) * tanh_fast(cc);
                        cst[r0 * 1024 + j] = cc;
                        hnext[r0 * 1024 + j] = __float2half(hh);
                        float rg = rmod[bt0 * MODW + 2048 + j];
                        outp[(size_t)tok0 * 1024 + j] =
                            __half2float(xbuf[(size_t)tok0 * 1024 + j]) + rg * hh;
                    }
                    {
                        float cprev = (t == 0) ? 0.f : cst[r1 * 1024 + j];
                        float cc = sigm(v3) * cprev + sigm(v2) * tanh_fast(p2);
                        float hh = sigm(p3) * tanh_fast(cc);
                        cst[r1 * 1024 + j] = cc;
                        hnext[r1 * 1024 + j] = __float2half(hh);
                        float rg = rmod[bt1 * MODW + 2048 + j];
                        outp[(size_t)tok1 * 1024 + j] =
                            __half2float(xbuf[(size_t)tok1 * 1024 + j]) + rg * hh;
                    }
                }
            }
        }

        if (t < TT - 1) {
            __syncthreads();
            if (tid == 0) {
                __threadfence();
                atomicAdd(&g_lstm_bar, 1u);
                const unsigned int target = 256u * (unsigned int)(t + 1);
                while (atomicAdd(&g_lstm_bar, 0u) < target) {}
                __threadfence();
            }
            __syncthreads();
        }
    }
}

// ---------------- batched weight transpose: all matrices in one launch ----------------
struct TransDesc { const float* W; __half* WT; int K; int N; int perm; int tileStart; };
struct TransArgs { TransDesc d[13]; };

__global__ __launch_bounds__(256)
void transpose_all_kernel(TransArgs a) {
    __shared__ float t[32][33];
    const int bid = blockIdx.x;
    int i = 0;
#pragma unroll
    for (int k = 0; k < 12; k++) if (bid >= a.d[k + 1].tileStart) i = k + 1;
    const TransDesc& td = a.d[i];
    const int local = bid - td.tileStart;
    const int ntx = td.N / 32;
    const int n0 = (local % ntx) * 32, k0 = (local / ntx) * 32;
    const int tx = threadIdx.x & 31, ty = threadIdx.x >> 5;
#pragma unroll
    for (int j = 0; j < 4; j++)
        t[ty + j * 8][tx] = td.W[(size_t)(k0 + ty + j * 8) * td.N + n0 + tx];
    __syncthreads();
#pragma unroll
    for (int j = 0; j < 4; j++) {
        int n = n0 + ty + j * 8;
        int nd = td.perm ? (4 * (n & 1023) + (n >> 10)) : n;
        td.WT[(size_t)nd * td.K + k0 + tx] = __float2half(t[tx][ty + j * 8]);
    }
}

// ---------------- block LN reduction helper ----------------
__device__ __forceinline__ void block_ln_stats(float s, float s2, float* red, int tid,
                                               float& mean, float& inv) {
#pragma unroll
    for (int o = 16; o; o >>= 1) {
        s += __shfl_xor_sync(0xffffffffu, s, o);
        s2 += __shfl_xor_sync(0xffffffffu, s2, o);
    }
    if ((tid & 31) == 0) { red[tid >> 5] = s; red[8 + (tid >> 5)] = s2; }
    __syncthreads();
    if (tid == 0) {
        float a = 0.f, b = 0.f;
        for (int i = 0; i < 8; i++) { a += red[i]; b += red[8 + i]; }
        red[0] = a; red[8] = b;
    }
    __syncthreads();
    mean = red[0] * (1.f / DD);
    const float var = red[8] * (1.f / DD) - mean * mean;
    inv = rsqrtf(var + 1e-6f);
}
__device__ __forceinline__ uint32_t pack_h2(float a, float b) {
    return h2_as_u32(__floats2half2_rn(a, b));
}

// ---------------- LayerNorm + adaLN modulate (fp32 x in, fp16 out; vectorized) --------
__global__ __launch_bounds__(256)
void ln_mod_kernel(const float* __restrict__ x, const float* __restrict__ mod,
                   int mstride, int shift_off, int scale_off, __half* __restrict__ out) {
    __shared__ float red[16];
    const int tok = blockIdx.x;
    const int tid = threadIdx.x;
    const int d0 = tid * 4;
    float4 xv = *(const float4*)(x + (size_t)tok * DD + d0);
    float s = xv.x + xv.y + xv.z + xv.w;
    float s2 = xv.x * xv.x + xv.y * xv.y + xv.z * xv.z + xv.w * xv.w;
    float mean, inv;
    block_ln_stats(s, s2, red, tid, mean, inv);
    const int bt = tok >> 8;
    const float* m = mod + (size_t)bt * mstride;
    float4 sh = *(const float4*)(m + shift_off + d0);
    float4 sc = *(const float4*)(m + scale_off + d0);
    uint2 o;
    o.x = pack_h2((xv.x - mean) * inv * (1.f + sc.x) + sh.x,
                  (xv.y - mean) * inv * (1.f + sc.y) + sh.y);
    o.y = pack_h2((xv.z - mean) * inv * (1.f + sc.z) + sh.z,
                  (xv.w - mean) * inv * (1.f + sc.w) + sh.w);
    *(uint2*)(out + (size_t)tok * DD + d0) = o;
}

// -------- fused gated residual add + LN + modulate (vectorized; XIN32 selects xin type) --
template<int XIN32>
__global__ __launch_bounds__(256)
void ga_ln_kernel(const void* __restrict__ xin, const __half* __restrict__ delta,
                  const float* __restrict__ modg, int gstride, int gate_off,
                  const float* __restrict__ modl, int lstride, int shift_off, int scale_off,
                  __half* __restrict__ xout, __half* __restrict__ lnout) {
    __shared__ float red[16];
    const int tok = blockIdx.x;
    const int tid = threadIdx.x;
    const int bt = tok >> 8;
    const int d0 = tid * 4;
    float xv0, xv1, xv2, xv3;
    if (XIN32) {
        float4 xv = *(const float4*)((const float*)xin + (size_t)tok * DD + d0);
        xv0 = xv.x; xv1 = xv.y; xv2 = xv.z; xv3 = xv.w;
    } else {
        uint2 xu = *(const uint2*)((const __half*)xin + (size_t)tok * DD + d0);
        __half2 h0 = *reinterpret_cast<__half2*>(&xu.x);
        __half2 h1 = *reinterpret_cast<__half2*>(&xu.y);
        xv0 = __half2float(__low2half(h0)); xv1 = __half2float(__high2half(h0));
        xv2 = __half2float(__low2half(h1)); xv3 = __half2float(__high2half(h1));
    }
    uint2 du = *(const uint2*)(delta + (size_t)tok * DD + d0);
    __half2 dh0 = *reinterpret_cast<__half2*>(&du.x);
    __half2 dh1 = *reinterpret_cast<__half2*>(&du.y);
    float4 gg = *(const float4*)(modg + (size_t)bt * gstride + gate_off + d0);
    float f0 = xv0 + gg.x * __half2float(__low2half(dh0));
    float f1 = xv1 + gg.y * __half2float(__high2half(dh0));
    float f2 = xv2 + gg.z * __half2float(__low2half(dh1));
    float f3 = xv3 + gg.w * __half2float(__high2half(dh1));
    uint2 xo;
    xo.x = pack_h2(f0, f1);
    xo.y = pack_h2(f2, f3);
    *(uint2*)(xout + (size_t)tok * DD + d0) = xo;
    float s = f0 + f1 + f2 + f3;
    float s2 = f0 * f0 + f1 * f1 + f2 * f2 + f3 * f3;
    float mean, inv;
    block_ln_stats(s, s2, red, tid, mean, inv);
    const float* ml = modl + (size_t)bt * lstride;
    float4 sh = *(const float4*)(ml + shift_off + d0);
    float4 sc = *(const float4*)(ml + scale_off + d0);
    uint2 lo;
    lo.x = pack_h2((f0 - mean) * inv * (1.f + sc.x) + sh.x,
                   (f1 - mean) * inv * (1.f + sc.y) + sh.y);
    lo.y = pack_h2((f2 - mean) * inv * (1.f + sc.z) + sh.z,
                   (f3 - mean) * inv * (1.f + sc.w) + sh.w);
    *(uint2*)(lnout + (size_t)tok * DD + d0) = lo;
}

// ---------------- setup: silu + combined ada bias + permuted lstm bias + barrier reset ----
__global__ void setup_kernel(const float* __restrict__ c, __half* __restrict__ csh,
                             const float* __restrict__ sbp, const float* __restrict__ tbp,
                             const float* __restrict__ rbp, float* __restrict__ adab,
                             const float* __restrict__ lba, const float* __restrict__ lbb,
                             float* __restrict__ lbias) {
    int i = blockIdx.x * 256 + threadIdx.x;
    if (i == 0) g_lstm_bar = 0u;
    if (i < NBT * DD) {
        float v = c[i];
        csh[i] = __float2half(v / (1.f + __expf(-v)));
    }
    if (i < MODW) {
        float b;
        if (i < 6144) b = sbp[i];
        else if (i < 12288) b = tbp[i - 6144];
        else b = rbp[i - 12288];
        adab[i] = b;
    }
    if (i < 4 * DD) {
        int j = i >> 2, g = i & 3;
        lbias[i] = lba[g * 1024 + j] + lbb[g * 1024 + j];
    }
}

// ======= spatial attention via mma.sync fp16 flash (L=256, dh=64, non-causal) =======
__global__ __launch_bounds__(256, 2)
void spatial_attn_tc(const __half* __restrict__ qkv, __half* __restrict__ out) {
    __shared__ __half sQ[128 * 72];
    __shared__ __half sK[64 * 72];
    __shared__ __half sVT[64 * 72];
    const int bid = blockIdx.x;
    const int qhalf = bid & 1;
    const int head = (bid >> 1) & 15;
    const int n = bid >> 5;
    const int tid = threadIdx.x;
    const int lane = tid & 31;
    const int wid = tid >> 5;
    const int g4 = lane >> 2, t4 = lane & 3;
    const size_t rowbase = (size_t)n * 256;

#pragma unroll
    for (int i = 0; i < 4; i++) {
        int idx = tid + i * 256;
        int row = idx >> 3, seg = idx & 7;
        *(uint4*)&sQ[row * 72 + seg * 8] =
            *(const uint4*)(qkv + (rowbase + qhalf * 128 + row) * 3072 + head * 64 + seg * 8);
    }
    __syncthreads();

    uint32_t af[4][4];
    {
        const int r = wid * 16 + g4;
#pragma unroll
        for (int ks = 0; ks < 4; ks++) {
            af[ks][0] = *(const uint32_t*)&sQ[r * 72 + ks * 16 + t4 * 2];
            af[ks][1] = *(const uint32_t*)&sQ[(r + 8) * 72 + ks * 16 + t4 * 2];
            af[ks][2] = *(const uint32_t*)&sQ[r * 72 + ks * 16 + 8 + t4 * 2];
            af[ks][3] = *(const uint32_t*)&sQ[(r + 8) * 72 + ks * 16 + 8 + t4 * 2];
        }
    }

    float O[8][4];
#pragma unroll
    for (int i = 0; i < 8; i++)
#pragma unroll
        for (int q = 0; q < 4; q++) O[i][q] = 0.f;
    float m0 = -1e30f, m1 = -1e30f, l0 = 0.f, l1 = 0.f;

    for (int kt = 0; kt < 4; kt++) {
#pragma unroll
        for (int i = 0; i < 2; i++) {
            int idx = tid + i * 256;
            int row = idx >> 3, seg = idx & 7;
            const __half* src = qkv + (rowbase + kt * 64 + row) * 3072 + 1024 + head * 64 + seg * 8;
            *(uint4*)&sK[row * 72 + seg * 8] = *(const uint4*)src;
            __half vv[8];
            *(uint4*)vv = *(const uint4*)(src + 1024);
#pragma unroll
            for (int jj = 0; jj < 8; jj++) sVT[(seg * 8 + jj) * 72 + row] = vv[jj];
        }
        __syncthreads();

        float sc[8][4];
#pragma unroll
        for (int nt = 0; nt < 8; nt++) {
#pragma unroll
            for (int q = 0; q < 4; q++) sc[nt][q] = 0.f;
#pragma unroll
            for (int ks = 0; ks < 4; ks++) {
                uint32_t b0 = *(const uint32_t*)&sK[(nt * 8 + g4) * 72 + ks * 16 + t4 * 2];
                uint32_t b1 = *(const uint32_t*)&sK[(nt * 8 + g4) * 72 + ks * 16 + 8 + t4 * 2];
                mma_f16(sc[nt], af[ks][0], af[ks][1], af[ks][2], af[ks][3], b0, b1);
            }
        }

        float mx0 = -1e30f, mx1 = -1e30f;
#pragma unroll
        for (int nt = 0; nt < 8; nt++) {
            sc[nt][0] *= 0.125f; sc[nt][1] *= 0.125f;
            sc[nt][2] *= 0.125f; sc[nt][3] *= 0.125f;
            mx0 = fmaxf(mx0, fmaxf(sc[nt][0], sc[nt][1]));
            mx1 = fmaxf(mx1, fmaxf(sc[nt][2], sc[nt][3]));
        }
        mx0 = fmaxf(mx0, __shfl_xor_sync(0xffffffffu, mx0, 1));
        mx0 = fmaxf(mx0, __shfl_xor_sync(0xffffffffu, mx0, 2));
        mx1 = fmaxf(mx1, __shfl_xor_sync(0xffffffffu, mx1, 1));
        mx1 = fmaxf(mx1, __shfl_xor_sync(0xffffffffu, mx1, 2));
        const float mn0 = fmaxf(m0, mx0), mn1 = fmaxf(m1, mx1);
        const float al0 = __expf(m0 - mn0), al1 = __expf(m1 - mn1);
        m0 = mn0; m1 = mn1;

        float sum0 = 0.f, sum1 = 0.f;
        uint32_t aP[8][2];
#pragma unroll
        for (int nt = 0; nt < 8; nt++) {
            float p0 = __expf(sc[nt][0] - mn0);
            float p1 = __expf(sc[nt][1] - mn0);
            float p2 = __expf(sc[nt][2] - mn1);
            float p3 = __expf(sc[nt][3] - mn1);
            sum0 += p0 + p1; sum1 += p2 + p3;
            aP[nt][0] = h2_as_u32(__floats2half2_rn(p0, p1));
            aP[nt][1] = h2_as_u32(__floats2half2_rn(p2, p3));
        }
        sum0 += __shfl_xor_sync(0xffffffffu, sum0, 1);
        sum0 += __shfl_xor_sync(0xffffffffu, sum0, 2);
        sum1 += __shfl_xor_sync(0xffffffffu, sum1, 1);
        sum1 += __shfl_xor_sync(0xffffffffu, sum1, 2);
        l0 = l0 * al0 + sum0;
        l1 = l1 * al1 + sum1;
#pragma unroll
        for (int nt2 = 0; nt2 < 8; nt2++) {
            O[nt2][0] *= al0; O[nt2][1] *= al0;
            O[nt2][2] *= al1; O[nt2][3] *= al1;
        }

#pragma unroll
        for (int ks2 = 0; ks2 < 4; ks2++) {
            const uint32_t a0 = aP[2 * ks2][0], a1 = aP[2 * ks2][1];
            const uint32_t a2 = aP[2 * ks2 + 1][0], a3 = aP[2 * ks2 + 1][1];
#pragma unroll
            for (int nt2 = 0; nt2 < 8; nt2++) {
                uint32_t b0 = *(const uint32_t*)&sVT[(nt2 * 8 + g4) * 72 + ks2 * 16 + t4 * 2];
                uint32_t b1 = *(const uint32_t*)&sVT[(nt2 * 8 + g4) * 72 + ks2 * 16 + 8 + t4 * 2];
                mma_f16(O[nt2], a0, a1, a2, a3, b0, b1);
            }
        }
        __syncthreads();
    }

    const float inv0 = 1.f / l0, inv1 = 1.f / l1;
    const int q0 = qhalf * 128 + wid * 16 + g4;
#pragma unroll
    for (int nt2 = 0; nt2 < 8; nt2++) {
        const int col = head * 64 + nt2 * 8 + t4 * 2;
        *(__half2*)(out + (rowbase + q0) * 1024 + col) =
            __floats2half2_rn(O[nt2][0] * inv0, O[nt2][1] * inv0);
        *(__half2*)(out + (rowbase + q0 + 8) * 1024 + col) =
            __floats2half2_rn(O[nt2][2] * inv1, O[nt2][3] * inv1);
    }
}

// ---------------- temporal attention (T=16, dh=64, causal; fp16 qkv in/out) ----------------
__global__ __launch_bounds__(128)
void temporal_attn_kernel(const __half* __restrict__ qkv, __half* __restrict__ out) {
    __shared__ float Q[16][65], K[16][65], V[16][65], S[16][17];
    const int bid = blockIdx.x;
    const int head = bid & 15;
    const int n = bid >> 4;
    const int b = n >> 8;
    const int hw = n & 255;
    const int tid = threadIdx.x;
    const size_t tokbase = (size_t)b * 4096 + hw;

    for (int i = tid; i < 16 * 64; i += 128) {
        int t = i >> 6, d = i & 63;
        size_t base = (tokbase + (size_t)t * 256) * 3072 + head * 64 + d;
        Q[t][d] = __half2float(qkv[base]);
        K[t][d] = __half2float(qkv[base + 1024]);
        V[t][d] = __half2float(qkv[base + 2048]);
    }
    __syncthreads();

    for (int idx = tid; idx < 256; idx += 128) {
        int qi = idx >> 4, kj = idx & 15;
        float s;
        if (kj <= qi) {
            float acc = 0.f;
#pragma unroll
            for (int d = 0; d < 64; d++) acc += Q[qi][d] * K[kj][d];
            s = acc * 0.125f;
        } else s = -1e30f;
        S[qi][kj] = s;
    }
    __syncthreads();

    {
        const int row = tid >> 3, c0 = tid & 7;
        float mx = fmaxf(S[row][c0], S[row][c0 + 8]);
#pragma unroll
        for (int o = 4; o; o >>= 1) mx = fmaxf(mx, __shfl_xor_sync(0xffffffffu, mx, o));
        float e0 = __expf(S[row][c0] - mx), e1 = __expf(S[row][c0 + 8] - mx);
        float sum = e0 + e1;
#pragma unroll
        for (int o = 4; o; o >>= 1) sum += __shfl_xor_sync(0xffffffffu, sum, o);
        float inv = 1.f / sum;
        S[row][c0] = e0 * inv;
        S[row][c0 + 8] = e1 * inv;
    }
    __syncthreads();

    for (int i = tid; i < 16 * 64; i += 128) {
        int qi = i >> 6, d = i & 63;
        float acc = 0.f;
#pragma unroll
        for (int k = 0; k < 16; k++) acc = fmaf(S[qi][k], V[k][d], acc);
        out[(tokbase + (size_t)qi * 256) * 1024 + head * 64 + d] = __float2half(acc);
    }
}

// ---------------- launch helpers ----------------
static void gemm(const __half* A, const __half* BT, const float* bias, void* C,
                 int M, int N, int K, int epi, int outh) {
    dim3 g(N / 128, (M + 127) / 128);
    if (epi == 1)      gemm_tc<1, 1><<<g, 128, GTC_SMEM_TOTAL>>>(A, BT, bias, C, M, N, K);
    else if (outh)     gemm_tc<0, 1><<<g, 128, GTC_SMEM_TOTAL>>>(A, BT, bias, C, M, N, K);
    else               gemm_tc<0, 0><<<g, 128, GTC_SMEM_TOTAL>>>(A, BT, bias, C, M, N, K);
}

extern "C" void kernel_launch(void* const* d_in, const int* in_sizes, int n_in,
                              void* d_out, int out_size) {
    const float* x        = (const float*)d_in[0];
    const float* c        = (const float*)d_in[1];
    const float* s_ada_w  = (const float*)d_in[2];
    const float* s_ada_b  = (const float*)d_in[3];
    const float* t_ada_w  = (const float*)d_in[4];
    const float* t_ada_b  = (const float*)d_in[5];
    const float* r_ada_w  = (const float*)d_in[6];
    const float* r_ada_b  = (const float*)d_in[7];
    const float* s_qkv_w  = (const float*)d_in[8];
    const float* s_out_w  = (const float*)d_in[9];
    const float* s_out_b  = (const float*)d_in[10];
    const float* t_qkv_w  = (const float*)d_in[11];
    const float* t_out_w  = (const float*)d_in[12];
    const float* t_out_b  = (const float*)d_in[13];
    const float* s_mlp_w1 = (const float*)d_in[14];
    const float* s_mlp_b1 = (const float*)d_in[15];
    const float* s_mlp_w2 = (const float*)d_in[16];
    const float* s_mlp_b2 = (const float*)d_in[17];
    const float* t_mlp_w1 = (const float*)d_in[18];
    const float* t_mlp_b1 = (const float*)d_in[19];
    const float* t_mlp_w2 = (const float*)d_in[20];
    const float* t_mlp_b2 = (const float*)d_in[21];
    const float* lstm_w_ih = (const float*)d_in[22];
    const float* lstm_w_hh = (const float*)d_in[23];
    const float* lstm_b_ih = (const float*)d_in[24];
    const float* lstm_b_hh = (const float*)d_in[25];
    float* out = (float*)d_out;

    cudaFuncSetAttribute(gemm_tc<0, 0>, cudaFuncAttributeMaxDynamicSharedMemorySize, GTC_SMEM_TOTAL);
    cudaFuncSetAttribute(gemm_tc<0, 1>, cudaFuncAttributeMaxDynamicSharedMemorySize, GTC_SMEM_TOTAL);
    cudaFuncSetAttribute(gemm_tc<1, 1>, cudaFuncAttributeMaxDynamicSharedMemorySize, GTC_SMEM_TOTAL);
    cudaFuncSetAttribute(lstm_persist_tc, cudaFuncAttributeMaxDynamicSharedMemorySize, LSTM_SMEM_TOTAL);

    __half *csh, *h1h, *qkvh, *deltah, *mlph, *gatesxh, *hstateh, *hstate2h, *wTh, *xbufh;
    float *modall, *adab, *cstate, *lstmbias;
    cudaGetSymbolAddress((void**)&csh, g_csh);
    cudaGetSymbolAddress((void**)&modall, g_modall);
    cudaGetSymbolAddress((void**)&adab, g_adab);
    cudaGetSymbolAddress((void**)&xbufh, g_xbufh);
    cudaGetSymbolAddress((void**)&h1h, g_h1h);
    cudaGetSymbolAddress((void**)&qkvh, g_qkvh);
    cudaGetSymbolAddress((void**)&deltah, g_deltah);
    cudaGetSymbolAddress((void**)&mlph, g_mlph);
    cudaGetSymbolAddress((void**)&gatesxh, g_gatesxh);
    cudaGetSymbolAddress((void**)&hstateh, g_hstateh);
    cudaGetSymbolAddress((void**)&hstate2h, g_hstate2h);
    cudaGetSymbolAddress((void**)&cstate, g_cstate);
    cudaGetSymbolAddress((void**)&lstmbias, g_lstmbias);
    cudaGetSymbolAddress((void**)&wTh, g_wTh);

    float* smod = modall;              // stride MODW
    float* tmod = modall + 6144;       // stride MODW
    float* rmod = modall + 12288;      // stride MODW

    const size_t MEG = 1048576;
    __half* wt_ada   = wTh + 0 * MEG;   // [15360,1024]: sada|tada|rada contiguous
    __half* wt_sqkv  = wTh + 15 * MEG;
    __half* wt_sout  = wTh + 18 * MEG;
    __half* wt_tqkv  = wTh + 19 * MEG;
    __half* wt_tout  = wTh + 22 * MEG;
    __half* wt_smlp1 = wTh + 23 * MEG;
    __half* wt_smlp2 = wTh + 27 * MEG;
    __half* wt_tmlp1 = wTh + 31 * MEG;
    __half* wt_tmlp2 = wTh + 35 * MEG;
    __half* wt_lih   = wTh + 39 * MEG;  // gate-interleaved [4096,1024]
    __half* wt_lhh   = wTh + 43 * MEG;  // gate-interleaved [4096,1024]

    // batched transpose: all 13 matrices, one launch
    {
        TransArgs ta;
        auto set = [&](int i, const float* W, __half* WT, int K, int N, int perm, int start) {
            ta.d[i].W = W; ta.d[i].WT = WT; ta.d[i].K = K; ta.d[i].N = N;
            ta.d[i].perm = perm; ta.d[i].tileStart = start;
        };
        int s = 0;
        set(0,  s_ada_w,  wt_ada,            1024, 6144, 0, s); s += (6144 / 32) * 32;
        set(1,  t_ada_w,  wt_ada + 6 * MEG,  1024, 6144, 0, s); s += (6144 / 32) * 32;
        set(2,  r_ada_w,  wt_ada + 12 * MEG, 1024, 3072, 0, s); s += (3072 / 32) * 32;
        set(3,  s_qkv_w,  wt_sqkv,  1024, 3072, 0, s); s += (3072 / 32) * 32;
        set(4,  s_out_w,  wt_sout,  1024, 1024, 0, s); s += (1024 / 32) * 32;
        set(5,  t_qkv_w,  wt_tqkv,  1024, 3072, 0, s); s += (3072 / 32) * 32;
        set(6,  t_out_w,  wt_tout,  1024, 1024, 0, s); s += (1024 / 32) * 32;
        set(7,  s_mlp_w1, wt_smlp1, 1024, 4096, 0, s); s += (4096 / 32) * 32;
        set(8,  s_mlp_w2, wt_smlp2, 4096, 1024, 0, s); s += (1024 / 32) * 128;
        set(9,  t_mlp_w1, wt_tmlp1, 1024, 4096, 0, s); s += (4096 / 32) * 32;
        set(10, t_mlp_w2, wt_tmlp2, 4096, 1024, 0, s); s += (1024 / 32) * 128;
        set(11, lstm_w_ih, wt_lih,  1024, 4096, 1, s); s += (4096 / 32) * 32;
        set(12, lstm_w_hh, wt_lhh,  1024, 4096, 1, s); s += (4096 / 32) * 32;
        transpose_all_kernel<<<s, 256>>>(ta);
    }

    // setup (silu + ada bias concat + lstm bias permute + barrier reset)
    setup_kernel<<<(NBT * DD + 255) / 256, 256>>>(c, csh, s_ada_b, t_ada_b, r_ada_b, adab,
                                                  lstm_b_ih, lstm_b_hh, lstmbias);
    gemm(csh, wt_ada, adab, modall, NBT, MODW, DD, 0, 0);

    // ---- spatial attention ----
    ln_mod_kernel<<<NTOK, 256>>>(x, smod, MODW, 0, DD, h1h);
    gemm(h1h, wt_sqkv, nullptr, qkvh, NTOK, 3 * DD, DD, 0, 1);
    spatial_attn_tc<<<1024, 256>>>(qkvh, h1h);
    gemm(h1h, wt_sout, s_out_b, deltah, NTOK, DD, DD, 0, 1);
    ga_ln_kernel<1><<<NTOK, 256>>>(x, deltah, smod, MODW, 2 * DD,
                                   smod, MODW, 3 * DD, 4 * DD, xbufh, h1h);

    // ---- spatial MLP ----
    gemm(h1h, wt_smlp1, s_mlp_b1, mlph, NTOK, 4 * DD, DD, 1, 1);
    gemm(mlph, wt_smlp2, s_mlp_b2, deltah, NTOK, DD, 4 * DD, 0, 1);
    ga_ln_kernel<0><<<NTOK, 256>>>(xbufh, deltah, smod, MODW, 5 * DD,
                                   tmod, MODW, 0, DD, xbufh, h1h);

    // ---- temporal attention (causal) ----
    gemm(h1h, wt_tqkv, nullptr, qkvh, NTOK, 3 * DD, DD, 0, 1);
    temporal_attn_kernel<<<8192, 128>>>(qkvh, h1h);
    gemm(h1h, wt_tout, t_out_b, deltah, NTOK, DD, DD, 0, 1);
    ga_ln_kernel<0><<<NTOK, 256>>>(xbufh, deltah, tmod, MODW, 2 * DD,
                                   tmod, MODW, 3 * DD, 4 * DD, xbufh, h1h);

    // ---- temporal MLP ----
    gemm(h1h, wt_tmlp1, t_mlp_b1, mlph, NTOK, 4 * DD, DD, 1, 1);
    gemm(mlph, wt_tmlp2, t_mlp_b2, deltah, NTOK, DD, 4 * DD, 0, 1);
    ga_ln_kernel<0><<<NTOK, 256>>>(xbufh, deltah, tmod, MODW, 5 * DD,
                                   rmod, MODW, 0, DD, xbufh, h1h);

    // ---- LSTM branch: persistent kernel, all 16 steps ----
    gemm(h1h, wt_lih, lstmbias, gatesxh, NTOK, 4 * DD, DD, 0, 1);
    lstm_persist_tc<<<dim3(32, 8), 128, LSTM_SMEM_TOTAL>>>(
        hstateh, hstate2h, wt_lhh, gatesxh, cstate, xbufh, rmod, out);
}

// round 14
// speedup vs baseline: 1.5081x; 1.5081x over previous
#include <cuda_runtime.h>
#include <cuda_fp16.h>
#include <math.h>
#include <cstdint>

// Problem constants
#define DD   1024
#define NTOK 8192      // B*T*H*W
#define NBT  32        // B*T
#define NSEQ 512       // B*H*W
#define TT   16
#define MODW 15360     // 6*DD + 6*DD + 3*DD combined ada width

// ---------------- scratch (device globals; no allocations allowed) ----------------
__device__ __half g_csh[NBT * DD];
__device__ float  g_modall[NBT * MODW];
__device__ float  g_adab[MODW];
__device__ __half g_xbufh[NTOK * DD];
__device__ __half g_h1h[NTOK * DD];
__device__ __half g_qkvh[NTOK * 3 * DD];
__device__ __half g_deltah[NTOK * DD];
__device__ __half g_mlph[NTOK * 4 * DD];
__device__ __half g_gatesxh[NTOK * 4 * DD];
__device__ __half g_hstateh[NSEQ * DD];
__device__ __half g_hstate2h[NSEQ * DD];
__device__ float  g_cstate[NSEQ * DD];
__device__ float  g_lstmbias[4 * DD];
__device__ unsigned int g_lstm_bar;
__device__ __half g_wTh[47u * 1048576u];   // transposed fp16 weights

__device__ __forceinline__ float tanh_fast(float x) {
    float r; asm("tanh.approx.f32 %0, %1;" : "=f"(r) : "f"(x)); return r;
}
__device__ __forceinline__ float gelu_tanh(float x) {
    return 0.5f * x * (1.f + tanh_fast(0.7978845608028654f * (x + 0.044715f * x * x * x)));
}
__device__ __forceinline__ float sigm(float x) { return 0.5f * (1.f + tanh_fast(0.5f * x)); }
__device__ __forceinline__ uint32_t h2_as_u32(__half2 h) {
    uint32_t u; *reinterpret_cast<__half2*>(&u) = h; return u;
}
__device__ __forceinline__ void mma_f16(float d[4], uint32_t a0, uint32_t a1, uint32_t a2,
                                        uint32_t a3, uint32_t b0, uint32_t b1) {
    asm volatile(
        "mma.sync.aligned.m16n8k16.row.col.f32.f16.f16.f32 "
        "{%0,%1,%2,%3}, {%4,%5,%6,%7}, {%8,%9}, {%0,%1,%2,%3};\n"
        : "+f"(d[0]), "+f"(d[1]), "+f"(d[2]), "+f"(d[3])
        : "r"(a0), "r"(a1), "r"(a2), "r"(a3), "r"(b0), "r"(b1));
}
__device__ __forceinline__ void cp_async16(uint32_t dst, const void* src, int szvalid) {
    asm volatile("cp.async.cg.shared.global [%0], [%1], 16, %2;"
                 :: "r"(dst), "l"(src), "r"(szvalid));
}
__device__ __forceinline__ void cp_commit() { asm volatile("cp.async.commit_group;"); }

// ================== fp16 tensor-core GEMM: C[M,N] = A[M,K] @ BT[N,K]^T ==================
// 128 threads = 4 warps (2x2), warp tile 64x64, block tile 128x128x32, 4-stage cp.async.
#define GPITCH_B   80
#define GOP_BYTES  (128 * GPITCH_B)
#define GSTAGE_B   (2 * GOP_BYTES)       // 20480 per stage
#define GTC_NSTAGE 4
#define GTC_SMEM_TOTAL (GTC_NSTAGE * GSTAGE_B)   // 81920 bytes

template<int EPI, int OUTH>
__global__ __launch_bounds__(128, 2)
void gemm_tc(const __half* __restrict__ A, const __half* __restrict__ BT,
             const float* __restrict__ bias, void* __restrict__ Cout,
             int M, int N, int K) {
    extern __shared__ char smem[];
    const uint32_t sb = (uint32_t)__cvta_generic_to_shared(smem);
    const int tid = threadIdx.x;
    const int lane = tid & 31;
    const int wid = tid >> 5;
    const int wr = wid >> 1;
    const int wc = wid & 1;
    const int g4 = lane >> 2, t4 = lane & 3;
    const int bx = blockIdx.x, by = blockIdx.y;
    const int gra = by * 128;
    const int gnb = bx * 128;

    float acc[4][8][4];
#pragma unroll
    for (int mt = 0; mt < 4; mt++)
#pragma unroll
        for (int nt = 0; nt < 8; nt++)
#pragma unroll
            for (int q = 0; q < 4; q++) acc[mt][nt][q] = 0.f;

    const int nk = K >> 5;

    auto load_stage = [&](int kc, int s) {
        const uint32_t sbase = sb + s * GSTAGE_B;
#pragma unroll
        for (int i = 0; i < 4; i++) {
            const int c = tid + i * 128;
            const int row = c >> 2, seg = c & 3;
            const int ga = gra + row;
            const bool ok = ga < M;
            cp_async16(sbase + row * GPITCH_B + seg * 16,
                       A + (size_t)(ok ? ga : 0) * K + kc * 32 + seg * 8, ok ? 16 : 0);
            cp_async16(sbase + GOP_BYTES + row * GPITCH_B + seg * 16,
                       BT + (size_t)(gnb + row) * K + kc * 32 + seg * 8, 16);
        }
    };

    load_stage(0, 0); cp_commit();
    load_stage(1, 1); cp_commit();
    load_stage(2, 2); cp_commit();

    for (int kc = 0; kc < nk; kc++) {
        if (kc < nk - 2)       asm volatile("cp.async.wait_group 2;");
        else if (kc == nk - 2) asm volatile("cp.async.wait_group 1;");
        else                   asm volatile("cp.async.wait_group 0;");
        __syncthreads();
        if (kc + 3 < nk) { load_stage(kc + 3, (kc + 3) & (GTC_NSTAGE - 1)); cp_commit(); }

        const char* sA = smem + (kc & (GTC_NSTAGE - 1)) * GSTAGE_B;
        const char* sB = sA + GOP_BYTES;
#pragma unroll
        for (int ks = 0; ks < 2; ks++) {
            const int kb = ks * 32 + t4 * 4;
            uint32_t af[4][4];
            uint32_t bf[8][2];
#pragma unroll
            for (int mt = 0; mt < 4; mt++) {
                const int r = wr * 64 + mt * 16 + g4;
                af[mt][0] = *(const uint32_t*)(sA + r * GPITCH_B + kb);
                af[mt][1] = *(const uint32_t*)(sA + (r + 8) * GPITCH_B + kb);
                af[mt][2] = *(const uint32_t*)(sA + r * GPITCH_B + kb + 16);
                af[mt][3] = *(const uint32_t*)(sA + (r + 8) * GPITCH_B + kb + 16);
            }
#pragma unroll
            for (int nt = 0; nt < 8; nt++) {
                const int n = wc * 64 + nt * 8 + g4;
                bf[nt][0] = *(const uint32_t*)(sB + n * GPITCH_B + kb);
                bf[nt][1] = *(const uint32_t*)(sB + n * GPITCH_B + kb + 16);
            }
#pragma unroll
            for (int mt = 0; mt < 4; mt++)
#pragma unroll
                for (int nt = 0; nt < 8; nt++)
                    mma_f16(acc[mt][nt], af[mt][0], af[mt][1], af[mt][2], af[mt][3],
                            bf[nt][0], bf[nt][1]);
        }
    }

#pragma unroll
    for (int mt = 0; mt < 4; mt++) {
        const int r0 = by * 128 + wr * 64 + mt * 16 + g4;
#pragma unroll
        for (int nt = 0; nt < 8; nt++) {
            const int col = bx * 128 + wc * 64 + nt * 8 + t4 * 2;
            float b0 = 0.f, b1 = 0.f;
            if (bias) { b0 = __ldg(bias + col); b1 = __ldg(bias + col + 1); }
            float v0 = acc[mt][nt][0] + b0;
            float v1 = acc[mt][nt][1] + b1;
            float v2 = acc[mt][nt][2] + b0;
            float v3 = acc[mt][nt][3] + b1;
            if (EPI == 1) {
                v0 = gelu_tanh(v0); v1 = gelu_tanh(v1);
                v2 = gelu_tanh(v2); v3 = gelu_tanh(v3);
            }
            if (OUTH) {
                __half* Ch = (__half*)Cout;
                if (r0 < M) *(__half2*)(Ch + (size_t)r0 * N + col) = __floats2half2_rn(v0, v1);
                if (r0 + 8 < M) *(__half2*)(Ch + (size_t)(r0 + 8) * N + col) = __floats2half2_rn(v2, v3);
            } else {
                float* Cf = (float*)Cout;
                if (r0 < M) *(float2*)(Cf + (size_t)r0 * N + col) = make_float2(v0, v1);
                if (r0 + 8 < M) *(float2*)(Cf + (size_t)(r0 + 8) * N + col) = make_float2(v2, v3);
            }
        }
    }
}

// ============ persistent fused LSTM: all 16 steps in one launch ============
#define LSA_OP   (64 * GPITCH_B)
#define LSB_OP   (128 * GPITCH_B)
#define LSTAGE_B (LSA_OP + LSB_OP)
#define LSTM_SMEM_TOTAL (2 * LSTAGE_B)

__global__ __launch_bounds__(128, 2)
void lstm_persist_tc(__half* __restrict__ h0buf, __half* __restrict__ h1buf,
                     const __half* __restrict__ BT, const __half* __restrict__ gx,
                     float* __restrict__ cst, const __half* __restrict__ xbuf,
                     const float* __restrict__ rmod, float* __restrict__ outp) {
    extern __shared__ char smem[];
    const uint32_t sb = (uint32_t)__cvta_generic_to_shared(smem);
    const int tid = threadIdx.x;
    const int lane = tid & 31;
    const int wid = tid >> 5;
    const int wr = wid >> 1;
    const int wc = wid & 1;
    const int g4 = lane >> 2, t4 = lane & 3;
    const int bx = blockIdx.x, by = blockIdx.y;
    const int gra = by * 64;
    const int gnb = bx * 128;
    const int K = 1024, nk = 32;

    for (int t = 0; t < TT; t++) {
        const __half* A = (t & 1) ? h1buf : h0buf;
        __half* hnext = (t & 1) ? h0buf : h1buf;

        float acc[2][8][4];
#pragma unroll
        for (int mt = 0; mt < 2; mt++)
#pragma unroll
            for (int nt = 0; nt < 8; nt++)
#pragma unroll
                for (int q = 0; q < 4; q++) acc[mt][nt][q] = 0.f;

        if (t > 0) {
            auto load_stage = [&](int kc, int p) {
                const uint32_t sbase = sb + p * LSTAGE_B;
#pragma unroll
                for (int i = 0; i < 2; i++) {
                    const int c = tid + i * 128;
                    const int row = c >> 2, seg = c & 3;
                    cp_async16(sbase + row * GPITCH_B + seg * 16,
                               A + (size_t)(gra + row) * K + kc * 32 + seg * 8, 16);
                }
#pragma unroll
                for (int i = 0; i < 4; i++) {
                    const int c = tid + i * 128;
                    const int row = c >> 2, seg = c & 3;
                    cp_async16(sbase + LSA_OP + row * GPITCH_B + seg * 16,
                               BT + (size_t)(gnb + row) * K + kc * 32 + seg * 8, 16);
                }
            };

            load_stage(0, 0);
            cp_commit();

            for (int kc = 0; kc < nk; kc++) {
                const int p = kc & 1;
                if (kc + 1 < nk) {
                    load_stage(kc + 1, p ^ 1);
                    cp_commit();
                    asm volatile("cp.async.wait_group 1;");
                } else {
                    asm volatile("cp.async.wait_group 0;");
                }
                __syncthreads();
                const char* sA = smem + p * LSTAGE_B;
                const char* sB = sA + LSA_OP;
#pragma unroll
                for (int ks = 0; ks < 2; ks++) {
                    const int kb = ks * 32 + t4 * 4;
                    uint32_t af[2][4];
                    uint32_t bf[8][2];
#pragma unroll
                    for (int mt = 0; mt < 2; mt++) {
                        const int r = wr * 32 + mt * 16 + g4;
                        af[mt][0] = *(const uint32_t*)(sA + r * GPITCH_B + kb);
                        af[mt][1] = *(const uint32_t*)(sA + (r + 8) * GPITCH_B + kb);
                        af[mt][2] = *(const uint32_t*)(sA + r * GPITCH_B + kb + 16);
                        af[mt][3] = *(const uint32_t*)(sA + (r + 8) * GPITCH_B + kb + 16);
                    }
#pragma unroll
                    for (int nt = 0; nt < 8; nt++) {
                        const int n = wc * 64 + nt * 8 + g4;
                        bf[nt][0] = *(const uint32_t*)(sB + n * GPITCH_B + kb);
                        bf[nt][1] = *(const uint32_t*)(sB + n * GPITCH_B + kb + 16);
                    }
#pragma unroll
                    for (int mt = 0; mt < 2; mt++)
#pragma unroll
                        for (int nt = 0; nt < 8; nt++)
                            mma_f16(acc[mt][nt], af[mt][0], af[mt][1], af[mt][2], af[mt][3],
                                    bf[nt][0], bf[nt][1]);
                }
                __syncthreads();
            }
        }

#pragma unroll
        for (int mt = 0; mt < 2; mt++) {
            const int r0 = by * 64 + wr * 32 + mt * 16 + g4;
            const int r1 = r0 + 8;
            const int tok0 = ((r0 >> 8) << 12) + (t << 8) + (r0 & 255);
            const int tok1 = ((r1 >> 8) << 12) + (t << 8) + (r1 & 255);
            const int bt0 = tok0 >> 8, bt1 = tok1 >> 8;
#pragma unroll
            for (int nt = 0; nt < 8; nt++) {
                const int col = bx * 128 + wc * 64 + nt * 8 + t4 * 2;
                __half2 gx0 = *(const __half2*)(gx + (size_t)tok0 * 4096 + col);
                __half2 gx1 = *(const __half2*)(gx + (size_t)tok1 * 4096 + col);
                float v0 = acc[mt][nt][0] + __half2float(__low2half(gx0));
                float v1 = acc[mt][nt][1] + __half2float(__high2half(gx0));
                float v2 = acc[mt][nt][2] + __half2float(__low2half(gx1));
                float v3 = acc[mt][nt][3] + __half2float(__high2half(gx1));
                float p0 = __shfl_xor_sync(0xffffffffu, v0, 1);
                float p1 = __shfl_xor_sync(0xffffffffu, v1, 1);
                float p2 = __shfl_xor_sync(0xffffffffu, v2, 1);
                float p3 = __shfl_xor_sync(0xffffffffu, v3, 1);
                if (!(lane & 1)) {
                    const int j = col >> 2;
                    {
                        float cprev = (t == 0) ? 0.f : cst[r0 * 1024 + j];
                        float cc = sigm(v1) * cprev + sigm(v0) * tanh_fast(p0);
                        float hh = sigm(p1) * tanh_fast(cc);
                        cst[r0 * 1024 + j] = cc;
                        hnext[r0 * 1024 + j] = __float2half(hh);
                        float rg = rmod[bt0 * MODW + 2048 + j];
                        outp[(size_t)tok0 * 1024 + j] =
                            __half2float(xbuf[(size_t)tok0 * 1024 + j]) + rg * hh;
                    }
                    {
                        float cprev = (t == 0) ? 0.f : cst[r1 * 1024 + j];
                        float cc = sigm(v3) * cprev + sigm(v2) * tanh_fast(p2);
                        float hh = sigm(p3) * tanh_fast(cc);
                        cst[r1 * 1024 + j] = cc;
                        hnext[r1 * 1024 + j] = __float2half(hh);
                        float rg = rmod[bt1 * MODW + 2048 + j];
                        outp[(size_t)tok1 * 1024 + j] =
                            __half2float(xbuf[(size_t)tok1 * 1024 + j]) + rg * hh;
                    }
                }
            }
        }

        if (t < TT - 1) {
            __syncthreads();
            if (tid == 0) {
                __threadfence();
                atomicAdd(&g_lstm_bar, 1u);
                const unsigned int target = 256u * (unsigned int)(t + 1);
                while (atomicAdd(&g_lstm_bar, 0u) < target) {}
                __threadfence();
            }
            __syncthreads();
        }
    }
}

// ---------------- batched weight transpose: all matrices in one launch ----------------
struct TransDesc { const float* W; __half* WT; int K; int N; int perm; int tileStart; };
struct TransArgs { TransDesc d[13]; };

__global__ __launch_bounds__(256)
void transpose_all_kernel(TransArgs a) {
    __shared__ float t[32][33];
    const int bid = blockIdx.x;
    int i = 0;
#pragma unroll
    for (int k = 0; k < 12; k++) if (bid >= a.d[k + 1].tileStart) i = k + 1;
    const TransDesc& td = a.d[i];
    const int local = bid - td.tileStart;
    const int ntx = td.N / 32;
    const int n0 = (local % ntx) * 32, k0 = (local / ntx) * 32;
    const int tx = threadIdx.x & 31, ty = threadIdx.x >> 5;
#pragma unroll
    for (int j = 0; j < 4; j++)
        t[ty + j * 8][tx] = td.W[(size_t)(k0 + ty + j * 8) * td.N + n0 + tx];
    __syncthreads();
#pragma unroll
    for (int j = 0; j < 4; j++) {
        int n = n0 + ty + j * 8;
        int nd = td.perm ? (4 * (n & 1023) + (n >> 10)) : n;
        td.WT[(size_t)nd * td.K + k0 + tx] = __float2half(t[tx][ty + j * 8]);
    }
}

// ---------------- LayerNorm + adaLN modulate (fp32 x in, fp16 out) ----------------
__global__ __launch_bounds__(256)
void ln_mod_kernel(const float* __restrict__ x, const float* __restrict__ mod,
                   int mstride, int shift_off, int scale_off, __half* __restrict__ out) {
    __shared__ float red[16];
    const int tok = blockIdx.x;
    const int tid = threadIdx.x;
    const float* xr = x + (size_t)tok * DD;
    float v[4];
    float s = 0.f, s2 = 0.f;
#pragma unroll
    for (int k = 0; k < 4; k++) {
        float f = xr[tid + k * 256];
        v[k] = f; s += f; s2 += f * f;
    }
#pragma unroll
    for (int o = 16; o; o >>= 1) {
        s += __shfl_xor_sync(0xffffffffu, s, o);
        s2 += __shfl_xor_sync(0xffffffffu, s2, o);
    }
    if ((tid & 31) == 0) { red[tid >> 5] = s; red[8 + (tid >> 5)] = s2; }
    __syncthreads();
    if (tid == 0) {
        float a = 0.f, b = 0.f;
        for (int i = 0; i < 8; i++) { a += red[i]; b += red[8 + i]; }
        red[0] = a; red[8] = b;
    }
    __syncthreads();
    const float mean = red[0] * (1.f / DD);
    const float var = red[8] * (1.f / DD) - mean * mean;
    const float inv = rsqrtf(var + 1e-6f);
    const int bt = tok >> 8;
    const float* m = mod + (size_t)bt * mstride;
    __half* orow = out + (size_t)tok * DD;
#pragma unroll
    for (int k = 0; k < 4; k++) {
        int d = tid + k * 256;
        float ln = (v[k] - mean) * inv;
        orow[d] = __float2half(ln * (1.f + m[scale_off + d]) + m[shift_off + d]);
    }
}

// -------- fused gated residual add + LayerNorm + modulate (fp16 delta; XIN32 selects xin) --
template<int XIN32>
__global__ __launch_bounds__(256)
void ga_ln_kernel(const void* __restrict__ xin, const __half* __restrict__ delta,
                  const float* __restrict__ modg, int gstride, int gate_off,
                  const float* __restrict__ modl, int lstride, int shift_off, int scale_off,
                  __half* __restrict__ xout, __half* __restrict__ lnout) {
    __shared__ float red[16];
    const int tok = blockIdx.x;
    const int tid = threadIdx.x;
    const int bt = tok >> 8;
    const __half* dr = delta + (size_t)tok * DD;
    const float* mg = modg + (size_t)bt * gstride + gate_off;
    float v[4];
    float s = 0.f, s2 = 0.f;
    __half* xo = xout + (size_t)tok * DD;
#pragma unroll
    for (int k = 0; k < 4; k++) {
        int d = tid + k * 256;
        float xv;
        if (XIN32) xv = ((const float*)xin)[(size_t)tok * DD + d];
        else       xv = __half2float(((const __half*)xin)[(size_t)tok * DD + d]);
        float f = xv + mg[d] * __half2float(dr[d]);
        xo[d] = __float2half(f);
        v[k] = f; s += f; s2 += f * f;
    }
#pragma unroll
    for (int o = 16; o; o >>= 1) {
        s += __shfl_xor_sync(0xffffffffu, s, o);
        s2 += __shfl_xor_sync(0xffffffffu, s2, o);
    }
    if ((tid & 31) == 0) { red[tid >> 5] = s; red[8 + (tid >> 5)] = s2; }
    __syncthreads();
    if (tid == 0) {
        float a = 0.f, b = 0.f;
        for (int i = 0; i < 8; i++) { a += red[i]; b += red[8 + i]; }
        red[0] = a; red[8] = b;
    }
    __syncthreads();
    const float mean = red[0] * (1.f / DD);
    const float var = red[8] * (1.f / DD) - mean * mean;
    const float inv = rsqrtf(var + 1e-6f);
    const float* ml = modl + (size_t)bt * lstride;
    __half* lo = lnout + (size_t)tok * DD;
#pragma unroll
    for (int k = 0; k < 4; k++) {
        int d = tid + k * 256;
        float ln = (v[k] - mean) * inv;
        lo[d] = __float2half(ln * (1.f + ml[scale_off + d]) + ml[shift_off + d]);
    }
}

// ---------------- setup: silu + combined ada bias + permuted lstm bias + barrier reset ----
__global__ void setup_kernel(const float* __restrict__ c, __half* __restrict__ csh,
                             const float* __restrict__ sbp, const float* __restrict__ tbp,
                             const float* __restrict__ rbp, float* __restrict__ adab,
                             const float* __restrict__ lba, const float* __restrict__ lbb,
                             float* __restrict__ lbias) {
    int i = blockIdx.x * 256 + threadIdx.x;
    if (i == 0) g_lstm_bar = 0u;
    if (i < NBT * DD) {
        float v = c[i];
        csh[i] = __float2half(v / (1.f + __expf(-v)));
    }
    if (i < MODW) {
        float b;
        if (i < 6144) b = sbp[i];
        else if (i < 12288) b = tbp[i - 6144];
        else b = rbp[i - 12288];
        adab[i] = b;
    }
    if (i < 4 * DD) {
        int j = i >> 2, g = i & 3;
        lbias[i] = lba[g * 1024 + j] + lbb[g * 1024 + j];
    }
}

// ======= spatial attention via mma.sync fp16 flash (L=256, dh=64, non-causal) =======
__global__ __launch_bounds__(256, 2)
void spatial_attn_tc(const __half* __restrict__ qkv, __half* __restrict__ out) {
    __shared__ __half sQ[128 * 72];
    __shared__ __half sK[64 * 72];
    __shared__ __half sVT[64 * 72];
    const int bid = blockIdx.x;
    const int qhalf = bid & 1;
    const int head = (bid >> 1) & 15;
    const int n = bid >> 5;
    const int tid = threadIdx.x;
    const int lane = tid & 31;
    const int wid = tid >> 5;
    const int g4 = lane >> 2, t4 = lane & 3;
    const size_t rowbase = (size_t)n * 256;

#pragma unroll
    for (int i = 0; i < 4; i++) {
        int idx = tid + i * 256;
        int row = idx >> 3, seg = idx & 7;
        *(uint4*)&sQ[row * 72 + seg * 8] =
            *(const uint4*)(qkv + (rowbase + qhalf * 128 + row) * 3072 + head * 64 + seg * 8);
    }
    __syncthreads();

    uint32_t af[4][4];
    {
        const int r = wid * 16 + g4;
#pragma unroll
        for (int ks = 0; ks < 4; ks++) {
            af[ks][0] = *(const uint32_t*)&sQ[r * 72 + ks * 16 + t4 * 2];
            af[ks][1] = *(const uint32_t*)&sQ[(r + 8) * 72 + ks * 16 + t4 * 2];
            af[ks][2] = *(const uint32_t*)&sQ[r * 72 + ks * 16 + 8 + t4 * 2];
            af[ks][3] = *(const uint32_t*)&sQ[(r + 8) * 72 + ks * 16 + 8 + t4 * 2];
        }
    }

    float O[8][4];
#pragma unroll
    for (int i = 0; i < 8; i++)
#pragma unroll
        for (int q = 0; q < 4; q++) O[i][q] = 0.f;
    float m0 = -1e30f, m1 = -1e30f, l0 = 0.f, l1 = 0.f;

    for (int kt = 0; kt < 4; kt++) {
#pragma unroll
        for (int i = 0; i < 2; i++) {
            int idx = tid + i * 256;
            int row = idx >> 3, seg = idx & 7;
            const __half* src = qkv + (rowbase + kt * 64 + row) * 3072 + 1024 + head * 64 + seg * 8;
            *(uint4*)&sK[row * 72 + seg * 8] = *(const uint4*)src;
            __half vv[8];
            *(uint4*)vv = *(const uint4*)(src + 1024);
#pragma unroll
            for (int jj = 0; jj < 8; jj++) sVT[(seg * 8 + jj) * 72 + row] = vv[jj];
        }
        __syncthreads();

        float sc[8][4];
#pragma unroll
        for (int nt = 0; nt < 8; nt++) {
#pragma unroll
            for (int q = 0; q < 4; q++) sc[nt][q] = 0.f;
#pragma unroll
            for (int ks = 0; ks < 4; ks++) {
                uint32_t b0 = *(const uint32_t*)&sK[(nt * 8 + g4) * 72 + ks * 16 + t4 * 2];
                uint32_t b1 = *(const uint32_t*)&sK[(nt * 8 + g4) * 72 + ks * 16 + 8 + t4 * 2];
                mma_f16(sc[nt], af[ks][0], af[ks][1], af[ks][2], af[ks][3], b0, b1);
            }
        }

        float mx0 = -1e30f, mx1 = -1e30f;
#pragma unroll
        for (int nt = 0; nt < 8; nt++) {
            sc[nt][0] *= 0.125f; sc[nt][1] *= 0.125f;
            sc[nt][2] *= 0.125f; sc[nt][3] *= 0.125f;
            mx0 = fmaxf(mx0, fmaxf(sc[nt][0], sc[nt][1]));
            mx1 = fmaxf(mx1, fmaxf(sc[nt][2], sc[nt][3]));
        }
        mx0 = fmaxf(mx0, __shfl_xor_sync(0xffffffffu, mx0, 1));
        mx0 = fmaxf(mx0, __shfl_xor_sync(0xffffffffu, mx0, 2));
        mx1 = fmaxf(mx1, __shfl_xor_sync(0xffffffffu, mx1, 1));
        mx1 = fmaxf(mx1, __shfl_xor_sync(0xffffffffu, mx1, 2));
        const float mn0 = fmaxf(m0, mx0), mn1 = fmaxf(m1, mx1);
        const float al0 = __expf(m0 - mn0), al1 = __expf(m1 - mn1);
        m0 = mn0; m1 = mn1;

        float sum0 = 0.f, sum1 = 0.f;
        uint32_t aP[8][2];
#pragma unroll
        for (int nt = 0; nt < 8; nt++) {
            float p0 = __expf(sc[nt][0] - mn0);
            float p1 = __expf(sc[nt][1] - mn0);
            float p2 = __expf(sc[nt][2] - mn1);
            float p3 = __expf(sc[nt][3] - mn1);
            sum0 += p0 + p1; sum1 += p2 + p3;
            aP[nt][0] = h2_as_u32(__floats2half2_rn(p0, p1));
            aP[nt][1] = h2_as_u32(__floats2half2_rn(p2, p3));
        }
        sum0 += __shfl_xor_sync(0xffffffffu, sum0, 1);
        sum0 += __shfl_xor_sync(0xffffffffu, sum0, 2);
        sum1 += __shfl_xor_sync(0xffffffffu, sum1, 1);
        sum1 += __shfl_xor_sync(0xffffffffu, sum1, 2);
        l0 = l0 * al0 + sum0;
        l1 = l1 * al1 + sum1;
#pragma unroll
        for (int nt2 = 0; nt2 < 8; nt2++) {
            O[nt2][0] *= al0; O[nt2][1] *= al0;
            O[nt2][2] *= al1; O[nt2][3] *= al1;
        }

#pragma unroll
        for (int ks2 = 0; ks2 < 4; ks2++) {
            const uint32_t a0 = aP[2 * ks2][0], a1 = aP[2 * ks2][1];
            const uint32_t a2 = aP[2 * ks2 + 1][0], a3 = aP[2 * ks2 + 1][1];
#pragma unroll
            for (int nt2 = 0; nt2 < 8; nt2++) {
                uint32_t b0 = *(const uint32_t*)&sVT[(nt2 * 8 + g4) * 72 + ks2 * 16 + t4 * 2];
                uint32_t b1 = *(const uint32_t*)&sVT[(nt2 * 8 + g4) * 72 + ks2 * 16 + 8 + t4 * 2];
                mma_f16(O[nt2], a0, a1, a2, a3, b0, b1);
            }
        }
        __syncthreads();
    }

    const float inv0 = 1.f / l0, inv1 = 1.f / l1;
    const int q0 = qhalf * 128 + wid * 16 + g4;
#pragma unroll
    for (int nt2 = 0; nt2 < 8; nt2++) {
        const int col = head * 64 + nt2 * 8 + t4 * 2;
        *(__half2*)(out + (rowbase + q0) * 1024 + col) =
            __floats2half2_rn(O[nt2][0] * inv0, O[nt2][1] * inv0);
        *(__half2*)(out + (rowbase + q0 + 8) * 1024 + col) =
            __floats2half2_rn(O[nt2][2] * inv1, O[nt2][3] * inv1);
    }
}

// ---------------- temporal attention (T=16, dh=64, causal; fp16 qkv in/out) ----------------
__global__ __launch_bounds__(128)
void temporal_attn_kernel(const __half* __restrict__ qkv, __half* __restrict__ out) {
    __shared__ float Q[16][65], K[16][65], V[16][65], S[16][17];
    const int bid = blockIdx.x;
    const int head = bid & 15;
    const int n = bid >> 4;
    const int b = n >> 8;
    const int hw = n & 255;
    const int tid = threadIdx.x;
    const size_t tokbase = (size_t)b * 4096 + hw;

    for (int i = tid; i < 16 * 64; i += 128) {
        int t = i >> 6, d = i & 63;
        size_t base = (tokbase + (size_t)t * 256) * 3072 + head * 64 + d;
        Q[t][d] = __half2float(qkv[base]);
        K[t][d] = __half2float(qkv[base + 1024]);
        V[t][d] = __half2float(qkv[base + 2048]);
    }
    __syncthreads();

    for (int idx = tid; idx < 256; idx += 128) {
        int qi = idx >> 4, kj = idx & 15;
        float s;
        if (kj <= qi) {
            float acc = 0.f;
#pragma unroll
            for (int d = 0; d < 64; d++) acc += Q[qi][d] * K[kj][d];
            s = acc * 0.125f;
        } else s = -1e30f;
        S[qi][kj] = s;
    }
    __syncthreads();

    {
        const int row = tid >> 3, c0 = tid & 7;
        float mx = fmaxf(S[row][c0], S[row][c0 + 8]);
#pragma unroll
        for (int o = 4; o; o >>= 1) mx = fmaxf(mx, __shfl_xor_sync(0xffffffffu, mx, o));
        float e0 = __expf(S[row][c0] - mx), e1 = __expf(S[row][c0 + 8] - mx);
        float sum = e0 + e1;
#pragma unroll
        for (int o = 4; o; o >>= 1) sum += __shfl_xor_sync(0xffffffffu, sum, o);
        float inv = 1.f / sum;
        S[row][c0] = e0 * inv;
        S[row][c0 + 8] = e1 * inv;
    }
    __syncthreads();

    for (int i = tid; i < 16 * 64; i += 128) {
        int qi = i >> 6, d = i & 63;
        float acc = 0.f;
#pragma unroll
        for (int k = 0; k < 16; k++) acc = fmaf(S[qi][k], V[k][d], acc);
        out[(tokbase + (size_t)qi * 256) * 1024 + head * 64 + d] = __float2half(acc);
    }
}

// ---------------- launch helpers ----------------
static void gemm(const __half* A, const __half* BT, const float* bias, void* C,
                 int M, int N, int K, int epi, int outh) {
    dim3 g(N / 128, (M + 127) / 128);
    if (epi == 1)      gemm_tc<1, 1><<<g, 128, GTC_SMEM_TOTAL>>>(A, BT, bias, C, M, N, K);
    else if (outh)     gemm_tc<0, 1><<<g, 128, GTC_SMEM_TOTAL>>>(A, BT, bias, C, M, N, K);
    else               gemm_tc<0, 0><<<g, 128, GTC_SMEM_TOTAL>>>(A, BT, bias, C, M, N, K);
}

extern "C" void kernel_launch(void* const* d_in, const int* in_sizes, int n_in,
                              void* d_out, int out_size) {
    const float* x        = (const float*)d_in[0];
    const float* c        = (const float*)d_in[1];
    const float* s_ada_w  = (const float*)d_in[2];
    const float* s_ada_b  = (const float*)d_in[3];
    const float* t_ada_w  = (const float*)d_in[4];
    const float* t_ada_b  = (const float*)d_in[5];
    const float* r_ada_w  = (const float*)d_in[6];
    const float* r_ada_b  = (const float*)d_in[7];
    const float* s_qkv_w  = (const float*)d_in[8];
    const float* s_out_w  = (const float*)d_in[9];
    const float* s_out_b  = (const float*)d_in[10];
    const float* t_qkv_w  = (const float*)d_in[11];
    const float* t_out_w  = (const float*)d_in[12];
    const float* t_out_b  = (const float*)d_in[13];
    const float* s_mlp_w1 = (const float*)d_in[14];
    const float* s_mlp_b1 = (const float*)d_in[15];
    const float* s_mlp_w2 = (const float*)d_in[16];
    const float* s_mlp_b2 = (const float*)d_in[17];
    const float* t_mlp_w1 = (const float*)d_in[18];
    const float* t_mlp_b1 = (const float*)d_in[19];
    const float* t_mlp_w2 = (const float*)d_in[20];
    const float* t_mlp_b2 = (const float*)d_in[21];
    const float* lstm_w_ih = (const float*)d_in[22];
    const float* lstm_w_hh = (const float*)d_in[23];
    const float* lstm_b_ih = (const float*)d_in[24];
    const float* lstm_b_hh = (const float*)d_in[25];
    float* out = (float*)d_out;

    cudaFuncSetAttribute(gemm_tc<0, 0>, cudaFuncAttributeMaxDynamicSharedMemorySize, GTC_SMEM_TOTAL);
    cudaFuncSetAttribute(gemm_tc<0, 1>, cudaFuncAttributeMaxDynamicSharedMemorySize, GTC_SMEM_TOTAL);
    cudaFuncSetAttribute(gemm_tc<1, 1>, cudaFuncAttributeMaxDynamicSharedMemorySize, GTC_SMEM_TOTAL);
    cudaFuncSetAttribute(lstm_persist_tc, cudaFuncAttributeMaxDynamicSharedMemorySize, LSTM_SMEM_TOTAL);

    __half *csh, *h1h, *qkvh, *deltah, *mlph, *gatesxh, *hstateh, *hstate2h, *wTh, *xbufh;
    float *modall, *adab, *cstate, *lstmbias;
    cudaGetSymbolAddress((void**)&csh, g_csh);
    cudaGetSymbolAddress((void**)&modall, g_modall);
    cudaGetSymbolAddress((void**)&adab, g_adab);
    cudaGetSymbolAddress((void**)&xbufh, g_xbufh);
    cudaGetSymbolAddress((void**)&h1h, g_h1h);
    cudaGetSymbolAddress((void**)&qkvh, g_qkvh);
    cudaGetSymbolAddress((void**)&deltah, g_deltah);
    cudaGetSymbolAddress((void**)&mlph, g_mlph);
    cudaGetSymbolAddress((void**)&gatesxh, g_gatesxh);
    cudaGetSymbolAddress((void**)&hstateh, g_hstateh);
    cudaGetSymbolAddress((void**)&hstate2h, g_hstate2h);
    cudaGetSymbolAddress((void**)&cstate, g_cstate);
    cudaGetSymbolAddress((void**)&lstmbias, g_lstmbias);
    cudaGetSymbolAddress((void**)&wTh, g_wTh);

    float* smod = modall;              // stride MODW
    float* tmod = modall + 6144;       // stride MODW
    float* rmod = modall + 12288;      // stride MODW

    const size_t MEG = 1048576;
    __half* wt_ada   = wTh + 0 * MEG;   // [15360,1024]: sada|tada|rada contiguous
    __half* wt_sqkv  = wTh + 15 * MEG;
    __half* wt_sout  = wTh + 18 * MEG;
    __half* wt_tqkv  = wTh + 19 * MEG;
    __half* wt_tout  = wTh + 22 * MEG;
    __half* wt_smlp1 = wTh + 23 * MEG;
    __half* wt_smlp2 = wTh + 27 * MEG;
    __half* wt_tmlp1 = wTh + 31 * MEG;
    __half* wt_tmlp2 = wTh + 35 * MEG;
    __half* wt_lih   = wTh + 39 * MEG;  // gate-interleaved [4096,1024]
    __half* wt_lhh   = wTh + 43 * MEG;  // gate-interleaved [4096,1024]

    // batched transpose: all 13 matrices, one launch
    {
        TransArgs ta;
        auto set = [&](int i, const float* W, __half* WT, int K, int N, int perm, int start) {
            ta.d[i].W = W; ta.d[i].WT = WT; ta.d[i].K = K; ta.d[i].N = N;
            ta.d[i].perm = perm; ta.d[i].tileStart = start;
        };
        int s = 0;
        set(0,  s_ada_w,  wt_ada,            1024, 6144, 0, s); s += (6144 / 32) * 32;
        set(1,  t_ada_w,  wt_ada + 6 * MEG,  1024, 6144, 0, s); s += (6144 / 32) * 32;
        set(2,  r_ada_w,  wt_ada + 12 * MEG, 1024, 3072, 0, s); s += (3072 / 32) * 32;
        set(3,  s_qkv_w,  wt_sqkv,  1024, 3072, 0, s); s += (3072 / 32) * 32;
        set(4,  s_out_w,  wt_sout,  1024, 1024, 0, s); s += (1024 / 32) * 32;
        set(5,  t_qkv_w,  wt_tqkv,  1024, 3072, 0, s); s += (3072 / 32) * 32;
        set(6,  t_out_w,  wt_tout,  1024, 1024, 0, s); s += (1024 / 32) * 32;
        set(7,  s_mlp_w1, wt_smlp1, 1024, 4096, 0, s); s += (4096 / 32) * 32;
        set(8,  s_mlp_w2, wt_smlp2, 4096, 1024, 0, s); s += (1024 / 32) * 128;
        set(9,  t_mlp_w1, wt_tmlp1, 1024, 4096, 0, s); s += (4096 / 32) * 32;
        set(10, t_mlp_w2, wt_tmlp2, 4096, 1024, 0, s); s += (1024 / 32) * 128;
        set(11, lstm_w_ih, wt_lih,  1024, 4096, 1, s); s += (4096 / 32) * 32;
        set(12, lstm_w_hh, wt_lhh,  1024, 4096, 1, s); s += (4096 / 32) * 32;
        transpose_all_kernel<<<s, 256>>>(ta);
    }

    // setup (silu + ada bias concat + lstm bias permute + barrier reset)
    setup_kernel<<<(NBT * DD + 255) / 256, 256>>>(c, csh, s_ada_b, t_ada_b, r_ada_b, adab,
                                                  lstm_b_ih, lstm_b_hh, lstmbias);
    gemm(csh, wt_ada, adab, modall, NBT, MODW, DD, 0, 0);

    // ---- spatial attention ----
    ln_mod_kernel<<<NTOK, 256>>>(x, smod, MODW, 0, DD, h1h);
    gemm(h1h, wt_sqkv, nullptr, qkvh, NTOK, 3 * DD, DD, 0, 1);
    spatial_attn_tc<<<1024, 256>>>(qkvh, h1h);
    gemm(h1h, wt_sout, s_out_b, deltah, NTOK, DD, DD, 0, 1);
    ga_ln_kernel<1><<<NTOK, 256>>>(x, deltah, smod, MODW, 2 * DD,
                                   smod, MODW, 3 * DD, 4 * DD, xbufh, h1h);

    // ---- spatial MLP ----
    gemm(h1h, wt_smlp1, s_mlp_b1, mlph, NTOK, 4 * DD, DD, 1, 1);
    gemm(mlph, wt_smlp2, s_mlp_b2, deltah, NTOK, DD, 4 * DD, 0, 1);
    ga_ln_kernel<0><<<NTOK, 256>>>(xbufh, deltah, smod, MODW, 5 * DD,
                                   tmod, MODW, 0, DD, xbufh, h1h);

    // ---- temporal attention (causal) ----
    gemm(h1h, wt_tqkv, nullptr, qkvh, NTOK, 3 * DD, DD, 0, 1);
    temporal_attn_kernel<<<8192, 128>>>(qkvh, h1h);
    gemm(h1h, wt_tout, t_out_b, deltah, NTOK, DD, DD, 0, 1);
    ga_ln_kernel<0><<<NTOK, 256>>>(xbufh, deltah, tmod, MODW, 2 * DD,
                                   tmod, MODW, 3 * DD, 4 * DD, xbufh, h1h);

    // ---- temporal MLP ----
    gemm(h1h, wt_tmlp1, t_mlp_b1, mlph, NTOK, 4 * DD, DD, 1, 1);
    gemm(mlph, wt_tmlp2, t_mlp_b2, deltah, NTOK, DD, 4 * DD, 0, 1);
    ga_ln_kernel<0><<<NTOK, 256>>>(xbufh, deltah, tmod, MODW, 5 * DD,
                                   rmod, MODW, 0, DD, xbufh, h1h);

    // ---- LSTM branch: persistent kernel, all 16 steps ----
    gemm(h1h, wt_lih, lstmbias, gatesxh, NTOK, 4 * DD, DD, 0, 1);
    lstm_persist_tc<<<dim3(32, 8), 128, LSTM_SMEM_TOTAL>>>(
        hstateh, hstate2h, wt_lhh, gatesxh, cstate, xbufh, rmod, out);
}

// round 15
// speedup vs baseline: 1.5517x; 1.0289x over previous
#include <cuda_runtime.h>
#include <cuda_fp16.h>
#include <math.h>
#include <cstdint>

// Problem constants
#define DD   1024
#define NTOK 8192      // B*T*H*W
#define NBT  32        // B*T
#define NSEQ 512       // B*H*W
#define TT   16
#define MODW 15360     // 6*DD + 6*DD + 3*DD combined ada width

// ---------------- scratch (device globals; no allocations allowed) ----------------
__device__ __half g_csh[NBT * DD];
__device__ float  g_modall[NBT * MODW];
__device__ float  g_adab[MODW];
__device__ __half g_xbufh[NTOK * DD];
__device__ __half g_h1h[NTOK * DD];
__device__ __half g_qkvh[NTOK * 3 * DD];
__device__ __half g_mlph[NTOK * 4 * DD];
__device__ __half g_gatesxh[NTOK * 4 * DD];
__device__ __half g_hstateh[NSEQ * DD];
__device__ __half g_hstate2h[NSEQ * DD];
__device__ float  g_cstate[NSEQ * DD];
__device__ float  g_lstmbias[4 * DD];
__device__ unsigned int g_lstm_bar;
__device__ __half g_wTh[47u * 1048576u];   // transposed fp16 weights

__device__ __forceinline__ float tanh_fast(float x) {
    float r; asm("tanh.approx.f32 %0, %1;" : "=f"(r) : "f"(x)); return r;
}
__device__ __forceinline__ float gelu_tanh(float x) {
    return 0.5f * x * (1.f + tanh_fast(0.7978845608028654f * (x + 0.044715f * x * x * x)));
}
__device__ __forceinline__ float sigm(float x) { return 0.5f * (1.f + tanh_fast(0.5f * x)); }
__device__ __forceinline__ uint32_t h2_as_u32(__half2 h) {
    uint32_t u; *reinterpret_cast<__half2*>(&u) = h; return u;
}
__device__ __forceinline__ void mma_f16(float d[4], uint32_t a0, uint32_t a1, uint32_t a2,
                                        uint32_t a3, uint32_t b0, uint32_t b1) {
    asm volatile(
        "mma.sync.aligned.m16n8k16.row.col.f32.f16.f16.f32 "
        "{%0,%1,%2,%3}, {%4,%5,%6,%7}, {%8,%9}, {%0,%1,%2,%3};\n"
        : "+f"(d[0]), "+f"(d[1]), "+f"(d[2]), "+f"(d[3])
        : "r"(a0), "r"(a1), "r"(a2), "r"(a3), "r"(b0), "r"(b1));
}
__device__ __forceinline__ void cp_async16(uint32_t dst, const void* src, int szvalid) {
    asm volatile("cp.async.cg.shared.global [%0], [%1], 16, %2;"
                 :: "r"(dst), "l"(src), "r"(szvalid));
}
__device__ __forceinline__ void cp_commit() { asm volatile("cp.async.commit_group;"); }

// ================== fp16 tensor-core GEMM: C[M,N] = A[M,K] @ BT[N,K]^T ==================
// 128 threads = 4 warps (2x2), warp tile 64x64, block tile 128x128x32, 4-stage cp.async.
// EPI: 0 = +bias, 1 = gelu(tanh)(x+bias), 2 = gated residual add (xout = xres + gate*(v+bias))
// OUTH: 0 = fp32 C, 1 = fp16 C. XR32 (EPI==2 only): xres is fp32 (else fp16).
#define GPITCH_B   80
#define GOP_BYTES  (128 * GPITCH_B)
#define GSTAGE_B   (2 * GOP_BYTES)       // 20480 per stage
#define GTC_NSTAGE 4
#define GTC_SMEM_TOTAL (GTC_NSTAGE * GSTAGE_B)   // 81920 bytes

template<int EPI, int OUTH, int XR32>
__global__ __launch_bounds__(128, 2)
void gemm_tc(const __half* __restrict__ A, const __half* __restrict__ BT,
             const float* __restrict__ bias, void* __restrict__ Cout,
             int M, int N, int K,
             const void* __restrict__ Xres, const float* __restrict__ modall, int goff) {
    extern __shared__ char smem[];
    const uint32_t sb = (uint32_t)__cvta_generic_to_shared(smem);
    const int tid = threadIdx.x;
    const int lane = tid & 31;
    const int wid = tid >> 5;
    const int wr = wid >> 1;
    const int wc = wid & 1;
    const int g4 = lane >> 2, t4 = lane & 3;
    const int bx = blockIdx.x, by = blockIdx.y;
    const int gra = by * 128;
    const int gnb = bx * 128;

    float acc[4][8][4];
#pragma unroll
    for (int mt = 0; mt < 4; mt++)
#pragma unroll
        for (int nt = 0; nt < 8; nt++)
#pragma unroll
            for (int q = 0; q < 4; q++) acc[mt][nt][q] = 0.f;

    const int nk = K >> 5;

    auto load_stage = [&](int kc, int s) {
        const uint32_t sbase = sb + s * GSTAGE_B;
#pragma unroll
        for (int i = 0; i < 4; i++) {
            const int c = tid + i * 128;
            const int row = c >> 2, seg = c & 3;
            const int ga = gra + row;
            const bool ok = ga < M;
            cp_async16(sbase + row * GPITCH_B + seg * 16,
                       A + (size_t)(ok ? ga : 0) * K + kc * 32 + seg * 8, ok ? 16 : 0);
            cp_async16(sbase + GOP_BYTES + row * GPITCH_B + seg * 16,
                       BT + (size_t)(gnb + row) * K + kc * 32 + seg * 8, 16);
        }
    };

    load_stage(0, 0); cp_commit();
    load_stage(1, 1); cp_commit();
    load_stage(2, 2); cp_commit();

    for (int kc = 0; kc < nk; kc++) {
        if (kc < nk - 2)       asm volatile("cp.async.wait_group 2;");
        else if (kc == nk - 2) asm volatile("cp.async.wait_group 1;");
        else                   asm volatile("cp.async.wait_group 0;");
        __syncthreads();
        if (kc + 3 < nk) { load_stage(kc + 3, (kc + 3) & (GTC_NSTAGE - 1)); cp_commit(); }

        const char* sA = smem + (kc & (GTC_NSTAGE - 1)) * GSTAGE_B;
        const char* sB = sA + GOP_BYTES;
#pragma unroll
        for (int ks = 0; ks < 2; ks++) {
            const int kb = ks * 32 + t4 * 4;
            uint32_t af[4][4];
            uint32_t bf[8][2];
#pragma unroll
            for (int mt = 0; mt < 4; mt++) {
                const int r = wr * 64 + mt * 16 + g4;
                af[mt][0] = *(const uint32_t*)(sA + r * GPITCH_B + kb);
                af[mt][1] = *(const uint32_t*)(sA + (r + 8) * GPITCH_B + kb);
                af[mt][2] = *(const uint32_t*)(sA + r * GPITCH_B + kb + 16);
                af[mt][3] = *(const uint32_t*)(sA + (r + 8) * GPITCH_B + kb + 16);
            }
#pragma unroll
            for (int nt = 0; nt < 8; nt++) {
                const int n = wc * 64 + nt * 8 + g4;
                bf[nt][0] = *(const uint32_t*)(sB + n * GPITCH_B + kb);
                bf[nt][1] = *(const uint32_t*)(sB + n * GPITCH_B + kb + 16);
            }
#pragma unroll
            for (int mt = 0; mt < 4; mt++)
#pragma unroll
                for (int nt = 0; nt < 8; nt++)
                    mma_f16(acc[mt][nt], af[mt][0], af[mt][1], af[mt][2], af[mt][3],
                            bf[nt][0], bf[nt][1]);
        }
    }

    // gate row pointer (EPI==2): 128-row tile is bt-aligned (256 rows/bt) => bt = by>>1
    const float* gp = (EPI == 2) ? (modall + (size_t)(by >> 1) * MODW + goff) : nullptr;

#pragma unroll
    for (int mt = 0; mt < 4; mt++) {
        const int r0 = by * 128 + wr * 64 + mt * 16 + g4;
#pragma unroll
        for (int nt = 0; nt < 8; nt++) {
            const int col = bx * 128 + wc * 64 + nt * 8 + t4 * 2;
            float b0 = 0.f, b1 = 0.f;
            if (bias) { b0 = __ldg(bias + col); b1 = __ldg(bias + col + 1); }
            float v0 = acc[mt][nt][0] + b0;
            float v1 = acc[mt][nt][1] + b1;
            float v2 = acc[mt][nt][2] + b0;
            float v3 = acc[mt][nt][3] + b1;
            if (EPI == 1) {
                v0 = gelu_tanh(v0); v1 = gelu_tanh(v1);
                v2 = gelu_tanh(v2); v3 = gelu_tanh(v3);
            }
            if (EPI == 2) {
                const float gg0 = __ldg(gp + col);
                const float gg1 = __ldg(gp + col + 1);
                float x0, x1, x2, x3;
                if (XR32) {
                    float2 a = *(const float2*)((const float*)Xres + (size_t)r0 * N + col);
                    float2 b = *(const float2*)((const float*)Xres + (size_t)(r0 + 8) * N + col);
                    x0 = a.x; x1 = a.y; x2 = b.x; x3 = b.y;
                } else {
                    __half2 a = *(const __half2*)((const __half*)Xres + (size_t)r0 * N + col);
                    __half2 b = *(const __half2*)((const __half*)Xres + (size_t)(r0 + 8) * N + col);
                    x0 = __half2float(__low2half(a)); x1 = __half2float(__high2half(a));
                    x2 = __half2float(__low2half(b)); x3 = __half2float(__high2half(b));
                }
                v0 = x0 + gg0 * v0; v1 = x1 + gg1 * v1;
                v2 = x2 + gg0 * v2; v3 = x3 + gg1 * v3;
                __half* Ch = (__half*)Cout;
                *(__half2*)(Ch + (size_t)r0 * N + col) = __floats2half2_rn(v0, v1);
                *(__half2*)(Ch + (size_t)(r0 + 8) * N + col) = __floats2half2_rn(v2, v3);
            } else if (OUTH) {
                __half* Ch = (__half*)Cout;
                if (r0 < M) *(__half2*)(Ch + (size_t)r0 * N + col) = __floats2half2_rn(v0, v1);
                if (r0 + 8 < M) *(__half2*)(Ch + (size_t)(r0 + 8) * N + col) = __floats2half2_rn(v2, v3);
            } else {
                float* Cf = (float*)Cout;
                if (r0 < M) *(float2*)(Cf + (size_t)r0 * N + col) = make_float2(v0, v1);
                if (r0 + 8 < M) *(float2*)(Cf + (size_t)(r0 + 8) * N + col) = make_float2(v2, v3);
            }
        }
    }
}

// ============ persistent fused LSTM: all 16 steps in one launch ============
#define LSA_OP   (64 * GPITCH_B)
#define LSB_OP   (128 * GPITCH_B)
#define LSTAGE_B (LSA_OP + LSB_OP)
#define LSTM_SMEM_TOTAL (2 * LSTAGE_B)

__global__ __launch_bounds__(128, 2)
void lstm_persist_tc(__half* __restrict__ h0buf, __half* __restrict__ h1buf,
                     const __half* __restrict__ BT, const __half* __restrict__ gx,
                     float* __restrict__ cst, const __half* __restrict__ xbuf,
                     const float* __restrict__ rmod, float* __restrict__ outp) {
    extern __shared__ char smem[];
    const uint32_t sb = (uint32_t)__cvta_generic_to_shared(smem);
    const int tid = threadIdx.x;
    const int lane = tid & 31;
    const int wid = tid >> 5;
    const int wr = wid >> 1;
    const int wc = wid & 1;
    const int g4 = lane >> 2, t4 = lane & 3;
    const int bx = blockIdx.x, by = blockIdx.y;
    const int gra = by * 64;
    const int gnb = bx * 128;
    const int K = 1024, nk = 32;

    for (int t = 0; t < TT; t++) {
        const __half* A = (t & 1) ? h1buf : h0buf;
        __half* hnext = (t & 1) ? h0buf : h1buf;

        float acc[2][8][4];
#pragma unroll
        for (int mt = 0; mt < 2; mt++)
#pragma unroll
            for (int nt = 0; nt < 8; nt++)
#pragma unroll
                for (int q = 0; q < 4; q++) acc[mt][nt][q] = 0.f;

        if (t > 0) {
            auto load_stage = [&](int kc, int p) {
                const uint32_t sbase = sb + p * LSTAGE_B;
#pragma unroll
                for (int i = 0; i < 2; i++) {
                    const int c = tid + i * 128;
                    const int row = c >> 2, seg = c & 3;
                    cp_async16(sbase + row * GPITCH_B + seg * 16,
                               A + (size_t)(gra + row) * K + kc * 32 + seg * 8, 16);
                }
#pragma unroll
                for (int i = 0; i < 4; i++) {
                    const int c = tid + i * 128;
                    const int row = c >> 2, seg = c & 3;
                    cp_async16(sbase + LSA_OP + row * GPITCH_B + seg * 16,
                               BT + (size_t)(gnb + row) * K + kc * 32 + seg * 8, 16);
                }
            };

            load_stage(0, 0);
            cp_commit();

            for (int kc = 0; kc < nk; kc++) {
                const int p = kc & 1;
                if (kc + 1 < nk) {
                    load_stage(kc + 1, p ^ 1);
                    cp_commit();
                    asm volatile("cp.async.wait_group 1;");
                } else {
                    asm volatile("cp.async.wait_group 0;");
                }
                __syncthreads();
                const char* sA = smem + p * LSTAGE_B;
                const char* sB = sA + LSA_OP;
#pragma unroll
                for (int ks = 0; ks < 2; ks++) {
                    const int kb = ks * 32 + t4 * 4;
                    uint32_t af[2][4];
                    uint32_t bf[8][2];
#pragma unroll
                    for (int mt = 0; mt < 2; mt++) {
                        const int r = wr * 32 + mt * 16 + g4;
                        af[mt][0] = *(const uint32_t*)(sA + r * GPITCH_B + kb);
                        af[mt][1] = *(const uint32_t*)(sA + (r + 8) * GPITCH_B + kb);
                        af[mt][2] = *(const uint32_t*)(sA + r * GPITCH_B + kb + 16);
                        af[mt][3] = *(const uint32_t*)(sA + (r + 8) * GPITCH_B + kb + 16);
                    }
#pragma unroll
                    for (int nt = 0; nt < 8; nt++) {
                        const int n = wc * 64 + nt * 8 + g4;
                        bf[nt][0] = *(const uint32_t*)(sB + n * GPITCH_B + kb);
                        bf[nt][1] = *(const uint32_t*)(sB + n * GPITCH_B + kb + 16);
                    }
#pragma unroll
                    for (int mt = 0; mt < 2; mt++)
#pragma unroll
                        for (int nt = 0; nt < 8; nt++)
                            mma_f16(acc[mt][nt], af[mt][0], af[mt][1], af[mt][2], af[mt][3],
                                    bf[nt][0], bf[nt][1]);
                }
                __syncthreads();
            }
        }

#pragma unroll
        for (int mt = 0; mt < 2; mt++) {
            const int r0 = by * 64 + wr * 32 + mt * 16 + g4;
            const int r1 = r0 + 8;
            const int tok0 = ((r0 >> 8) << 12) + (t << 8) + (r0 & 255);
            const int tok1 = ((r1 >> 8) << 12) + (t << 8) + (r1 & 255);
            const int bt0 = tok0 >> 8, bt1 = tok1 >> 8;
#pragma unroll
            for (int nt = 0; nt < 8; nt++) {
                const int col = bx * 128 + wc * 64 + nt * 8 + t4 * 2;
                __half2 gx0 = *(const __half2*)(gx + (size_t)tok0 * 4096 + col);
                __half2 gx1 = *(const __half2*)(gx + (size_t)tok1 * 4096 + col);
                float v0 = acc[mt][nt][0] + __half2float(__low2half(gx0));
                float v1 = acc[mt][nt][1] + __half2float(__high2half(gx0));
                float v2 = acc[mt][nt][2] + __half2float(__low2half(gx1));
                float v3 = acc[mt][nt][3] + __half2float(__high2half(gx1));
                float p0 = __shfl_xor_sync(0xffffffffu, v0, 1);
                float p1 = __shfl_xor_sync(0xffffffffu, v1, 1);
                float p2 = __shfl_xor_sync(0xffffffffu, v2, 1);
                float p3 = __shfl_xor_sync(0xffffffffu, v3, 1);
                if (!(lane & 1)) {
                    const int j = col >> 2;
                    {
                        float cprev = (t == 0) ? 0.f : cst[r0 * 1024 + j];
                        float cc = sigm(v1) * cprev + sigm(v0) * tanh_fast(p0);
                        float hh = sigm(p1) * tanh_fast(cc);
                        cst[r0 * 1024 + j] = cc;
                        hnext[r0 * 1024 + j] = __float2half(hh);
                        float rg = rmod[bt0 * MODW + 2048 + j];
                        outp[(size_t)tok0 * 1024 + j] =
                            __half2float(xbuf[(size_t)tok0 * 1024 + j]) + rg * hh;
                    }
                    {
                        float cprev = (t == 0) ? 0.f : cst[r1 * 1024 + j];
                        float cc = sigm(v3) * cprev + sigm(v2) * tanh_fast(p2);
                        float hh = sigm(p3) * tanh_fast(cc);
                        cst[r1 * 1024 + j] = cc;
                        hnext[r1 * 1024 + j] = __float2half(hh);
                        float rg = rmod[bt1 * MODW + 2048 + j];
                        outp[(size_t)tok1 * 1024 + j] =
                            __half2float(xbuf[(size_t)tok1 * 1024 + j]) + rg * hh;
                    }
                }
            }
        }

        if (t < TT - 1) {
            __syncthreads();
            if (tid == 0) {
                __threadfence();
                atomicAdd(&g_lstm_bar, 1u);
                const unsigned int target = 256u * (unsigned int)(t + 1);
                while (atomicAdd(&g_lstm_bar, 0u) < target) {}
                __threadfence();
            }
            __syncthreads();
        }
    }
}

// ---------------- batched weight transpose: all matrices in one launch ----------------
struct TransDesc { const float* W; __half* WT; int K; int N; int perm; int tileStart; };
struct TransArgs { TransDesc d[13]; };

__global__ __launch_bounds__(256)
void transpose_all_kernel(TransArgs a) {
    __shared__ float t[32][33];
    const int bid = blockIdx.x;
    int i = 0;
#pragma unroll
    for (int k = 0; k < 12; k++) if (bid >= a.d[k + 1].tileStart) i = k + 1;
    const TransDesc& td = a.d[i];
    const int local = bid - td.tileStart;
    const int ntx = td.N / 32;
    const int n0 = (local % ntx) * 32, k0 = (local / ntx) * 32;
    const int tx = threadIdx.x & 31, ty = threadIdx.x >> 5;
#pragma unroll
    for (int j = 0; j < 4; j++)
        t[ty + j * 8][tx] = td.W[(size_t)(k0 + ty + j * 8) * td.N + n0 + tx];
    __syncthreads();
#pragma unroll
    for (int j = 0; j < 4; j++) {
        int n = n0 + ty + j * 8;
        int nd = td.perm ? (4 * (n & 1023) + (n >> 10)) : n;
        td.WT[(size_t)nd * td.K + k0 + tx] = __float2half(t[tx][ty + j * 8]);
    }
}

// -------- LayerNorm + adaLN modulate (IN32 selects fp32/fp16 x; fp16 out) --------
// Proven stride-256 scalar access pattern (4 independent loads/thread).
template<int IN32>
__global__ __launch_bounds__(256)
void ln_mod_kernel(const void* __restrict__ x, const float* __restrict__ mod,
                   int mstride, int shift_off, int scale_off, __half* __restrict__ out) {
    __shared__ float red[16];
    const int tok = blockIdx.x;
    const int tid = threadIdx.x;
    float v[4];
    float s = 0.f, s2 = 0.f;
#pragma unroll
    for (int k = 0; k < 4; k++) {
        float f;
        if (IN32) f = ((const float*)x)[(size_t)tok * DD + tid + k * 256];
        else      f = __half2float(((const __half*)x)[(size_t)tok * DD + tid + k * 256]);
        v[k] = f; s += f; s2 += f * f;
    }
#pragma unroll
    for (int o = 16; o; o >>= 1) {
        s += __shfl_xor_sync(0xffffffffu, s, o);
        s2 += __shfl_xor_sync(0xffffffffu, s2, o);
    }
    if ((tid & 31) == 0) { red[tid >> 5] = s; red[8 + (tid >> 5)] = s2; }
    __syncthreads();
    if (tid == 0) {
        float a = 0.f, b = 0.f;
        for (int i = 0; i < 8; i++) { a += red[i]; b += red[8 + i]; }
        red[0] = a; red[8] = b;
    }
    __syncthreads();
    const float mean = red[0] * (1.f / DD);
    const float var = red[8] * (1.f / DD) - mean * mean;
    const float inv = rsqrtf(var + 1e-6f);
    const int bt = tok >> 8;
    const float* m = mod + (size_t)bt * mstride;
    __half* orow = out + (size_t)tok * DD;
#pragma unroll
    for (int k = 0; k < 4; k++) {
        int d = tid + k * 256;
        float ln = (v[k] - mean) * inv;
        orow[d] = __float2half(ln * (1.f + m[scale_off + d]) + m[shift_off + d]);
    }
}

// ---------------- setup: silu + combined ada bias + permuted lstm bias + barrier reset ----
__global__ void setup_kernel(const float* __restrict__ c, __half* __restrict__ csh,
                             const float* __restrict__ sbp, const float* __restrict__ tbp,
                             const float* __restrict__ rbp, float* __restrict__ adab,
                             const float* __restrict__ lba, const float* __restrict__ lbb,
                             float* __restrict__ lbias) {
    int i = blockIdx.x * 256 + threadIdx.x;
    if (i == 0) g_lstm_bar = 0u;
    if (i < NBT * DD) {
        float v = c[i];
        csh[i] = __float2half(v / (1.f + __expf(-v)));
    }
    if (i < MODW) {
        float b;
        if (i < 6144) b = sbp[i];
        else if (i < 12288) b = tbp[i - 6144];
        else b = rbp[i - 12288];
        adab[i] = b;
    }
    if (i < 4 * DD) {
        int j = i >> 2, g = i & 3;
        lbias[i] = lba[g * 1024 + j] + lbb[g * 1024 + j];
    }
}

// ======= spatial attention via mma.sync fp16 flash (L=256, dh=64, non-causal) =======
__global__ __launch_bounds__(256, 2)
void spatial_attn_tc(const __half* __restrict__ qkv, __half* __restrict__ out) {
    __shared__ __half sQ[128 * 72];
    __shared__ __half sK[64 * 72];
    __shared__ __half sVT[64 * 72];
    const int bid = blockIdx.x;
    const int qhalf = bid & 1;
    const int head = (bid >> 1) & 15;
    const int n = bid >> 5;
    const int tid = threadIdx.x;
    const int lane = tid & 31;
    const int wid = tid >> 5;
    const int g4 = lane >> 2, t4 = lane & 3;
    const size_t rowbase = (size_t)n * 256;

#pragma unroll
    for (int i = 0; i < 4; i++) {
        int idx = tid + i * 256;
        int row = idx >> 3, seg = idx & 7;
        *(uint4*)&sQ[row * 72 + seg * 8] =
            *(const uint4*)(qkv + (rowbase + qhalf * 128 + row) * 3072 + head * 64 + seg * 8);
    }
    __syncthreads();

    uint32_t af[4][4];
    {
        const int r = wid * 16 + g4;
#pragma unroll
        for (int ks = 0; ks < 4; ks++) {
            af[ks][0] = *(const uint32_t*)&sQ[r * 72 + ks * 16 + t4 * 2];
            af[ks][1] = *(const uint32_t*)&sQ[(r + 8) * 72 + ks * 16 + t4 * 2];
            af[ks][2] = *(const uint32_t*)&sQ[r * 72 + ks * 16 + 8 + t4 * 2];
            af[ks][3] = *(const uint32_t*)&sQ[(r + 8) * 72 + ks * 16 + 8 + t4 * 2];
        }
    }

    float O[8][4];
#pragma unroll
    for (int i = 0; i < 8; i++)
#pragma unroll
        for (int q = 0; q < 4; q++) O[i][q] = 0.f;
    float m0 = -1e30f, m1 = -1e30f, l0 = 0.f, l1 = 0.f;

    for (int kt = 0; kt < 4; kt++) {
#pragma unroll
        for (int i = 0; i < 2; i++) {
            int idx = tid + i * 256;
            int row = idx >> 3, seg = idx & 7;
            const __half* src = qkv + (rowbase + kt * 64 + row) * 3072 + 1024 + head * 64 + seg * 8;
            *(uint4*)&sK[row * 72 + seg * 8] = *(const uint4*)src;
            __half vv[8];
            *(uint4*)vv = *(const uint4*)(src + 1024);
#pragma unroll
            for (int jj = 0; jj < 8; jj++) sVT[(seg * 8 + jj) * 72 + row] = vv[jj];
        }
        __syncthreads();

        float sc[8][4];
#pragma unroll
        for (int nt = 0; nt < 8; nt++) {
#pragma unroll
            for (int q = 0; q < 4; q++) sc[nt][q] = 0.f;
#pragma unroll
            for (int ks = 0; ks < 4; ks++) {
                uint32_t b0 = *(const uint32_t*)&sK[(nt * 8 + g4) * 72 + ks * 16 + t4 * 2];
                uint32_t b1 = *(const uint32_t*)&sK[(nt * 8 + g4) * 72 + ks * 16 + 8 + t4 * 2];
                mma_f16(sc[nt], af[ks][0], af[ks][1], af[ks][2], af[ks][3], b0, b1);
            }
        }

        float mx0 = -1e30f, mx1 = -1e30f;
#pragma unroll
        for (int nt = 0; nt < 8; nt++) {
            sc[nt][0] *= 0.125f; sc[nt][1] *= 0.125f;
            sc[nt][2] *= 0.125f; sc[nt][3] *= 0.125f;
            mx0 = fmaxf(mx0, fmaxf(sc[nt][0], sc[nt][1]));
            mx1 = fmaxf(mx1, fmaxf(sc[nt][2], sc[nt][3]));
        }
        mx0 = fmaxf(mx0, __shfl_xor_sync(0xffffffffu, mx0, 1));
        mx0 = fmaxf(mx0, __shfl_xor_sync(0xffffffffu, mx0, 2));
        mx1 = fmaxf(mx1, __shfl_xor_sync(0xffffffffu, mx1, 1));
        mx1 = fmaxf(mx1, __shfl_xor_sync(0xffffffffu, mx1, 2));
        const float mn0 = fmaxf(m0, mx0), mn1 = fmaxf(m1, mx1);
        const float al0 = __expf(m0 - mn0), al1 = __expf(m1 - mn1);
        m0 = mn0; m1 = mn1;

        float sum0 = 0.f, sum1 = 0.f;
        uint32_t aP[8][2];
#pragma unroll
        for (int nt = 0; nt < 8; nt++) {
            float p0 = __expf(sc[nt][0] - mn0);
            float p1 = __expf(sc[nt][1] - mn0);
            float p2 = __expf(sc[nt][2] - mn1);
            float p3 = __expf(sc[nt][3] - mn1);
            sum0 += p0 + p1; sum1 += p2 + p3;
            aP[nt][0] = h2_as_u32(__floats2half2_rn(p0, p1));
            aP[nt][1] = h2_as_u32(__floats2half2_rn(p2, p3));
        }
        sum0 += __shfl_xor_sync(0xffffffffu, sum0, 1);
        sum0 += __shfl_xor_sync(0xffffffffu, sum0, 2);
        sum1 += __shfl_xor_sync(0xffffffffu, sum1, 1);
        sum1 += __shfl_xor_sync(0xffffffffu, sum1, 2);
        l0 = l0 * al0 + sum0;
        l1 = l1 * al1 + sum1;
#pragma unroll
        for (int nt2 = 0; nt2 < 8; nt2++) {
            O[nt2][0] *= al0; O[nt2][1] *= al0;
            O[nt2][2] *= al1; O[nt2][3] *= al1;
        }

#pragma unroll
        for (int ks2 = 0; ks2 < 4; ks2++) {
            const uint32_t a0 = aP[2 * ks2][0], a1 = aP[2 * ks2][1];
            const uint32_t a2 = aP[2 * ks2 + 1][0], a3 = aP[2 * ks2 + 1][1];
#pragma unroll
            for (int nt2 = 0; nt2 < 8; nt2++) {
                uint32_t b0 = *(const uint32_t*)&sVT[(nt2 * 8 + g4) * 72 + ks2 * 16 + t4 * 2];
                uint32_t b1 = *(const uint32_t*)&sVT[(nt2 * 8 + g4) * 72 + ks2 * 16 + 8 + t4 * 2];
                mma_f16(O[nt2], a0, a1, a2, a3, b0, b1);
            }
        }
        __syncthreads();
    }

    const float inv0 = 1.f / l0, inv1 = 1.f / l1;
    const int q0 = qhalf * 128 + wid * 16 + g4;
#pragma unroll
    for (int nt2 = 0; nt2 < 8; nt2++) {
        const int col = head * 64 + nt2 * 8 + t4 * 2;
        *(__half2*)(out + (rowbase + q0) * 1024 + col) =
            __floats2half2_rn(O[nt2][0] * inv0, O[nt2][1] * inv0);
        *(__half2*)(out + (rowbase + q0 + 8) * 1024 + col) =
            __floats2half2_rn(O[nt2][2] * inv1, O[nt2][3] * inv1);
    }
}

// ---------------- temporal attention (T=16, dh=64, causal; fp16 qkv in/out) ----------------
__global__ __launch_bounds__(128)
void temporal_attn_kernel(const __half* __restrict__ qkv, __half* __restrict__ out) {
    __shared__ float Q[16][65], K[16][65], V[16][65], S[16][17];
    const int bid = blockIdx.x;
    const int head = bid & 15;
    const int n = bid >> 4;
    const int b = n >> 8;
    const int hw = n & 255;
    const int tid = threadIdx.x;
    const size_t tokbase = (size_t)b * 4096 + hw;

    for (int i = tid; i < 16 * 64; i += 128) {
        int t = i >> 6, d = i & 63;
        size_t base = (tokbase + (size_t)t * 256) * 3072 + head * 64 + d;
        Q[t][d] = __half2float(qkv[base]);
        K[t][d] = __half2float(qkv[base + 1024]);
        V[t][d] = __half2float(qkv[base + 2048]);
    }
    __syncthreads();

    for (int idx = tid; idx < 256; idx += 128) {
        int qi = idx >> 4, kj = idx & 15;
        float s;
        if (kj <= qi) {
            float acc = 0.f;
#pragma unroll
            for (int d = 0; d < 64; d++) acc += Q[qi][d] * K[kj][d];
            s = acc * 0.125f;
        } else s = -1e30f;
        S[qi][kj] = s;
    }
    __syncthreads();

    {
        const int row = tid >> 3, c0 = tid & 7;
        float mx = fmaxf(S[row][c0], S[row][c0 + 8]);
#pragma unroll
        for (int o = 4; o; o >>= 1) mx = fmaxf(mx, __shfl_xor_sync(0xffffffffu, mx, o));
        float e0 = __expf(S[row][c0] - mx), e1 = __expf(S[row][c0 + 8] - mx);
        float sum = e0 + e1;
#pragma unroll
        for (int o = 4; o; o >>= 1) sum += __shfl_xor_sync(0xffffffffu, sum, o);
        float inv = 1.f / sum;
        S[row][c0] = e0 * inv;
        S[row][c0 + 8] = e1 * inv;
    }
    __syncthreads();

    for (int i = tid; i < 16 * 64; i += 128) {
        int qi = i >> 6, d = i & 63;
        float acc = 0.f;
#pragma unroll
        for (int k = 0; k < 16; k++) acc = fmaf(S[qi][k], V[k][d], acc);
        out[(tokbase + (size_t)qi * 256) * 1024 + head * 64 + d] = __float2half(acc);
    }
}

// ---------------- launch helpers ----------------
static void gemm(const __half* A, const __half* BT, const float* bias, void* C,
                 int M, int N, int K, int epi, int outh) {
    dim3 g(N / 128, (M + 127) / 128);
    if (epi == 1)      gemm_tc<1, 1, 0><<<g, 128, GTC_SMEM_TOTAL>>>(A, BT, bias, C, M, N, K,
                                                                    nullptr, nullptr, 0);
    else if (outh)     gemm_tc<0, 1, 0><<<g, 128, GTC_SMEM_TOTAL>>>(A, BT, bias, C, M, N, K,
                                                                    nullptr, nullptr, 0);
    else               gemm_tc<0, 0, 0><<<g, 128, GTC_SMEM_TOTAL>>>(A, BT, bias, C, M, N, K,
                                                                    nullptr, nullptr, 0);
}
// gated-residual epilogue GEMM: xout = xres + gate*(A@BT^T + bias)
template<int XR32>
static void gemm_ga(const __half* A, const __half* BT, const float* bias, __half* Xout,
                    int M, int N, int K, const void* Xres, const float* modall, int goff) {
    dim3 g(N / 128, (M + 127) / 128);
    gemm_tc<2, 1, XR32><<<g, 128, GTC_SMEM_TOTAL>>>(A, BT, bias, Xout, M, N, K,
                                                    Xres, modall, goff);
}

extern "C" void kernel_launch(void* const* d_in, const int* in_sizes, int n_in,
                              void* d_out, int out_size) {
    const float* x        = (const float*)d_in[0];
    const float* c        = (const float*)d_in[1];
    const float* s_ada_w  = (const float*)d_in[2];
    const float* s_ada_b  = (const float*)d_in[3];
    const float* t_ada_w  = (const float*)d_in[4];
    const float* t_ada_b  = (const float*)d_in[5];
    const float* r_ada_w  = (const float*)d_in[6];
    const float* r_ada_b  = (const float*)d_in[7];
    const float* s_qkv_w  = (const float*)d_in[8];
    const float* s_out_w  = (const float*)d_in[9];
    const float* s_out_b  = (const float*)d_in[10];
    const float* t_qkv_w  = (const float*)d_in[11];
    const float* t_out_w  = (const float*)d_in[12];
    const float* t_out_b  = (const float*)d_in[13];
    const float* s_mlp_w1 = (const float*)d_in[14];
    const float* s_mlp_b1 = (const float*)d_in[15];
    const float* s_mlp_w2 = (const float*)d_in[16];
    const float* s_mlp_b2 = (const float*)d_in[17];
    const float* t_mlp_w1 = (const float*)d_in[18];
    const float* t_mlp_b1 = (const float*)d_in[19];
    const float* t_mlp_w2 = (const float*)d_in[20];
    const float* t_mlp_b2 = (const float*)d_in[21];
    const float* lstm_w_ih = (const float*)d_in[22];
    const float* lstm_w_hh = (const float*)d_in[23];
    const float* lstm_b_ih = (const float*)d_in[24];
    const float* lstm_b_hh = (const float*)d_in[25];
    float* out = (float*)d_out;

    cudaFuncSetAttribute(gemm_tc<0, 0, 0>, cudaFuncAttributeMaxDynamicSharedMemorySize, GTC_SMEM_TOTAL);
    cudaFuncSetAttribute(gemm_tc<0, 1, 0>, cudaFuncAttributeMaxDynamicSharedMemorySize, GTC_SMEM_TOTAL);
    cudaFuncSetAttribute(gemm_tc<1, 1, 0>, cudaFuncAttributeMaxDynamicSharedMemorySize, GTC_SMEM_TOTAL);
    cudaFuncSetAttribute(gemm_tc<2, 1, 0>, cudaFuncAttributeMaxDynamicSharedMemorySize, GTC_SMEM_TOTAL);
    cudaFuncSetAttribute(gemm_tc<2, 1, 1>, cudaFuncAttributeMaxDynamicSharedMemorySize, GTC_SMEM_TOTAL);
    cudaFuncSetAttribute(lstm_persist_tc, cudaFuncAttributeMaxDynamicSharedMemorySize, LSTM_SMEM_TOTAL);

    __half *csh, *h1h, *qkvh, *mlph, *gatesxh, *hstateh, *hstate2h, *wTh, *xbufh;
    float *modall, *adab, *cstate, *lstmbias;
    cudaGetSymbolAddress((void**)&csh, g_csh);
    cudaGetSymbolAddress((void**)&modall, g_modall);
    cudaGetSymbolAddress((void**)&adab, g_adab);
    cudaGetSymbolAddress((void**)&xbufh, g_xbufh);
    cudaGetSymbolAddress((void**)&h1h, g_h1h);
    cudaGetSymbolAddress((void**)&qkvh, g_qkvh);
    cudaGetSymbolAddress((void**)&mlph, g_mlph);
    cudaGetSymbolAddress((void**)&gatesxh, g_gatesxh);
    cudaGetSymbolAddress((void**)&hstateh, g_hstateh);
    cudaGetSymbolAddress((void**)&hstate2h, g_hstate2h);
    cudaGetSymbolAddress((void**)&cstate, g_cstate);
    cudaGetSymbolAddress((void**)&lstmbias, g_lstmbias);
    cudaGetSymbolAddress((void**)&wTh, g_wTh);

    float* rmod = modall + 12288;      // stride MODW

    const size_t MEG = 1048576;
    __half* wt_ada   = wTh + 0 * MEG;   // [15360,1024]: sada|tada|rada contiguous
    __half* wt_sqkv  = wTh + 15 * MEG;
    __half* wt_sout  = wTh + 18 * MEG;
    __half* wt_tqkv  = wTh + 19 * MEG;
    __half* wt_tout  = wTh + 22 * MEG;
    __half* wt_smlp1 = wTh + 23 * MEG;
    __half* wt_smlp2 = wTh + 27 * MEG;
    __half* wt_tmlp1 = wTh + 31 * MEG;
    __half* wt_tmlp2 = wTh + 35 * MEG;
    __half* wt_lih   = wTh + 39 * MEG;  // gate-interleaved [4096,1024]
    __half* wt_lhh   = wTh + 43 * MEG;  // gate-interleaved [4096,1024]

    // batched transpose: all 13 matrices, one launch
    {
        TransArgs ta;
        auto set = [&](int i, const float* W, __half* WT, int K, int N, int perm, int start) {
            ta.d[i].W = W; ta.d[i].WT = WT; ta.d[i].K = K; ta.d[i].N = N;
            ta.d[i].perm = perm; ta.d[i].tileStart = start;
        };
        int s = 0;
        set(0,  s_ada_w,  wt_ada,            1024, 6144, 0, s); s += (6144 / 32) * 32;
        set(1,  t_ada_w,  wt_ada + 6 * MEG,  1024, 6144, 0, s); s += (6144 / 32) * 32;
        set(2,  r_ada_w,  wt_ada + 12 * MEG, 1024, 3072, 0, s); s += (3072 / 32) * 32;
        set(3,  s_qkv_w,  wt_sqkv,  1024, 3072, 0, s); s += (3072 / 32) * 32;
        set(4,  s_out_w,  wt_sout,  1024, 1024, 0, s); s += (1024 / 32) * 32;
        set(5,  t_qkv_w,  wt_tqkv,  1024, 3072, 0, s); s += (3072 / 32) * 32;
        set(6,  t_out_w,  wt_tout,  1024, 1024, 0, s); s += (1024 / 32) * 32;
        set(7,  s_mlp_w1, wt_smlp1, 1024, 4096, 0, s); s += (4096 / 32) * 32;
        set(8,  s_mlp_w2, wt_smlp2, 4096, 1024, 0, s); s += (1024 / 32) * 128;
        set(9,  t_mlp_w1, wt_tmlp1, 1024, 4096, 0, s); s += (4096 / 32) * 32;
        set(10, t_mlp_w2, wt_tmlp2, 4096, 1024, 0, s); s += (1024 / 32) * 128;
        set(11, lstm_w_ih, wt_lih,  1024, 4096, 1, s); s += (4096 / 32) * 32;
        set(12, lstm_w_hh, wt_lhh,  1024, 4096, 1, s); s += (4096 / 32) * 32;
        transpose_all_kernel<<<s, 256>>>(ta);
    }

    // setup (silu + ada bias concat + lstm bias permute + barrier reset)
    setup_kernel<<<(NBT * DD + 255) / 256, 256>>>(c, csh, s_ada_b, t_ada_b, r_ada_b, adab,
                                                  lstm_b_ih, lstm_b_hh, lstmbias);
    gemm(csh, wt_ada, adab, modall, NBT, MODW, DD, 0, 0);

    // absolute offsets into a modall row:
    //   spatial:  shift_msa 0, scale_msa 1024, gate_msa 2048, shift_mlp 3072,
    //             scale_mlp 4096, gate_mlp 5120
    //   temporal: +6144;  recurrent: +12288

    // ---- spatial attention ----
    ln_mod_kernel<1><<<NTOK, 256>>>(x, modall, MODW, 0, 1024, h1h);
    gemm(h1h, wt_sqkv, nullptr, qkvh, NTOK, 3 * DD, DD, 0, 1);
    spatial_attn_tc<<<1024, 256>>>(qkvh, h1h);
    gemm_ga<1>(h1h, wt_sout, s_out_b, xbufh, NTOK, DD, DD, x, modall, 2048);
    ln_mod_kernel<0><<<NTOK, 256>>>(xbufh, modall, MODW, 3072, 4096, h1h);

    // ---- spatial MLP ----
    gemm(h1h, wt_smlp1, s_mlp_b1, mlph, NTOK, 4 * DD, DD, 1, 1);
    gemm_ga<0>(mlph, wt_smlp2, s_mlp_b2, xbufh, NTOK, DD, 4 * DD, xbufh, modall, 5120);
    ln_mod_kernel<0><<<NTOK, 256>>>(xbufh, modall, MODW, 6144, 7168, h1h);

    // ---- temporal attention (causal) ----
    gemm(h1h, wt_tqkv, nullptr, qkvh, NTOK, 3 * DD, DD, 0, 1);
    temporal_attn_kernel<<<8192, 128>>>(qkvh, h1h);
    gemm_ga<0>(h1h, wt_tout, t_out_b, xbufh, NTOK, DD, DD, xbufh, modall, 8192);
    ln_mod_kernel<0><<<NTOK, 256>>>(xbufh, modall, MODW, 9216, 10240, h1h);

    // ---- temporal MLP ----
    gemm(h1h, wt_tmlp1, t_mlp_b1, mlph, NTOK, 4 * DD, DD, 1, 1);
    gemm_ga<0>(mlph, wt_tmlp2, t_mlp_b2, xbufh, NTOK, DD, 4 * DD, xbufh, modall, 11264);
    ln_mod_kernel<0><<<NTOK, 256>>>(xbufh, modall, MODW, 12288, 13312, h1h);

    // ---- LSTM branch: persistent kernel, all 16 steps ----
    gemm(h1h, wt_lih, lstmbias, gatesxh, NTOK, 4 * DD, DD, 0, 1);
    lstm_persist_tc<<<dim3(32, 8), 128, LSTM_SMEM_TOTAL>>>(
        hstateh, hstate2h, wt_lhh, gatesxh, cstate, xbufh, rmod, out);
}

// round 16
// speedup vs baseline: 1.5683x; 1.0107x over previous
#include <cuda_runtime.h>
#include <cuda_fp16.h>
#include <math.h>
#include <cstdint>

// Problem constants
#define DD   1024
#define NTOK 8192      // B*T*H*W
#define NBT  32        // B*T
#define NSEQ 512       // B*H*W
#define TT   16
#define MODW 15360     // 6*DD + 6*DD + 3*DD combined ada width

// ---------------- scratch (device globals; no allocations allowed) ----------------
__device__ __half g_csh[NBT * DD];
__device__ float  g_modall[NBT * MODW];
__device__ float  g_adab[MODW];
__device__ __half g_xbufh[NTOK * DD];
__device__ __half g_h1h[NTOK * DD];
__device__ __half g_qkvh[NTOK * 3 * DD];
__device__ __half g_mlph[NTOK * 4 * DD];
__device__ __half g_gatesxh[NTOK * 4 * DD];
__device__ __half g_hstateh[NSEQ * DD];
__device__ __half g_hstate2h[NSEQ * DD];
__device__ float  g_cstate[NSEQ * DD];
__device__ float  g_lstmbias[4 * DD];
__device__ unsigned int g_lstm_bar;
__device__ __half g_wTh[47u * 1048576u];   // transposed fp16 weights

__device__ __forceinline__ float tanh_fast(float x) {
    float r; asm("tanh.approx.f32 %0, %1;" : "=f"(r) : "f"(x)); return r;
}
__device__ __forceinline__ float gelu_tanh(float x) {
    return 0.5f * x * (1.f + tanh_fast(0.7978845608028654f * (x + 0.044715f * x * x * x)));
}
__device__ __forceinline__ float sigm(float x) { return 0.5f * (1.f + tanh_fast(0.5f * x)); }
__device__ __forceinline__ uint32_t h2_as_u32(__half2 h) {
    uint32_t u; *reinterpret_cast<__half2*>(&u) = h; return u;
}
__device__ __forceinline__ void mma_f16(float d[4], uint32_t a0, uint32_t a1, uint32_t a2,
                                        uint32_t a3, uint32_t b0, uint32_t b1) {
    asm volatile(
        "mma.sync.aligned.m16n8k16.row.col.f32.f16.f16.f32 "
        "{%0,%1,%2,%3}, {%4,%5,%6,%7}, {%8,%9}, {%0,%1,%2,%3};\n"
        : "+f"(d[0]), "+f"(d[1]), "+f"(d[2]), "+f"(d[3])
        : "r"(a0), "r"(a1), "r"(a2), "r"(a3), "r"(b0), "r"(b1));
}
__device__ __forceinline__ void cp_async16(uint32_t dst, const void* src, int szvalid) {
    asm volatile("cp.async.cg.shared.global [%0], [%1], 16, %2;"
                 :: "r"(dst), "l"(src), "r"(szvalid));
}
__device__ __forceinline__ void cp_commit() { asm volatile("cp.async.commit_group;"); }

// ================== fp16 tensor-core GEMM: C[M,N] = A[M,K] @ BT[N,K]^T ==================
// 128 threads = 4 warps (2x2), warp tile 64x64, block tile 128x128x32, 4-stage cp.async.
// EPI: 0 = +bias, 1 = gelu(tanh)(x+bias), 2 = gated residual add (xout = xres + gate*(v+bias))
// OUTH: 0 = fp32 C, 1 = fp16 C. XR32 (EPI==2 only): xres is fp32 (else fp16).
#define GPITCH_B   80
#define GOP_BYTES  (128 * GPITCH_B)
#define GSTAGE_B   (2 * GOP_BYTES)       // 20480 per stage
#define GTC_NSTAGE 4
#define GTC_SMEM_TOTAL (GTC_NSTAGE * GSTAGE_B)   // 81920 bytes

template<int EPI, int OUTH, int XR32>
__global__ __launch_bounds__(128, 2)
void gemm_tc(const __half* __restrict__ A, const __half* __restrict__ BT,
             const float* __restrict__ bias, void* __restrict__ Cout,
             int M, int N, int K,
             const void* __restrict__ Xres, const float* __restrict__ modall, int goff) {
    extern __shared__ char smem[];
    const uint32_t sb = (uint32_t)__cvta_generic_to_shared(smem);
    const int tid = threadIdx.x;
    const int lane = tid & 31;
    const int wid = tid >> 5;
    const int wr = wid >> 1;
    const int wc = wid & 1;
    const int g4 = lane >> 2, t4 = lane & 3;
    const int bx = blockIdx.x, by = blockIdx.y;
    const int gra = by * 128;
    const int gnb = bx * 128;

    float acc[4][8][4];
#pragma unroll
    for (int mt = 0; mt < 4; mt++)
#pragma unroll
        for (int nt = 0; nt < 8; nt++)
#pragma unroll
            for (int q = 0; q < 4; q++) acc[mt][nt][q] = 0.f;

    const int nk = K >> 5;

    auto load_stage = [&](int kc, int s) {
        const uint32_t sbase = sb + s * GSTAGE_B;
#pragma unroll
        for (int i = 0; i < 4; i++) {
            const int c = tid + i * 128;
            const int row = c >> 2, seg = c & 3;
            const int ga = gra + row;
            const bool ok = ga < M;
            cp_async16(sbase + row * GPITCH_B + seg * 16,
                       A + (size_t)(ok ? ga : 0) * K + kc * 32 + seg * 8, ok ? 16 : 0);
            cp_async16(sbase + GOP_BYTES + row * GPITCH_B + seg * 16,
                       BT + (size_t)(gnb + row) * K + kc * 32 + seg * 8, 16);
        }
    };

    load_stage(0, 0); cp_commit();
    load_stage(1, 1); cp_commit();
    load_stage(2, 2); cp_commit();

    for (int kc = 0; kc < nk; kc++) {
        if (kc < nk - 2)       asm volatile("cp.async.wait_group 2;");
        else if (kc == nk - 2) asm volatile("cp.async.wait_group 1;");
        else                   asm volatile("cp.async.wait_group 0;");
        __syncthreads();
        if (kc + 3 < nk) { load_stage(kc + 3, (kc + 3) & (GTC_NSTAGE - 1)); cp_commit(); }

        const char* sA = smem + (kc & (GTC_NSTAGE - 1)) * GSTAGE_B;
        const char* sB = sA + GOP_BYTES;
#pragma unroll
        for (int ks = 0; ks < 2; ks++) {
            const int kb = ks * 32 + t4 * 4;
            uint32_t af[4][4];
            uint32_t bf[8][2];
#pragma unroll
            for (int mt = 0; mt < 4; mt++) {
                const int r = wr * 64 + mt * 16 + g4;
                af[mt][0] = *(const uint32_t*)(sA + r * GPITCH_B + kb);
                af[mt][1] = *(const uint32_t*)(sA + (r + 8) * GPITCH_B + kb);
                af[mt][2] = *(const uint32_t*)(sA + r * GPITCH_B + kb + 16);
                af[mt][3] = *(const uint32_t*)(sA + (r + 8) * GPITCH_B + kb + 16);
            }
#pragma unroll
            for (int nt = 0; nt < 8; nt++) {
                const int n = wc * 64 + nt * 8 + g4;
                bf[nt][0] = *(const uint32_t*)(sB + n * GPITCH_B + kb);
                bf[nt][1] = *(const uint32_t*)(sB + n * GPITCH_B + kb + 16);
            }
#pragma unroll
            for (int mt = 0; mt < 4; mt++)
#pragma unroll
                for (int nt = 0; nt < 8; nt++)
                    mma_f16(acc[mt][nt], af[mt][0], af[mt][1], af[mt][2], af[mt][3],
                            bf[nt][0], bf[nt][1]);
        }
    }

    // gate row pointer (EPI==2): 128-row tile is bt-aligned (256 rows/bt) => bt = by>>1
    const float* gp = (EPI == 2) ? (modall + (size_t)(by >> 1) * MODW + goff) : nullptr;

#pragma unroll
    for (int mt = 0; mt < 4; mt++) {
        const int r0 = by * 128 + wr * 64 + mt * 16 + g4;
#pragma unroll
        for (int nt = 0; nt < 8; nt++) {
            const int col = bx * 128 + wc * 64 + nt * 8 + t4 * 2;
            float b0 = 0.f, b1 = 0.f;
            if (bias) { b0 = __ldg(bias + col); b1 = __ldg(bias + col + 1); }
            float v0 = acc[mt][nt][0] + b0;
            float v1 = acc[mt][nt][1] + b1;
            float v2 = acc[mt][nt][2] + b0;
            float v3 = acc[mt][nt][3] + b1;
            if (EPI == 1) {
                v0 = gelu_tanh(v0); v1 = gelu_tanh(v1);
                v2 = gelu_tanh(v2); v3 = gelu_tanh(v3);
            }
            if (EPI == 2) {
                const float gg0 = __ldg(gp + col);
                const float gg1 = __ldg(gp + col + 1);
                float x0, x1, x2, x3;
                if (XR32) {
                    float2 a = *(const float2*)((const float*)Xres + (size_t)r0 * N + col);
                    float2 b = *(const float2*)((const float*)Xres + (size_t)(r0 + 8) * N + col);
                    x0 = a.x; x1 = a.y; x2 = b.x; x3 = b.y;
                } else {
                    __half2 a = *(const __half2*)((const __half*)Xres + (size_t)r0 * N + col);
                    __half2 b = *(const __half2*)((const __half*)Xres + (size_t)(r0 + 8) * N + col);
                    x0 = __half2float(__low2half(a)); x1 = __half2float(__high2half(a));
                    x2 = __half2float(__low2half(b)); x3 = __half2float(__high2half(b));
                }
                v0 = x0 + gg0 * v0; v1 = x1 + gg1 * v1;
                v2 = x2 + gg0 * v2; v3 = x3 + gg1 * v3;
                __half* Ch = (__half*)Cout;
                *(__half2*)(Ch + (size_t)r0 * N + col) = __floats2half2_rn(v0, v1);
                *(__half2*)(Ch + (size_t)(r0 + 8) * N + col) = __floats2half2_rn(v2, v3);
            } else if (OUTH) {
                __half* Ch = (__half*)Cout;
                if (r0 < M) *(__half2*)(Ch + (size_t)r0 * N + col) = __floats2half2_rn(v0, v1);
                if (r0 + 8 < M) *(__half2*)(Ch + (size_t)(r0 + 8) * N + col) = __floats2half2_rn(v2, v3);
            } else {
                float* Cf = (float*)Cout;
                if (r0 < M) *(float2*)(Cf + (size_t)r0 * N + col) = make_float2(v0, v1);
                if (r0 + 8 < M) *(float2*)(Cf + (size_t)(r0 + 8) * N + col) = make_float2(v2, v3);
            }
        }
    }
}

// ============ persistent fused LSTM: all 16 steps in one launch, 4-stage pipeline ============
#define LSA_OP   (64 * GPITCH_B)
#define LSB_OP   (128 * GPITCH_B)
#define LSTAGE_B (LSA_OP + LSB_OP)      // 15360
#define LSTM_NSTAGE 4
#define LSTM_SMEM_TOTAL (LSTM_NSTAGE * LSTAGE_B)   // 61440

__global__ __launch_bounds__(128, 2)
void lstm_persist_tc(__half* __restrict__ h0buf, __half* __restrict__ h1buf,
                     const __half* __restrict__ BT, const __half* __restrict__ gx,
                     float* __restrict__ cst, const __half* __restrict__ xbuf,
                     const float* __restrict__ rmod, float* __restrict__ outp) {
    extern __shared__ char smem[];
    const uint32_t sb = (uint32_t)__cvta_generic_to_shared(smem);
    const int tid = threadIdx.x;
    const int lane = tid & 31;
    const int wid = tid >> 5;
    const int wr = wid >> 1;
    const int wc = wid & 1;
    const int g4 = lane >> 2, t4 = lane & 3;
    const int bx = blockIdx.x, by = blockIdx.y;
    const int gra = by * 64;
    const int gnb = bx * 128;
    const int K = 1024, nk = 32;

    for (int t = 0; t < TT; t++) {
        const __half* A = (t & 1) ? h1buf : h0buf;
        __half* hnext = (t & 1) ? h0buf : h1buf;

        float acc[2][8][4];
#pragma unroll
        for (int mt = 0; mt < 2; mt++)
#pragma unroll
            for (int nt = 0; nt < 8; nt++)
#pragma unroll
                for (int q = 0; q < 4; q++) acc[mt][nt][q] = 0.f;

        if (t > 0) {
            auto load_stage = [&](int kc, int s) {
                const uint32_t sbase = sb + s * LSTAGE_B;
#pragma unroll
                for (int i = 0; i < 2; i++) {
                    const int c = tid + i * 128;
                    const int row = c >> 2, seg = c & 3;
                    cp_async16(sbase + row * GPITCH_B + seg * 16,
                               A + (size_t)(gra + row) * K + kc * 32 + seg * 8, 16);
                }
#pragma unroll
                for (int i = 0; i < 4; i++) {
                    const int c = tid + i * 128;
                    const int row = c >> 2, seg = c & 3;
                    cp_async16(sbase + LSA_OP + row * GPITCH_B + seg * 16,
                               BT + (size_t)(gnb + row) * K + kc * 32 + seg * 8, 16);
                }
            };

            load_stage(0, 0); cp_commit();
            load_stage(1, 1); cp_commit();
            load_stage(2, 2); cp_commit();

            for (int kc = 0; kc < nk; kc++) {
                if (kc < nk - 2)       asm volatile("cp.async.wait_group 2;");
                else if (kc == nk - 2) asm volatile("cp.async.wait_group 1;");
                else                   asm volatile("cp.async.wait_group 0;");
                __syncthreads();
                if (kc + 3 < nk) { load_stage(kc + 3, (kc + 3) & (LSTM_NSTAGE - 1)); cp_commit(); }

                const char* sA = smem + (kc & (LSTM_NSTAGE - 1)) * LSTAGE_B;
                const char* sB = sA + LSA_OP;
#pragma unroll
                for (int ks = 0; ks < 2; ks++) {
                    const int kb = ks * 32 + t4 * 4;
                    uint32_t af[2][4];
                    uint32_t bf[8][2];
#pragma unroll
                    for (int mt = 0; mt < 2; mt++) {
                        const int r = wr * 32 + mt * 16 + g4;
                        af[mt][0] = *(const uint32_t*)(sA + r * GPITCH_B + kb);
                        af[mt][1] = *(const uint32_t*)(sA + (r + 8) * GPITCH_B + kb);
                        af[mt][2] = *(const uint32_t*)(sA + r * GPITCH_B + kb + 16);
                        af[mt][3] = *(const uint32_t*)(sA + (r + 8) * GPITCH_B + kb + 16);
                    }
#pragma unroll
                    for (int nt = 0; nt < 8; nt++) {
                        const int n = wc * 64 + nt * 8 + g4;
                        bf[nt][0] = *(const uint32_t*)(sB + n * GPITCH_B + kb);
                        bf[nt][1] = *(const uint32_t*)(sB + n * GPITCH_B + kb + 16);
                    }
#pragma unroll
                    for (int mt = 0; mt < 2; mt++)
#pragma unroll
                        for (int nt = 0; nt < 8; nt++)
                            mma_f16(acc[mt][nt], af[mt][0], af[mt][1], af[mt][2], af[mt][3],
                                    bf[nt][0], bf[nt][1]);
                }
            }
        }

#pragma unroll
        for (int mt = 0; mt < 2; mt++) {
            const int r0 = by * 64 + wr * 32 + mt * 16 + g4;
            const int r1 = r0 + 8;
            const int tok0 = ((r0 >> 8) << 12) + (t << 8) + (r0 & 255);
            const int tok1 = ((r1 >> 8) << 12) + (t << 8) + (r1 & 255);
            const int bt0 = tok0 >> 8, bt1 = tok1 >> 8;
#pragma unroll
            for (int nt = 0; nt < 8; nt++) {
                const int col = bx * 128 + wc * 64 + nt * 8 + t4 * 2;
                __half2 gx0 = *(const __half2*)(gx + (size_t)tok0 * 4096 + col);
                __half2 gx1 = *(const __half2*)(gx + (size_t)tok1 * 4096 + col);
                float v0 = acc[mt][nt][0] + __half2float(__low2half(gx0));
                float v1 = acc[mt][nt][1] + __half2float(__high2half(gx0));
                float v2 = acc[mt][nt][2] + __half2float(__low2half(gx1));
                float v3 = acc[mt][nt][3] + __half2float(__high2half(gx1));
                float p0 = __shfl_xor_sync(0xffffffffu, v0, 1);
                float p1 = __shfl_xor_sync(0xffffffffu, v1, 1);
                float p2 = __shfl_xor_sync(0xffffffffu, v2, 1);
                float p3 = __shfl_xor_sync(0xffffffffu, v3, 1);
                if (!(lane & 1)) {
                    const int j = col >> 2;
                    {
                        float cprev = (t == 0) ? 0.f : cst[r0 * 1024 + j];
                        float cc = sigm(v1) * cprev + sigm(v0) * tanh_fast(p0);
                        float hh = sigm(p1) * tanh_fast(cc);
                        cst[r0 * 1024 + j] = cc;
                        hnext[r0 * 1024 + j] = __float2half(hh);
                        float rg = rmod[bt0 * MODW + 2048 + j];
                        outp[(size_t)tok0 * 1024 + j] =
                            __half2float(xbuf[(size_t)tok0 * 1024 + j]) + rg * hh;
                    }
                    {
                        float cprev = (t == 0) ? 0.f : cst[r1 * 1024 + j];
                        float cc = sigm(v3) * cprev + sigm(v2) * tanh_fast(p2);
                        float hh = sigm(p3) * tanh_fast(cc);
                        cst[r1 * 1024 + j] = cc;
                        hnext[r1 * 1024 + j] = __float2half(hh);
                        float rg = rmod[bt1 * MODW + 2048 + j];
                        outp[(size_t)tok1 * 1024 + j] =
                            __half2float(xbuf[(size_t)tok1 * 1024 + j]) + rg * hh;
                    }
                }
            }
        }

        if (t < TT - 1) {
            __syncthreads();
            if (tid == 0) {
                __threadfence();
                atomicAdd(&g_lstm_bar, 1u);
                const unsigned int target = 256u * (unsigned int)(t + 1);
                while (atomicAdd(&g_lstm_bar, 0u) < target) {}
                __threadfence();
            }
            __syncthreads();
        }
    }
}

// ---------------- batched weight transpose: all matrices in one launch ----------------
struct TransDesc { const float* W; __half* WT; int K; int N; int perm; int tileStart; };
struct TransArgs { TransDesc d[13]; };

__global__ __launch_bounds__(256)
void transpose_all_kernel(TransArgs a) {
    __shared__ float t[32][33];
    const int bid = blockIdx.x;
    int i = 0;
#pragma unroll
    for (int k = 0; k < 12; k++) if (bid >= a.d[k + 1].tileStart) i = k + 1;
    const TransDesc& td = a.d[i];
    const int local = bid - td.tileStart;
    const int ntx = td.N / 32;
    const int n0 = (local % ntx) * 32, k0 = (local / ntx) * 32;
    const int tx = threadIdx.x & 31, ty = threadIdx.x >> 5;
#pragma unroll
    for (int j = 0; j < 4; j++)
        t[ty + j * 8][tx] = td.W[(size_t)(k0 + ty + j * 8) * td.N + n0 + tx];
    __syncthreads();
#pragma unroll
    for (int j = 0; j < 4; j++) {
        int n = n0 + ty + j * 8;
        int nd = td.perm ? (4 * (n & 1023) + (n >> 10)) : n;
        td.WT[(size_t)nd * td.K + k0 + tx] = __float2half(t[tx][ty + j * 8]);
    }
}

// -------- LayerNorm + adaLN modulate (IN32 selects fp32/fp16 x; fp16 out) --------
// Proven stride-256 scalar access pattern (4 independent loads/thread).
template<int IN32>
__global__ __launch_bounds__(256)
void ln_mod_kernel(const void* __restrict__ x, const float* __restrict__ mod,
                   int mstride, int shift_off, int scale_off, __half* __restrict__ out) {
    __shared__ float red[16];
    const int tok = blockIdx.x;
    const int tid = threadIdx.x;
    float v[4];
    float s = 0.f, s2 = 0.f;
#pragma unroll
    for (int k = 0; k < 4; k++) {
        float f;
        if (IN32) f = ((const float*)x)[(size_t)tok * DD + tid + k * 256];
        else      f = __half2float(((const __half*)x)[(size_t)tok * DD + tid + k * 256]);
        v[k] = f; s += f; s2 += f * f;
    }
#pragma unroll
    for (int o = 16; o; o >>= 1) {
        s += __shfl_xor_sync(0xffffffffu, s, o);
        s2 += __shfl_xor_sync(0xffffffffu, s2, o);
    }
    if ((tid & 31) == 0) { red[tid >> 5] = s; red[8 + (tid >> 5)] = s2; }
    __syncthreads();
    if (tid == 0) {
        float a = 0.f, b = 0.f;
        for (int i = 0; i < 8; i++) { a += red[i]; b += red[8 + i]; }
        red[0] = a; red[8] = b;
    }
    __syncthreads();
    const float mean = red[0] * (1.f / DD);
    const float var = red[8] * (1.f / DD) - mean * mean;
    const float inv = rsqrtf(var + 1e-6f);
    const int bt = tok >> 8;
    const float* m = mod + (size_t)bt * mstride;
    __half* orow = out + (size_t)tok * DD;
#pragma unroll
    for (int k = 0; k < 4; k++) {
        int d = tid + k * 256;
        float ln = (v[k] - mean) * inv;
        orow[d] = __float2half(ln * (1.f + m[scale_off + d]) + m[shift_off + d]);
    }
}

// ---------------- setup: silu + combined ada bias + permuted lstm bias + barrier reset ----
__global__ void setup_kernel(const float* __restrict__ c, __half* __restrict__ csh,
                             const float* __restrict__ sbp, const float* __restrict__ tbp,
                             const float* __restrict__ rbp, float* __restrict__ adab,
                             const float* __restrict__ lba, const float* __restrict__ lbb,
                             float* __restrict__ lbias) {
    int i = blockIdx.x * 256 + threadIdx.x;
    if (i == 0) g_lstm_bar = 0u;
    if (i < NBT * DD) {
        float v = c[i];
        csh[i] = __float2half(v / (1.f + __expf(-v)));
    }
    if (i < MODW) {
        float b;
        if (i < 6144) b = sbp[i];
        else if (i < 12288) b = tbp[i - 6144];
        else b = rbp[i - 12288];
        adab[i] = b;
    }
    if (i < 4 * DD) {
        int j = i >> 2, g = i & 3;
        lbias[i] = lba[g * 1024 + j] + lbb[g * 1024 + j];
    }
}

// ======= spatial attention via mma.sync fp16 flash (L=256, dh=64, non-causal) =======
__global__ __launch_bounds__(256, 2)
void spatial_attn_tc(const __half* __restrict__ qkv, __half* __restrict__ out) {
    __shared__ __half sQ[128 * 72];
    __shared__ __half sK[64 * 72];
    __shared__ __half sVT[64 * 72];
    const int bid = blockIdx.x;
    const int qhalf = bid & 1;
    const int head = (bid >> 1) & 15;
    const int n = bid >> 5;
    const int tid = threadIdx.x;
    const int lane = tid & 31;
    const int wid = tid >> 5;
    const int g4 = lane >> 2, t4 = lane & 3;
    const size_t rowbase = (size_t)n * 256;

#pragma unroll
    for (int i = 0; i < 4; i++) {
        int idx = tid + i * 256;
        int row = idx >> 3, seg = idx & 7;
        *(uint4*)&sQ[row * 72 + seg * 8] =
            *(const uint4*)(qkv + (rowbase + qhalf * 128 + row) * 3072 + head * 64 + seg * 8);
    }
    __syncthreads();

    uint32_t af[4][4];
    {
        const int r = wid * 16 + g4;
#pragma unroll
        for (int ks = 0; ks < 4; ks++) {
            af[ks][0] = *(const uint32_t*)&sQ[r * 72 + ks * 16 + t4 * 2];
            af[ks][1] = *(const uint32_t*)&sQ[(r + 8) * 72 + ks * 16 + t4 * 2];
            af[ks][2] = *(const uint32_t*)&sQ[r * 72 + ks * 16 + 8 + t4 * 2];
            af[ks][3] = *(const uint32_t*)&sQ[(r + 8) * 72 + ks * 16 + 8 + t4 * 2];
        }
    }

    float O[8][4];
#pragma unroll
    for (int i = 0; i < 8; i++)
#pragma unroll
        for (int q = 0; q < 4; q++) O[i][q] = 0.f;
    float m0 = -1e30f, m1 = -1e30f, l0 = 0.f, l1 = 0.f;

    for (int kt = 0; kt < 4; kt++) {
#pragma unroll
        for (int i = 0; i < 2; i++) {
            int idx = tid + i * 256;
            int row = idx >> 3, seg = idx & 7;
            const __half* src = qkv + (rowbase + kt * 64 + row) * 3072 + 1024 + head * 64 + seg * 8;
            *(uint4*)&sK[row * 72 + seg * 8] = *(const uint4*)src;
            __half vv[8];
            *(uint4*)vv = *(const uint4*)(src + 1024);
#pragma unroll
            for (int jj = 0; jj < 8; jj++) sVT[(seg * 8 + jj) * 72 + row] = vv[jj];
        }
        __syncthreads();

        float sc[8][4];
#pragma unroll
        for (int nt = 0; nt < 8; nt++) {
#pragma unroll
            for (int q = 0; q < 4; q++) sc[nt][q] = 0.f;
#pragma unroll
            for (int ks = 0; ks < 4; ks++) {
                uint32_t b0 = *(const uint32_t*)&sK[(nt * 8 + g4) * 72 + ks * 16 + t4 * 2];
                uint32_t b1 = *(const uint32_t*)&sK[(nt * 8 + g4) * 72 + ks * 16 + 8 + t4 * 2];
                mma_f16(sc[nt], af[ks][0], af[ks][1], af[ks][2], af[ks][3], b0, b1);
            }
        }

        float mx0 = -1e30f, mx1 = -1e30f;
#pragma unroll
        for (int nt = 0; nt < 8; nt++) {
            sc[nt][0] *= 0.125f; sc[nt][1] *= 0.125f;
            sc[nt][2] *= 0.125f; sc[nt][3] *= 0.125f;
            mx0 = fmaxf(mx0, fmaxf(sc[nt][0], sc[nt][1]));
            mx1 = fmaxf(mx1, fmaxf(sc[nt][2], sc[nt][3]));
        }
        mx0 = fmaxf(mx0, __shfl_xor_sync(0xffffffffu, mx0, 1));
        mx0 = fmaxf(mx0, __shfl_xor_sync(0xffffffffu, mx0, 2));
        mx1 = fmaxf(mx1, __shfl_xor_sync(0xffffffffu, mx1, 1));
        mx1 = fmaxf(mx1, __shfl_xor_sync(0xffffffffu, mx1, 2));
        const float mn0 = fmaxf(m0, mx0), mn1 = fmaxf(m1, mx1);
        const float al0 = __expf(m0 - mn0), al1 = __expf(m1 - mn1);
        m0 = mn0; m1 = mn1;

        float sum0 = 0.f, sum1 = 0.f;
        uint32_t aP[8][2];
#pragma unroll
        for (int nt = 0; nt < 8; nt++) {
            float p0 = __expf(sc[nt][0] - mn0);
            float p1 = __expf(sc[nt][1] - mn0);
            float p2 = __expf(sc[nt][2] - mn1);
            float p3 = __expf(sc[nt][3] - mn1);
            sum0 += p0 + p1; sum1 += p2 + p3;
            aP[nt][0] = h2_as_u32(__floats2half2_rn(p0, p1));
            aP[nt][1] = h2_as_u32(__floats2half2_rn(p2, p3));
        }
        sum0 += __shfl_xor_sync(0xffffffffu, sum0, 1);
        sum0 += __shfl_xor_sync(0xffffffffu, sum0, 2);
        sum1 += __shfl_xor_sync(0xffffffffu, sum1, 1);
        sum1 += __shfl_xor_sync(0xffffffffu, sum1, 2);
        l0 = l0 * al0 + sum0;
        l1 = l1 * al1 + sum1;
#pragma unroll
        for (int nt2 = 0; nt2 < 8; nt2++) {
            O[nt2][0] *= al0; O[nt2][1] *= al0;
            O[nt2][2] *= al1; O[nt2][3] *= al1;
        }

#pragma unroll
        for (int ks2 = 0; ks2 < 4; ks2++) {
            const uint32_t a0 = aP[2 * ks2][0], a1 = aP[2 * ks2][1];
            const uint32_t a2 = aP[2 * ks2 + 1][0], a3 = aP[2 * ks2 + 1][1];
#pragma unroll
            for (int nt2 = 0; nt2 < 8; nt2++) {
                uint32_t b0 = *(const uint32_t*)&sVT[(nt2 * 8 + g4) * 72 + ks2 * 16 + t4 * 2];
                uint32_t b1 = *(const uint32_t*)&sVT[(nt2 * 8 + g4) * 72 + ks2 * 16 + 8 + t4 * 2];
                mma_f16(O[nt2], a0, a1, a2, a3, b0, b1);
            }
        }
        __syncthreads();
    }

    const float inv0 = 1.f / l0, inv1 = 1.f / l1;
    const int q0 = qhalf * 128 + wid * 16 + g4;
#pragma unroll
    for (int nt2 = 0; nt2 < 8; nt2++) {
        const int col = head * 64 + nt2 * 8 + t4 * 2;
        *(__half2*)(out + (rowbase + q0) * 1024 + col) =
            __floats2half2_rn(O[nt2][0] * inv0, O[nt2][1] * inv0);
        *(__half2*)(out + (rowbase + q0 + 8) * 1024 + col) =
            __floats2half2_rn(O[nt2][2] * inv1, O[nt2][3] * inv1);
    }
}

// ---------------- temporal attention (T=16, dh=64, causal; fp16 qkv in/out) ----------------
__global__ __launch_bounds__(128)
void temporal_attn_kernel(const __half* __restrict__ qkv, __half* __restrict__ out) {
    __shared__ float Q[16][65], K[16][65], V[16][65], S[16][17];
    const int bid = blockIdx.x;
    const int head = bid & 15;
    const int n = bid >> 4;
    const int b = n >> 8;
    const int hw = n & 255;
    const int tid = threadIdx.x;
    const size_t tokbase = (size_t)b * 4096 + hw;

    for (int i = tid; i < 16 * 64; i += 128) {
        int t = i >> 6, d = i & 63;
        size_t base = (tokbase + (size_t)t * 256) * 3072 + head * 64 + d;
        Q[t][d] = __half2float(qkv[base]);
        K[t][d] = __half2float(qkv[base + 1024]);
        V[t][d] = __half2float(qkv[base + 2048]);
    }
    __syncthreads();

    for (int idx = tid; idx < 256; idx += 128) {
        int qi = idx >> 4, kj = idx & 15;
        float s;
        if (kj <= qi) {
            float acc = 0.f;
#pragma unroll
            for (int d = 0; d < 64; d++) acc += Q[qi][d] * K[kj][d];
            s = acc * 0.125f;
        } else s = -1e30f;
        S[qi][kj] = s;
    }
    __syncthreads();

    {
        const int row = tid >> 3, c0 = tid & 7;
        float mx = fmaxf(S[row][c0], S[row][c0 + 8]);
#pragma unroll
        for (int o = 4; o; o >>= 1) mx = fmaxf(mx, __shfl_xor_sync(0xffffffffu, mx, o));
        float e0 = __expf(S[row][c0] - mx), e1 = __expf(S[row][c0 + 8] - mx);
        float sum = e0 + e1;
#pragma unroll
        for (int o = 4; o; o >>= 1) sum += __shfl_xor_sync(0xffffffffu, sum, o);
        float inv = 1.f / sum;
        S[row][c0] = e0 * inv;
        S[row][c0 + 8] = e1 * inv;
    }
    __syncthreads();

    for (int i = tid; i < 16 * 64; i += 128) {
        int qi = i >> 6, d = i & 63;
        float acc = 0.f;
#pragma unroll
        for (int k = 0; k < 16; k++) acc = fmaf(S[qi][k], V[k][d], acc);
        out[(tokbase + (size_t)qi * 256) * 1024 + head * 64 + d] = __float2half(acc);
    }
}

// ---------------- launch helpers ----------------
static void gemm(const __half* A, const __half* BT, const float* bias, void* C,
                 int M, int N, int K, int epi, int outh) {
    dim3 g(N / 128, (M + 127) / 128);
    if (epi == 1)      gemm_tc<1, 1, 0><<<g, 128, GTC_SMEM_TOTAL>>>(A, BT, bias, C, M, N, K,
                                                                    nullptr, nullptr, 0);
    else if (outh)     gemm_tc<0, 1, 0><<<g, 128, GTC_SMEM_TOTAL>>>(A, BT, bias, C, M, N, K,
                                                                    nullptr, nullptr, 0);
    else               gemm_tc<0, 0, 0><<<g, 128, GTC_SMEM_TOTAL>>>(A, BT, bias, C, M, N, K,
                                                                    nullptr, nullptr, 0);
}
// gated-residual epilogue GEMM: xout = xres + gate*(A@BT^T + bias)
template<int XR32>
static void gemm_ga(const __half* A, const __half* BT, const float* bias, __half* Xout,
                    int M, int N, int K, const void* Xres, const float* modall, int goff) {
    dim3 g(N / 128, (M + 127) / 128);
    gemm_tc<2, 1, XR32><<<g, 128, GTC_SMEM_TOTAL>>>(A, BT, bias, Xout, M, N, K,
                                                    Xres, modall, goff);
}

extern "C" void kernel_launch(void* const* d_in, const int* in_sizes, int n_in,
                              void* d_out, int out_size) {
    const float* x        = (const float*)d_in[0];
    const float* c        = (const float*)d_in[1];
    const float* s_ada_w  = (const float*)d_in[2];
    const float* s_ada_b  = (const float*)d_in[3];
    const float* t_ada_w  = (const float*)d_in[4];
    const float* t_ada_b  = (const float*)d_in[5];
    const float* r_ada_w  = (const float*)d_in[6];
    const float* r_ada_b  = (const float*)d_in[7];
    const float* s_qkv_w  = (const float*)d_in[8];
    const float* s_out_w  = (const float*)d_in[9];
    const float* s_out_b  = (const float*)d_in[10];
    const float* t_qkv_w  = (const float*)d_in[11];
    const float* t_out_w  = (const float*)d_in[12];
    const float* t_out_b  = (const float*)d_in[13];
    const float* s_mlp_w1 = (const float*)d_in[14];
    const float* s_mlp_b1 = (const float*)d_in[15];
    const float* s_mlp_w2 = (const float*)d_in[16];
    const float* s_mlp_b2 = (const float*)d_in[17];
    const float* t_mlp_w1 = (const float*)d_in[18];
    const float* t_mlp_b1 = (const float*)d_in[19];
    const float* t_mlp_w2 = (const float*)d_in[20];
    const float* t_mlp_b2 = (const float*)d_in[21];
    const float* lstm_w_ih = (const float*)d_in[22];
    const float* lstm_w_hh = (const float*)d_in[23];
    const float* lstm_b_ih = (const float*)d_in[24];
    const float* lstm_b_hh = (const float*)d_in[25];
    float* out = (float*)d_out;

    cudaFuncSetAttribute(gemm_tc<0, 0, 0>, cudaFuncAttributeMaxDynamicSharedMemorySize, GTC_SMEM_TOTAL);
    cudaFuncSetAttribute(gemm_tc<0, 1, 0>, cudaFuncAttributeMaxDynamicSharedMemorySize, GTC_SMEM_TOTAL);
    cudaFuncSetAttribute(gemm_tc<1, 1, 0>, cudaFuncAttributeMaxDynamicSharedMemorySize, GTC_SMEM_TOTAL);
    cudaFuncSetAttribute(gemm_tc<2, 1, 0>, cudaFuncAttributeMaxDynamicSharedMemorySize, GTC_SMEM_TOTAL);
    cudaFuncSetAttribute(gemm_tc<2, 1, 1>, cudaFuncAttributeMaxDynamicSharedMemorySize, GTC_SMEM_TOTAL);
    cudaFuncSetAttribute(lstm_persist_tc, cudaFuncAttributeMaxDynamicSharedMemorySize, LSTM_SMEM_TOTAL);

    __half *csh, *h1h, *qkvh, *mlph, *gatesxh, *hstateh, *hstate2h, *wTh, *xbufh;
    float *modall, *adab, *cstate, *lstmbias;
    cudaGetSymbolAddress((void**)&csh, g_csh);
    cudaGetSymbolAddress((void**)&modall, g_modall);
    cudaGetSymbolAddress((void**)&adab, g_adab);
    cudaGetSymbolAddress((void**)&xbufh, g_xbufh);
    cudaGetSymbolAddress((void**)&h1h, g_h1h);
    cudaGetSymbolAddress((void**)&qkvh, g_qkvh);
    cudaGetSymbolAddress((void**)&mlph, g_mlph);
    cudaGetSymbolAddress((void**)&gatesxh, g_gatesxh);
    cudaGetSymbolAddress((void**)&hstateh, g_hstateh);
    cudaGetSymbolAddress((void**)&hstate2h, g_hstate2h);
    cudaGetSymbolAddress((void**)&cstate, g_cstate);
    cudaGetSymbolAddress((void**)&lstmbias, g_lstmbias);
    cudaGetSymbolAddress((void**)&wTh, g_wTh);

    float* rmod = modall + 12288;      // stride MODW

    const size_t MEG = 1048576;
    __half* wt_ada   = wTh + 0 * MEG;   // [15360,1024]: sada|tada|rada contiguous
    __half* wt_sqkv  = wTh + 15 * MEG;
    __half* wt_sout  = wTh + 18 * MEG;
    __half* wt_tqkv  = wTh + 19 * MEG;
    __half* wt_tout  = wTh + 22 * MEG;
    __half* wt_smlp1 = wTh + 23 * MEG;
    __half* wt_smlp2 = wTh + 27 * MEG;
    __half* wt_tmlp1 = wTh + 31 * MEG;
    __half* wt_tmlp2 = wTh + 35 * MEG;
    __half* wt_lih   = wTh + 39 * MEG;  // gate-interleaved [4096,1024]
    __half* wt_lhh   = wTh + 43 * MEG;  // gate-interleaved [4096,1024]

    // batched transpose: all 13 matrices, one launch
    {
        TransArgs ta;
        auto set = [&](int i, const float* W, __half* WT, int K, int N, int perm, int start) {
            ta.d[i].W = W; ta.d[i].WT = WT; ta.d[i].K = K; ta.d[i].N = N;
            ta.d[i].perm = perm; ta.d[i].tileStart = start;
        };
        int s = 0;
        set(0,  s_ada_w,  wt_ada,            1024, 6144, 0, s); s += (6144 / 32) * 32;
        set(1,  t_ada_w,  wt_ada + 6 * MEG,  1024, 6144, 0, s); s += (6144 / 32) * 32;
        set(2,  r_ada_w,  wt_ada + 12 * MEG, 1024, 3072, 0, s); s += (3072 / 32) * 32;
        set(3,  s_qkv_w,  wt_sqkv,  1024, 3072, 0, s); s += (3072 / 32) * 32;
        set(4,  s_out_w,  wt_sout,  1024, 1024, 0, s); s += (1024 / 32) * 32;
        set(5,  t_qkv_w,  wt_tqkv,  1024, 3072, 0, s); s += (3072 / 32) * 32;
        set(6,  t_out_w,  wt_tout,  1024, 1024, 0, s); s += (1024 / 32) * 32;
        set(7,  s_mlp_w1, wt_smlp1, 1024, 4096, 0, s); s += (4096 / 32) * 32;
        set(8,  s_mlp_w2, wt_smlp2, 4096, 1024, 0, s); s += (1024 / 32) * 128;
        set(9,  t_mlp_w1, wt_tmlp1, 1024, 4096, 0, s); s += (4096 / 32) * 32;
        set(10, t_mlp_w2, wt_tmlp2, 4096, 1024, 0, s); s += (1024 / 32) * 128;
        set(11, lstm_w_ih, wt_lih,  1024, 4096, 1, s); s += (4096 / 32) * 32;
        set(12, lstm_w_hh, wt_lhh,  1024, 4096, 1, s); s += (4096 / 32) * 32;
        transpose_all_kernel<<<s, 256>>>(ta);
    }

    // setup (silu + ada bias concat + lstm bias permute + barrier reset)
    setup_kernel<<<(NBT * DD + 255) / 256, 256>>>(c, csh, s_ada_b, t_ada_b, r_ada_b, adab,
                                                  lstm_b_ih, lstm_b_hh, lstmbias);
    gemm(csh, wt_ada, adab, modall, NBT, MODW, DD, 0, 0);

    // absolute offsets into a modall row:
    //   spatial:  shift_msa 0, scale_msa 1024, gate_msa 2048, shift_mlp 3072,
    //             scale_mlp 4096, gate_mlp 5120
    //   temporal: +6144;  recurrent: +12288

    // ---- spatial attention ----
    ln_mod_kernel<1><<<NTOK, 256>>>(x, modall, MODW, 0, 1024, h1h);
    gemm(h1h, wt_sqkv, nullptr, qkvh, NTOK, 3 * DD, DD, 0, 1);
    spatial_attn_tc<<<1024, 256>>>(qkvh, h1h);
    gemm_ga<1>(h1h, wt_sout, s_out_b, xbufh, NTOK, DD, DD, x, modall, 2048);
    ln_mod_kernel<0><<<NTOK, 256>>>(xbufh, modall, MODW, 3072, 4096, h1h);

    // ---- spatial MLP ----
    gemm(h1h, wt_smlp1, s_mlp_b1, mlph, NTOK, 4 * DD, DD, 1, 1);
    gemm_ga<0>(mlph, wt_smlp2, s_mlp_b2, xbufh, NTOK, DD, 4 * DD, xbufh, modall, 5120);
    ln_mod_kernel<0><<<NTOK, 256>>>(xbufh, modall, MODW, 6144, 7168, h1h);

    // ---- temporal attention (causal) ----
    gemm(h1h, wt_tqkv, nullptr, qkvh, NTOK, 3 * DD, DD, 0, 1);
    temporal_attn_kernel<<<8192, 128>>>(qkvh, h1h);
    gemm_ga<0>(h1h, wt_tout, t_out_b, xbufh, NTOK, DD, DD, xbufh, modall, 8192);
    ln_mod_kernel<0><<<NTOK, 256>>>(xbufh, modall, MODW, 9216, 10240, h1h);

    // ---- temporal MLP ----
    gemm(h1h, wt_tmlp1, t_mlp_b1, mlph, NTOK, 4 * DD, DD, 1, 1);
    gemm_ga<0>(mlph, wt_tmlp2, t_mlp_b2, xbufh, NTOK, DD, 4 * DD, xbufh, modall, 11264);
    ln_mod_kernel<0><<<NTOK, 256>>>(xbufh, modall, MODW, 12288, 13312, h1h);

    // ---- LSTM branch: persistent kernel, all 16 steps ----
    gemm(h1h, wt_lih, lstmbias, gatesxh, NTOK, 4 * DD, DD, 0, 1);
    lstm_persist_tc<<<dim3(32, 8), 128, LSTM_SMEM_TOTAL>>>(
        hstateh, hstate2h, wt_lhh, gatesxh, cstate, xbufh, rmod, out);
}

// round 17
// speedup vs baseline: 1.5871x; 1.0120x over previous
#include <cuda_runtime.h>
#include <cuda_fp16.h>
#include <math.h>
#include <cstdint>

// Problem constants
#define DD   1024
#define NTOK 8192      // B*T*H*W
#define NBT  32        // B*T
#define NSEQ 512       // B*H*W
#define TT   16
#define MODW 15360     // 6*DD + 6*DD + 3*DD combined ada width

// ---------------- scratch (device globals; no allocations allowed) ----------------
__device__ __half g_csh[NBT * DD];
__device__ float  g_modall[NBT * MODW];
__device__ float  g_adab[MODW];
__device__ __half g_xbufh[NTOK * DD];
__device__ __half g_h1h[NTOK * DD];
__device__ __half g_qkvh[NTOK * 3 * DD];
__device__ __half g_mlph[NTOK * 4 * DD];
__device__ __half g_gatesxh[NTOK * 4 * DD];
__device__ __half g_hstateh[NSEQ * DD];
__device__ __half g_hstate2h[NSEQ * DD];
__device__ float  g_cstate[NSEQ * DD];
__device__ float  g_lstmbias[4 * DD];
__device__ unsigned int g_lstm_bars[8];
__device__ __half g_wTh[47u * 1048576u];   // transposed fp16 weights

__device__ __forceinline__ float tanh_fast(float x) {
    float r; asm("tanh.approx.f32 %0, %1;" : "=f"(r) : "f"(x)); return r;
}
__device__ __forceinline__ float gelu_tanh(float x) {
    return 0.5f * x * (1.f + tanh_fast(0.7978845608028654f * (x + 0.044715f * x * x * x)));
}
__device__ __forceinline__ float sigm(float x) { return 0.5f * (1.f + tanh_fast(0.5f * x)); }
__device__ __forceinline__ uint32_t h2_as_u32(__half2 h) {
    uint32_t u; *reinterpret_cast<__half2*>(&u) = h; return u;
}
__device__ __forceinline__ void mma_f16(float d[4], uint32_t a0, uint32_t a1, uint32_t a2,
                                        uint32_t a3, uint32_t b0, uint32_t b1) {
    asm volatile(
        "mma.sync.aligned.m16n8k16.row.col.f32.f16.f16.f32 "
        "{%0,%1,%2,%3}, {%4,%5,%6,%7}, {%8,%9}, {%0,%1,%2,%3};\n"
        : "+f"(d[0]), "+f"(d[1]), "+f"(d[2]), "+f"(d[3])
        : "r"(a0), "r"(a1), "r"(a2), "r"(a3), "r"(b0), "r"(b1));
}
__device__ __forceinline__ void cp_async16(uint32_t dst, const void* src, int szvalid) {
    asm volatile("cp.async.cg.shared.global [%0], [%1], 16, %2;"
                 :: "r"(dst), "l"(src), "r"(szvalid));
}
__device__ __forceinline__ void cp_commit() { asm volatile("cp.async.commit_group;"); }

// ================== fp16 tensor-core GEMM: C[M,N] = A[M,K] @ BT[N,K]^T ==================
// 128 threads = 4 warps (2x2), warp tile 64x64, block tile 128x128x32, 4-stage cp.async.
// EPI: 0 = +bias, 1 = gelu(tanh)(x+bias), 2 = gated residual add (xout = xres + gate*(v+bias))
// OUTH: 0 = fp32 C, 1 = fp16 C. XR32 (EPI==2 only): xres is fp32 (else fp16).
#define GPITCH_B   80
#define GOP_BYTES  (128 * GPITCH_B)
#define GSTAGE_B   (2 * GOP_BYTES)       // 20480 per stage
#define GTC_NSTAGE 4
#define GTC_SMEM_TOTAL (GTC_NSTAGE * GSTAGE_B)   // 81920 bytes

template<int EPI, int OUTH, int XR32>
__global__ __launch_bounds__(128, 2)
void gemm_tc(const __half* __restrict__ A, const __half* __restrict__ BT,
             const float* __restrict__ bias, void* __restrict__ Cout,
             int M, int N, int K,
             const void* __restrict__ Xres, const float* __restrict__ modall, int goff) {
    extern __shared__ char smem[];
    const uint32_t sb = (uint32_t)__cvta_generic_to_shared(smem);
    const int tid = threadIdx.x;
    const int lane = tid & 31;
    const int wid = tid >> 5;
    const int wr = wid >> 1;
    const int wc = wid & 1;
    const int g4 = lane >> 2, t4 = lane & 3;
    const int bx = blockIdx.x, by = blockIdx.y;
    const int gra = by * 128;
    const int gnb = bx * 128;

    float acc[4][8][4];
#pragma unroll
    for (int mt = 0; mt < 4; mt++)
#pragma unroll
        for (int nt = 0; nt < 8; nt++)
#pragma unroll
            for (int q = 0; q < 4; q++) acc[mt][nt][q] = 0.f;

    const int nk = K >> 5;

    auto load_stage = [&](int kc, int s) {
        const uint32_t sbase = sb + s * GSTAGE_B;
#pragma unroll
        for (int i = 0; i < 4; i++) {
            const int c = tid + i * 128;
            const int row = c >> 2, seg = c & 3;
            const int ga = gra + row;
            const bool ok = ga < M;
            cp_async16(sbase + row * GPITCH_B + seg * 16,
                       A + (size_t)(ok ? ga : 0) * K + kc * 32 + seg * 8, ok ? 16 : 0);
            cp_async16(sbase + GOP_BYTES + row * GPITCH_B + seg * 16,
                       BT + (size_t)(gnb + row) * K + kc * 32 + seg * 8, 16);
        }
    };

    load_stage(0, 0); cp_commit();
    load_stage(1, 1); cp_commit();
    load_stage(2, 2); cp_commit();

    for (int kc = 0; kc < nk; kc++) {
        if (kc < nk - 2)       asm volatile("cp.async.wait_group 2;");
        else if (kc == nk - 2) asm volatile("cp.async.wait_group 1;");
        else                   asm volatile("cp.async.wait_group 0;");
        __syncthreads();
        if (kc + 3 < nk) { load_stage(kc + 3, (kc + 3) & (GTC_NSTAGE - 1)); cp_commit(); }

        const char* sA = smem + (kc & (GTC_NSTAGE - 1)) * GSTAGE_B;
        const char* sB = sA + GOP_BYTES;
#pragma unroll
        for (int ks = 0; ks < 2; ks++) {
            const int kb = ks * 32 + t4 * 4;
            uint32_t af[4][4];
            uint32_t bf[8][2];
#pragma unroll
            for (int mt = 0; mt < 4; mt++) {
                const int r = wr * 64 + mt * 16 + g4;
                af[mt][0] = *(const uint32_t*)(sA + r * GPITCH_B + kb);
                af[mt][1] = *(const uint32_t*)(sA + (r + 8) * GPITCH_B + kb);
                af[mt][2] = *(const uint32_t*)(sA + r * GPITCH_B + kb + 16);
                af[mt][3] = *(const uint32_t*)(sA + (r + 8) * GPITCH_B + kb + 16);
            }
#pragma unroll
            for (int nt = 0; nt < 8; nt++) {
                const int n = wc * 64 + nt * 8 + g4;
                bf[nt][0] = *(const uint32_t*)(sB + n * GPITCH_B + kb);
                bf[nt][1] = *(const uint32_t*)(sB + n * GPITCH_B + kb + 16);
            }
#pragma unroll
            for (int mt = 0; mt < 4; mt++)
#pragma unroll
                for (int nt = 0; nt < 8; nt++)
                    mma_f16(acc[mt][nt], af[mt][0], af[mt][1], af[mt][2], af[mt][3],
                            bf[nt][0], bf[nt][1]);
        }
    }

    // gate row pointer (EPI==2): 128-row tile is bt-aligned (256 rows/bt) => bt = by>>1
    const float* gp = (EPI == 2) ? (modall + (size_t)(by >> 1) * MODW + goff) : nullptr;

#pragma unroll
    for (int mt = 0; mt < 4; mt++) {
        const int r0 = by * 128 + wr * 64 + mt * 16 + g4;
#pragma unroll
        for (int nt = 0; nt < 8; nt++) {
            const int col = bx * 128 + wc * 64 + nt * 8 + t4 * 2;
            float b0 = 0.f, b1 = 0.f;
            if (bias) { b0 = __ldg(bias + col); b1 = __ldg(bias + col + 1); }
            float v0 = acc[mt][nt][0] + b0;
            float v1 = acc[mt][nt][1] + b1;
            float v2 = acc[mt][nt][2] + b0;
            float v3 = acc[mt][nt][3] + b1;
            if (EPI == 1) {
                v0 = gelu_tanh(v0); v1 = gelu_tanh(v1);
                v2 = gelu_tanh(v2); v3 = gelu_tanh(v3);
            }
            if (EPI == 2) {
                const float gg0 = __ldg(gp + col);
                const float gg1 = __ldg(gp + col + 1);
                float x0, x1, x2, x3;
                if (XR32) {
                    float2 a = *(const float2*)((const float*)Xres + (size_t)r0 * N + col);
                    float2 b = *(const float2*)((const float*)Xres + (size_t)(r0 + 8) * N + col);
                    x0 = a.x; x1 = a.y; x2 = b.x; x3 = b.y;
                } else {
                    __half2 a = *(const __half2*)((const __half*)Xres + (size_t)r0 * N + col);
                    __half2 b = *(const __half2*)((const __half*)Xres + (size_t)(r0 + 8) * N + col);
                    x0 = __half2float(__low2half(a)); x1 = __half2float(__high2half(a));
                    x2 = __half2float(__low2half(b)); x3 = __half2float(__high2half(b));
                }
                v0 = x0 + gg0 * v0; v1 = x1 + gg1 * v1;
                v2 = x2 + gg0 * v2; v3 = x3 + gg1 * v3;
                __half* Ch = (__half*)Cout;
                *(__half2*)(Ch + (size_t)r0 * N + col) = __floats2half2_rn(v0, v1);
                *(__half2*)(Ch + (size_t)(r0 + 8) * N + col) = __floats2half2_rn(v2, v3);
            } else if (OUTH) {
                __half* Ch = (__half*)Cout;
                if (r0 < M) *(__half2*)(Ch + (size_t)r0 * N + col) = __floats2half2_rn(v0, v1);
                if (r0 + 8 < M) *(__half2*)(Ch + (size_t)(r0 + 8) * N + col) = __floats2half2_rn(v2, v3);
            } else {
                float* Cf = (float*)Cout;
                if (r0 < M) *(float2*)(Cf + (size_t)r0 * N + col) = make_float2(v0, v1);
                if (r0 + 8 < M) *(float2*)(Cf + (size_t)(r0 + 8) * N + col) = make_float2(v2, v3);
            }
        }
    }
}

// ============ persistent fused LSTM: all 16 steps in one launch, 4-stage pipeline ============
// Per-by row-group barrier (32 arrivals): step t+1 CTA (bx,by) only reads h rows written
// by the 32 CTAs sharing by; cstate is owner-local; gx/xbuf/rmod read-only.
#define LSA_OP   (64 * GPITCH_B)
#define LSB_OP   (128 * GPITCH_B)
#define LSTAGE_B (LSA_OP + LSB_OP)      // 15360
#define LSTM_NSTAGE 4
#define LSTM_SMEM_TOTAL (LSTM_NSTAGE * LSTAGE_B)   // 61440

__global__ __launch_bounds__(128, 2)
void lstm_persist_tc(__half* __restrict__ h0buf, __half* __restrict__ h1buf,
                     const __half* __restrict__ BT, const __half* __restrict__ gx,
                     float* __restrict__ cst, const __half* __restrict__ xbuf,
                     const float* __restrict__ rmod, float* __restrict__ outp) {
    extern __shared__ char smem[];
    const uint32_t sb = (uint32_t)__cvta_generic_to_shared(smem);
    const int tid = threadIdx.x;
    const int lane = tid & 31;
    const int wid = tid >> 5;
    const int wr = wid >> 1;
    const int wc = wid & 1;
    const int g4 = lane >> 2, t4 = lane & 3;
    const int bx = blockIdx.x, by = blockIdx.y;
    const int gra = by * 64;
    const int gnb = bx * 128;
    const int K = 1024, nk = 32;

    for (int t = 0; t < TT; t++) {
        const __half* A = (t & 1) ? h1buf : h0buf;
        __half* hnext = (t & 1) ? h0buf : h1buf;

        float acc[2][8][4];
#pragma unroll
        for (int mt = 0; mt < 2; mt++)
#pragma unroll
            for (int nt = 0; nt < 8; nt++)
#pragma unroll
                for (int q = 0; q < 4; q++) acc[mt][nt][q] = 0.f;

        if (t > 0) {
            auto load_stage = [&](int kc, int s) {
                const uint32_t sbase = sb + s * LSTAGE_B;
#pragma unroll
                for (int i = 0; i < 2; i++) {
                    const int c = tid + i * 128;
                    const int row = c >> 2, seg = c & 3;
                    cp_async16(sbase + row * GPITCH_B + seg * 16,
                               A + (size_t)(gra + row) * K + kc * 32 + seg * 8, 16);
                }
#pragma unroll
                for (int i = 0; i < 4; i++) {
                    const int c = tid + i * 128;
                    const int row = c >> 2, seg = c & 3;
                    cp_async16(sbase + LSA_OP + row * GPITCH_B + seg * 16,
                               BT + (size_t)(gnb + row) * K + kc * 32 + seg * 8, 16);
                }
            };

            load_stage(0, 0); cp_commit();
            load_stage(1, 1); cp_commit();
            load_stage(2, 2); cp_commit();

            for (int kc = 0; kc < nk; kc++) {
                if (kc < nk - 2)       asm volatile("cp.async.wait_group 2;");
                else if (kc == nk - 2) asm volatile("cp.async.wait_group 1;");
                else                   asm volatile("cp.async.wait_group 0;");
                __syncthreads();
                if (kc + 3 < nk) { load_stage(kc + 3, (kc + 3) & (LSTM_NSTAGE - 1)); cp_commit(); }

                const char* sA = smem + (kc & (LSTM_NSTAGE - 1)) * LSTAGE_B;
                const char* sB = sA + LSA_OP;
#pragma unroll
                for (int ks = 0; ks < 2; ks++) {
                    const int kb = ks * 32 + t4 * 4;
                    uint32_t af[2][4];
                    uint32_t bf[8][2];
#pragma unroll
                    for (int mt = 0; mt < 2; mt++) {
                        const int r = wr * 32 + mt * 16 + g4;
                        af[mt][0] = *(const uint32_t*)(sA + r * GPITCH_B + kb);
                        af[mt][1] = *(const uint32_t*)(sA + (r + 8) * GPITCH_B + kb);
                        af[mt][2] = *(const uint32_t*)(sA + r * GPITCH_B + kb + 16);
                        af[mt][3] = *(const uint32_t*)(sA + (r + 8) * GPITCH_B + kb + 16);
                    }
#pragma unroll
                    for (int nt = 0; nt < 8; nt++) {
                        const int n = wc * 64 + nt * 8 + g4;
                        bf[nt][0] = *(const uint32_t*)(sB + n * GPITCH_B + kb);
                        bf[nt][1] = *(const uint32_t*)(sB + n * GPITCH_B + kb + 16);
                    }
#pragma unroll
                    for (int mt = 0; mt < 2; mt++)
#pragma unroll
                        for (int nt = 0; nt < 8; nt++)
                            mma_f16(acc[mt][nt], af[mt][0], af[mt][1], af[mt][2], af[mt][3],
                                    bf[nt][0], bf[nt][1]);
                }
            }
        }

#pragma unroll
        for (int mt = 0; mt < 2; mt++) {
            const int r0 = by * 64 + wr * 32 + mt * 16 + g4;
            const int r1 = r0 + 8;
            const int tok0 = ((r0 >> 8) << 12) + (t << 8) + (r0 & 255);
            const int tok1 = ((r1 >> 8) << 12) + (t << 8) + (r1 & 255);
            const int bt0 = tok0 >> 8, bt1 = tok1 >> 8;
#pragma unroll
            for (int nt = 0; nt < 8; nt++) {
                const int col = bx * 128 + wc * 64 + nt * 8 + t4 * 2;
                __half2 gx0 = *(const __half2*)(gx + (size_t)tok0 * 4096 + col);
                __half2 gx1 = *(const __half2*)(gx + (size_t)tok1 * 4096 + col);
                float v0 = acc[mt][nt][0] + __half2float(__low2half(gx0));
                float v1 = acc[mt][nt][1] + __half2float(__high2half(gx0));
                float v2 = acc[mt][nt][2] + __half2float(__low2half(gx1));
                float v3 = acc[mt][nt][3] + __half2float(__high2half(gx1));
                float p0 = __shfl_xor_sync(0xffffffffu, v0, 1);
                float p1 = __shfl_xor_sync(0xffffffffu, v1, 1);
                float p2 = __shfl_xor_sync(0xffffffffu, v2, 1);
                float p3 = __shfl_xor_sync(0xffffffffu, v3, 1);
                if (!(lane & 1)) {
                    const int j = col >> 2;
                    {
                        float cprev = (t == 0) ? 0.f : cst[r0 * 1024 + j];
                        float cc = sigm(v1) * cprev + sigm(v0) * tanh_fast(p0);
                        float hh = sigm(p1) * tanh_fast(cc);
                        cst[r0 * 1024 + j] = cc;
                        hnext[r0 * 1024 + j] = __float2half(hh);
                        float rg = rmod[bt0 * MODW + 2048 + j];
                        outp[(size_t)tok0 * 1024 + j] =
                            __half2float(xbuf[(size_t)tok0 * 1024 + j]) + rg * hh;
                    }
                    {
                        float cprev = (t == 0) ? 0.f : cst[r1 * 1024 + j];
                        float cc = sigm(v3) * cprev + sigm(v2) * tanh_fast(p2);
                        float hh = sigm(p3) * tanh_fast(cc);
                        cst[r1 * 1024 + j] = cc;
                        hnext[r1 * 1024 + j] = __float2half(hh);
                        float rg = rmod[bt1 * MODW + 2048 + j];
                        outp[(size_t)tok1 * 1024 + j] =
                            __half2float(xbuf[(size_t)tok1 * 1024 + j]) + rg * hh;
                    }
                }
            }
        }

        // per-by row-group barrier (32 arrivals per group) between steps
        if (t < TT - 1) {
            __syncthreads();
            if (tid == 0) {
                __threadfence();
                atomicAdd(&g_lstm_bars[by], 1u);
                const unsigned int target = 32u * (unsigned int)(t + 1);
                while (atomicAdd(&g_lstm_bars[by], 0u) < target) {}
                __threadfence();
            }
            __syncthreads();
        }
    }
}

// ---------------- batched weight transpose: all matrices in one launch ----------------
struct TransDesc { const float* W; __half* WT; int K; int N; int perm; int tileStart; };
struct TransArgs { TransDesc d[13]; };

__global__ __launch_bounds__(256)
void transpose_all_kernel(TransArgs a) {
    __shared__ float t[32][33];
    const int bid = blockIdx.x;
    int i = 0;
#pragma unroll
    for (int k = 0; k < 12; k++) if (bid >= a.d[k + 1].tileStart) i = k + 1;
    const TransDesc& td = a.d[i];
    const int local = bid - td.tileStart;
    const int ntx = td.N / 32;
    const int n0 = (local % ntx) * 32, k0 = (local / ntx) * 32;
    const int tx = threadIdx.x & 31, ty = threadIdx.x >> 5;
#pragma unroll
    for (int j = 0; j < 4; j++)
        t[ty + j * 8][tx] = td.W[(size_t)(k0 + ty + j * 8) * td.N + n0 + tx];
    __syncthreads();
#pragma unroll
    for (int j = 0; j < 4; j++) {
        int n = n0 + ty + j * 8;
        int nd = td.perm ? (4 * (n & 1023) + (n >> 10)) : n;
        td.WT[(size_t)nd * td.K + k0 + tx] = __float2half(t[tx][ty + j * 8]);
    }
}

// -------- LayerNorm + adaLN modulate (IN32 selects fp32/fp16 x; fp16 out) --------
// Proven stride-256 scalar access pattern (4 independent loads/thread).
template<int IN32>
__global__ __launch_bounds__(256)
void ln_mod_kernel(const void* __restrict__ x, const float* __restrict__ mod,
                   int mstride, int shift_off, int scale_off, __half* __restrict__ out) {
    __shared__ float red[16];
    const int tok = blockIdx.x;
    const int tid = threadIdx.x;
    float v[4];
    float s = 0.f, s2 = 0.f;
#pragma unroll
    for (int k = 0; k < 4; k++) {
        float f;
        if (IN32) f = ((const float*)x)[(size_t)tok * DD + tid + k * 256];
        else      f = __half2float(((const __half*)x)[(size_t)tok * DD + tid + k * 256]);
        v[k] = f; s += f; s2 += f * f;
    }
#pragma unroll
    for (int o = 16; o; o >>= 1) {
        s += __shfl_xor_sync(0xffffffffu, s, o);
        s2 += __shfl_xor_sync(0xffffffffu, s2, o);
    }
    if ((tid & 31) == 0) { red[tid >> 5] = s; red[8 + (tid >> 5)] = s2; }
    __syncthreads();
    if (tid == 0) {
        float a = 0.f, b = 0.f;
        for (int i = 0; i < 8; i++) { a += red[i]; b += red[8 + i]; }
        red[0] = a; red[8] = b;
    }
    __syncthreads();
    const float mean = red[0] * (1.f / DD);
    const float var = red[8] * (1.f / DD) - mean * mean;
    const float inv = rsqrtf(var + 1e-6f);
    const int bt = tok >> 8;
    const float* m = mod + (size_t)bt * mstride;
    __half* orow = out + (size_t)tok * DD;
#pragma unroll
    for (int k = 0; k < 4; k++) {
        int d = tid + k * 256;
        float ln = (v[k] - mean) * inv;
        orow[d] = __float2half(ln * (1.f + m[scale_off + d]) + m[shift_off + d]);
    }
}

// ---------------- setup: silu + combined ada bias + permuted lstm bias + barrier reset ----
__global__ void setup_kernel(const float* __restrict__ c, __half* __restrict__ csh,
                             const float* __restrict__ sbp, const float* __restrict__ tbp,
                             const float* __restrict__ rbp, float* __restrict__ adab,
                             const float* __restrict__ lba, const float* __restrict__ lbb,
                             float* __restrict__ lbias) {
    int i = blockIdx.x * 256 + threadIdx.x;
    if (i < 8) g_lstm_bars[i] = 0u;
    if (i < NBT * DD) {
        float v = c[i];
        csh[i] = __float2half(v / (1.f + __expf(-v)));
    }
    if (i < MODW) {
        float b;
        if (i < 6144) b = sbp[i];
        else if (i < 12288) b = tbp[i - 6144];
        else b = rbp[i - 12288];
        adab[i] = b;
    }
    if (i < 4 * DD) {
        int j = i >> 2, g = i & 3;
        lbias[i] = lba[g * 1024 + j] + lbb[g * 1024 + j];
    }
}

// ======= spatial attention via mma.sync fp16 flash (L=256, dh=64, non-causal) =======
__global__ __launch_bounds__(256, 2)
void spatial_attn_tc(const __half* __restrict__ qkv, __half* __restrict__ out) {
    __shared__ __half sQ[128 * 72];
    __shared__ __half sK[64 * 72];
    __shared__ __half sVT[64 * 72];
    const int bid = blockIdx.x;
    const int qhalf = bid & 1;
    const int head = (bid >> 1) & 15;
    const int n = bid >> 5;
    const int tid = threadIdx.x;
    const int lane = tid & 31;
    const int wid = tid >> 5;
    const int g4 = lane >> 2, t4 = lane & 3;
    const size_t rowbase = (size_t)n * 256;

#pragma unroll
    for (int i = 0; i < 4; i++) {
        int idx = tid + i * 256;
        int row = idx >> 3, seg = idx & 7;
        *(uint4*)&sQ[row * 72 + seg * 8] =
            *(const uint4*)(qkv + (rowbase + qhalf * 128 + row) * 3072 + head * 64 + seg * 8);
    }
    __syncthreads();

    uint32_t af[4][4];
    {
        const int r = wid * 16 + g4;
#pragma unroll
        for (int ks = 0; ks < 4; ks++) {
            af[ks][0] = *(const uint32_t*)&sQ[r * 72 + ks * 16 + t4 * 2];
            af[ks][1] = *(const uint32_t*)&sQ[(r + 8) * 72 + ks * 16 + t4 * 2];
            af[ks][2] = *(const uint32_t*)&sQ[r * 72 + ks * 16 + 8 + t4 * 2];
            af[ks][3] = *(const uint32_t*)&sQ[(r + 8) * 72 + ks * 16 + 8 + t4 * 2];
        }
    }

    float O[8][4];
#pragma unroll
    for (int i = 0; i < 8; i++)
#pragma unroll
        for (int q = 0; q < 4; q++) O[i][q] = 0.f;
    float m0 = -1e30f, m1 = -1e30f, l0 = 0.f, l1 = 0.f;

    for (int kt = 0; kt < 4; kt++) {
#pragma unroll
        for (int i = 0; i < 2; i++) {
            int idx = tid + i * 256;
            int row = idx >> 3, seg = idx & 7;
            const __half* src = qkv + (rowbase + kt * 64 + row) * 3072 + 1024 + head * 64 + seg * 8;
            *(uint4*)&sK[row * 72 + seg * 8] = *(const uint4*)src;
            __half vv[8];
            *(uint4*)vv = *(const uint4*)(src + 1024);
#pragma unroll
            for (int jj = 0; jj < 8; jj++) sVT[(seg * 8 + jj) * 72 + row] = vv[jj];
        }
        __syncthreads();

        float sc[8][4];
#pragma unroll
        for (int nt = 0; nt < 8; nt++) {
#pragma unroll
            for (int q = 0; q < 4; q++) sc[nt][q] = 0.f;
#pragma unroll
            for (int ks = 0; ks < 4; ks++) {
                uint32_t b0 = *(const uint32_t*)&sK[(nt * 8 + g4) * 72 + ks * 16 + t4 * 2];
                uint32_t b1 = *(const uint32_t*)&sK[(nt * 8 + g4) * 72 + ks * 16 + 8 + t4 * 2];
                mma_f16(sc[nt], af[ks][0], af[ks][1], af[ks][2], af[ks][3], b0, b1);
            }
        }

        float mx0 = -1e30f, mx1 = -1e30f;
#pragma unroll
        for (int nt = 0; nt < 8; nt++) {
            sc[nt][0] *= 0.125f; sc[nt][1] *= 0.125f;
            sc[nt][2] *= 0.125f; sc[nt][3] *= 0.125f;
            mx0 = fmaxf(mx0, fmaxf(sc[nt][0], sc[nt][1]));
            mx1 = fmaxf(mx1, fmaxf(sc[nt][2], sc[nt][3]));
        }
        mx0 = fmaxf(mx0, __shfl_xor_sync(0xffffffffu, mx0, 1));
        mx0 = fmaxf(mx0, __shfl_xor_sync(0xffffffffu, mx0, 2));
        mx1 = fmaxf(mx1, __shfl_xor_sync(0xffffffffu, mx1, 1));
        mx1 = fmaxf(mx1, __shfl_xor_sync(0xffffffffu, mx1, 2));
        const float mn0 = fmaxf(m0, mx0), mn1 = fmaxf(m1, mx1);
        const float al0 = __expf(m0 - mn0), al1 = __expf(m1 - mn1);
        m0 = mn0; m1 = mn1;

        float sum0 = 0.f, sum1 = 0.f;
        uint32_t aP[8][2];
#pragma unroll
        for (int nt = 0; nt < 8; nt++) {
            float p0 = __expf(sc[nt][0] - mn0);
            float p1 = __expf(sc[nt][1] - mn0);
            float p2 = __expf(sc[nt][2] - mn1);
            float p3 = __expf(sc[nt][3] - mn1);
            sum0 += p0 + p1; sum1 += p2 + p3;
            aP[nt][0] = h2_as_u32(__floats2half2_rn(p0, p1));
            aP[nt][1] = h2_as_u32(__floats2half2_rn(p2, p3));
        }
        sum0 += __shfl_xor_sync(0xffffffffu, sum0, 1);
        sum0 += __shfl_xor_sync(0xffffffffu, sum0, 2);
        sum1 += __shfl_xor_sync(0xffffffffu, sum1, 1);
        sum1 += __shfl_xor_sync(0xffffffffu, sum1, 2);
        l0 = l0 * al0 + sum0;
        l1 = l1 * al1 + sum1;
#pragma unroll
        for (int nt2 = 0; nt2 < 8; nt2++) {
            O[nt2][0] *= al0; O[nt2][1] *= al0;
            O[nt2][2] *= al1; O[nt2][3] *= al1;
        }

#pragma unroll
        for (int ks2 = 0; ks2 < 4; ks2++) {
            const uint32_t a0 = aP[2 * ks2][0], a1 = aP[2 * ks2][1];
            const uint32_t a2 = aP[2 * ks2 + 1][0], a3 = aP[2 * ks2 + 1][1];
#pragma unroll
            for (int nt2 = 0; nt2 < 8; nt2++) {
                uint32_t b0 = *(const uint32_t*)&sVT[(nt2 * 8 + g4) * 72 + ks2 * 16 + t4 * 2];
                uint32_t b1 = *(const uint32_t*)&sVT[(nt2 * 8 + g4) * 72 + ks2 * 16 + 8 + t4 * 2];
                mma_f16(O[nt2], a0, a1, a2, a3, b0, b1);
            }
        }
        __syncthreads();
    }

    const float inv0 = 1.f / l0, inv1 = 1.f / l1;
    const int q0 = qhalf * 128 + wid * 16 + g4;
#pragma unroll
    for (int nt2 = 0; nt2 < 8; nt2++) {
        const int col = head * 64 + nt2 * 8 + t4 * 2;
        *(__half2*)(out + (rowbase + q0) * 1024 + col) =
            __floats2half2_rn(O[nt2][0] * inv0, O[nt2][1] * inv0);
        *(__half2*)(out + (rowbase + q0 + 8) * 1024 + col) =
            __floats2half2_rn(O[nt2][2] * inv1, O[nt2][3] * inv1);
    }
}

// ---------------- temporal attention (T=16, dh=64, causal; fp16 qkv in/out) ----------------
__global__ __launch_bounds__(128)
void temporal_attn_kernel(const __half* __restrict__ qkv, __half* __restrict__ out) {
    __shared__ float Q[16][65], K[16][65], V[16][65], S[16][17];
    const int bid = blockIdx.x;
    const int head = bid & 15;
    const int n = bid >> 4;
    const int b = n >> 8;
    const int hw = n & 255;
    const int tid = threadIdx.x;
    const size_t tokbase = (size_t)b * 4096 + hw;

    for (int i = tid; i < 16 * 64; i += 128) {
        int t = i >> 6, d = i & 63;
        size_t base = (tokbase + (size_t)t * 256) * 3072 + head * 64 + d;
        Q[t][d] = __half2float(qkv[base]);
        K[t][d] = __half2float(qkv[base + 1024]);
        V[t][d] = __half2float(qkv[base + 2048]);
    }
    __syncthreads();

    for (int idx = tid; idx < 256; idx += 128) {
        int qi = idx >> 4, kj = idx & 15;
        float s;
        if (kj <= qi) {
            float acc = 0.f;
#pragma unroll
            for (int d = 0; d < 64; d++) acc += Q[qi][d] * K[kj][d];
            s = acc * 0.125f;
        } else s = -1e30f;
        S[qi][kj] = s;
    }
    __syncthreads();

    {
        const int row = tid >> 3, c0 = tid & 7;
        float mx = fmaxf(S[row][c0], S[row][c0 + 8]);
#pragma unroll
        for (int o = 4; o; o >>= 1) mx = fmaxf(mx, __shfl_xor_sync(0xffffffffu, mx, o));
        float e0 = __expf(S[row][c0] - mx), e1 = __expf(S[row][c0 + 8] - mx);
        float sum = e0 + e1;
#pragma unroll
        for (int o = 4; o; o >>= 1) sum += __shfl_xor_sync(0xffffffffu, sum, o);
        float inv = 1.f / sum;
        S[row][c0] = e0 * inv;
        S[row][c0 + 8] = e1 * inv;
    }
    __syncthreads();

    for (int i = tid; i < 16 * 64; i += 128) {
        int qi = i >> 6, d = i & 63;
        float acc = 0.f;
#pragma unroll
        for (int k = 0; k < 16; k++) acc = fmaf(S[qi][k], V[k][d], acc);
        out[(tokbase + (size_t)qi * 256) * 1024 + head * 64 + d] = __float2half(acc);
    }
}

// ---------------- launch helpers ----------------
static void gemm(const __half* A, const __half* BT, const float* bias, void* C,
                 int M, int N, int K, int epi, int outh) {
    dim3 g(N / 128, (M + 127) / 128);
    if (epi == 1)      gemm_tc<1, 1, 0><<<g, 128, GTC_SMEM_TOTAL>>>(A, BT, bias, C, M, N, K,
                                                                    nullptr, nullptr, 0);
    else if (outh)     gemm_tc<0, 1, 0><<<g, 128, GTC_SMEM_TOTAL>>>(A, BT, bias, C, M, N, K,
                                                                    nullptr, nullptr, 0);
    else               gemm_tc<0, 0, 0><<<g, 128, GTC_SMEM_TOTAL>>>(A, BT, bias, C, M, N, K,
                                                                    nullptr, nullptr, 0);
}
// gated-residual epilogue GEMM: xout = xres + gate*(A@BT^T + bias)
template<int XR32>
static void gemm_ga(const __half* A, const __half* BT, const float* bias, __half* Xout,
                    int M, int N, int K, const void* Xres, const float* modall, int goff) {
    dim3 g(N / 128, (M + 127) / 128);
    gemm_tc<2, 1, XR32><<<g, 128, GTC_SMEM_TOTAL>>>(A, BT, bias, Xout, M, N, K,
                                                    Xres, modall, goff);
}

extern "C" void kernel_launch(void* const* d_in, const int* in_sizes, int n_in,
                              void* d_out, int out_size) {
    const float* x        = (const float*)d_in[0];
    const float* c        = (const float*)d_in[1];
    const float* s_ada_w  = (const float*)d_in[2];
    const float* s_ada_b  = (const float*)d_in[3];
    const float* t_ada_w  = (const float*)d_in[4];
    const float* t_ada_b  = (const float*)d_in[5];
    const float* r_ada_w  = (const float*)d_in[6];
    const float* r_ada_b  = (const float*)d_in[7];
    const float* s_qkv_w  = (const float*)d_in[8];
    const float* s_out_w  = (const float*)d_in[9];
    const float* s_out_b  = (const float*)d_in[10];
    const float* t_qkv_w  = (const float*)d_in[11];
    const float* t_out_w  = (const float*)d_in[12];
    const float* t_out_b  = (const float*)d_in[13];
    const float* s_mlp_w1 = (const float*)d_in[14];
    const float* s_mlp_b1 = (const float*)d_in[15];
    const float* s_mlp_w2 = (const float*)d_in[16];
    const float* s_mlp_b2 = (const float*)d_in[17];
    const float* t_mlp_w1 = (const float*)d_in[18];
    const float* t_mlp_b1 = (const float*)d_in[19];
    const float* t_mlp_w2 = (const float*)d_in[20];
    const float* t_mlp_b2 = (const float*)d_in[21];
    const float* lstm_w_ih = (const float*)d_in[22];
    const float* lstm_w_hh = (const float*)d_in[23];
    const float* lstm_b_ih = (const float*)d_in[24];
    const float* lstm_b_hh = (const float*)d_in[25];
    float* out = (float*)d_out;

    cudaFuncSetAttribute(gemm_tc<0, 0, 0>, cudaFuncAttributeMaxDynamicSharedMemorySize, GTC_SMEM_TOTAL);
    cudaFuncSetAttribute(gemm_tc<0, 1, 0>, cudaFuncAttributeMaxDynamicSharedMemorySize, GTC_SMEM_TOTAL);
    cudaFuncSetAttribute(gemm_tc<1, 1, 0>, cudaFuncAttributeMaxDynamicSharedMemorySize, GTC_SMEM_TOTAL);
    cudaFuncSetAttribute(gemm_tc<2, 1, 0>, cudaFuncAttributeMaxDynamicSharedMemorySize, GTC_SMEM_TOTAL);
    cudaFuncSetAttribute(gemm_tc<2, 1, 1>, cudaFuncAttributeMaxDynamicSharedMemorySize, GTC_SMEM_TOTAL);
    cudaFuncSetAttribute(lstm_persist_tc, cudaFuncAttributeMaxDynamicSharedMemorySize, LSTM_SMEM_TOTAL);

    __half *csh, *h1h, *qkvh, *mlph, *gatesxh, *hstateh, *hstate2h, *wTh, *xbufh;
    float *modall, *adab, *cstate, *lstmbias;
    cudaGetSymbolAddress((void**)&csh, g_csh);
    cudaGetSymbolAddress((void**)&modall, g_modall);
    cudaGetSymbolAddress((void**)&adab, g_adab);
    cudaGetSymbolAddress((void**)&xbufh, g_xbufh);
    cudaGetSymbolAddress((void**)&h1h, g_h1h);
    cudaGetSymbolAddress((void**)&qkvh, g_qkvh);
    cudaGetSymbolAddress((void**)&mlph, g_mlph);
    cudaGetSymbolAddress((void**)&gatesxh, g_gatesxh);
    cudaGetSymbolAddress((void**)&hstateh, g_hstateh);
    cudaGetSymbolAddress((void**)&hstate2h, g_hstate2h);
    cudaGetSymbolAddress((void**)&cstate, g_cstate);
    cudaGetSymbolAddress((void**)&lstmbias, g_lstmbias);
    cudaGetSymbolAddress((void**)&wTh, g_wTh);

    float* rmod = modall + 12288;      // stride MODW

    const size_t MEG = 1048576;
    __half* wt_ada   = wTh + 0 * MEG;   // [15360,1024]: sada|tada|rada contiguous
    __half* wt_sqkv  = wTh + 15 * MEG;
    __half* wt_sout  = wTh + 18 * MEG;
    __half* wt_tqkv  = wTh + 19 * MEG;
    __half* wt_tout  = wTh + 22 * MEG;
    __half* wt_smlp1 = wTh + 23 * MEG;
    __half* wt_smlp2 = wTh + 27 * MEG;
    __half* wt_tmlp1 = wTh + 31 * MEG;
    __half* wt_tmlp2 = wTh + 35 * MEG;
    __half* wt_lih   = wTh + 39 * MEG;  // gate-interleaved [4096,1024]
    __half* wt_lhh   = wTh + 43 * MEG;  // gate-interleaved [4096,1024]

    // batched transpose: all 13 matrices, one launch
    {
        TransArgs ta;
        auto set = [&](int i, const float* W, __half* WT, int K, int N, int perm, int start) {
            ta.d[i].W = W; ta.d[i].WT = WT; ta.d[i].K = K; ta.d[i].N = N;
            ta.d[i].perm = perm; ta.d[i].tileStart = start;
        };
        int s = 0;
        set(0,  s_ada_w,  wt_ada,            1024, 6144, 0, s); s += (6144 / 32) * 32;
        set(1,  t_ada_w,  wt_ada + 6 * MEG,  1024, 6144, 0, s); s += (6144 / 32) * 32;
        set(2,  r_ada_w,  wt_ada + 12 * MEG, 1024, 3072, 0, s); s += (3072 / 32) * 32;
        set(3,  s_qkv_w,  wt_sqkv,  1024, 3072, 0, s); s += (3072 / 32) * 32;
        set(4,  s_out_w,  wt_sout,  1024, 1024, 0, s); s += (1024 / 32) * 32;
        set(5,  t_qkv_w,  wt_tqkv,  1024, 3072, 0, s); s += (3072 / 32) * 32;
        set(6,  t_out_w,  wt_tout,  1024, 1024, 0, s); s += (1024 / 32) * 32;
        set(7,  s_mlp_w1, wt_smlp1, 1024, 4096, 0, s); s += (4096 / 32) * 32;
        set(8,  s_mlp_w2, wt_smlp2, 4096, 1024, 0, s); s += (1024 / 32) * 128;
        set(9,  t_mlp_w1, wt_tmlp1, 1024, 4096, 0, s); s += (4096 / 32) * 32;
        set(10, t_mlp_w2, wt_tmlp2, 4096, 1024, 0, s); s += (1024 / 32) * 128;
        set(11, lstm_w_ih, wt_lih,  1024, 4096, 1, s); s += (4096 / 32) * 32;
        set(12, lstm_w_hh, wt_lhh,  1024, 4096, 1, s); s += (4096 / 32) * 32;
        transpose_all_kernel<<<s, 256>>>(ta);
    }

    // setup (silu + ada bias concat + lstm bias permute + barrier reset)
    setup_kernel<<<(NBT * DD + 255) / 256, 256>>>(c, csh, s_ada_b, t_ada_b, r_ada_b, adab,
                                                  lstm_b_ih, lstm_b_hh, lstmbias);
    gemm(csh, wt_ada, adab, modall, NBT, MODW, DD, 0, 0);

    // absolute offsets into a modall row:
    //   spatial:  shift_msa 0, scale_msa 1024, gate_msa 2048, shift_mlp 3072,
    //             scale_mlp 4096, gate_mlp 5120
    //   temporal: +6144;  recurrent: +12288

    // ---- spatial attention ----
    ln_mod_kernel<1><<<NTOK, 256>>>(x, modall, MODW, 0, 1024, h1h);
    gemm(h1h, wt_sqkv, nullptr, qkvh, NTOK, 3 * DD, DD, 0, 1);
    spatial_attn_tc<<<1024, 256>>>(qkvh, h1h);
    gemm_ga<1>(h1h, wt_sout, s_out_b, xbufh, NTOK, DD, DD, x, modall, 2048);
    ln_mod_kernel<0><<<NTOK, 256>>>(xbufh, modall, MODW, 3072, 4096, h1h);

    // ---- spatial MLP ----
    gemm(h1h, wt_smlp1, s_mlp_b1, mlph, NTOK, 4 * DD, DD, 1, 1);
    gemm_ga<0>(mlph, wt_smlp2, s_mlp_b2, xbufh, NTOK, DD, 4 * DD, xbufh, modall, 5120);
    ln_mod_kernel<0><<<NTOK, 256>>>(xbufh, modall, MODW, 6144, 7168, h1h);

    // ---- temporal attention (causal) ----
    gemm(h1h, wt_tqkv, nullptr, qkvh, NTOK, 3 * DD, DD, 0, 1);
    temporal_attn_kernel<<<8192, 128>>>(qkvh, h1h);
    gemm_ga<0>(h1h, wt_tout, t_out_b, xbufh, NTOK, DD, DD, xbufh, modall, 8192);
    ln_mod_kernel<0><<<NTOK, 256>>>(xbufh, modall, MODW, 9216, 10240, h1h);

    // ---- temporal MLP ----
    gemm(h1h, wt_tmlp1, t_mlp_b1, mlph, NTOK, 4 * DD, DD, 1, 1);
    gemm_ga<0>(mlph, wt_tmlp2, t_mlp_b2, xbufh, NTOK, DD, 4 * DD, xbufh, modall, 11264);
    ln_mod_kernel<0><<<NTOK, 256>>>(xbufh, modall, MODW, 12288, 13312, h1h);

    // ---- LSTM branch: persistent kernel, all 16 steps ----
    gemm(h1h, wt_lih, lstmbias, gatesxh, NTOK, 4 * DD, DD, 0, 1);
    lstm_persist_tc<<<dim3(32, 8), 128, LSTM_SMEM_TOTAL>>>(
        hstateh, hstate2h, wt_lhh, gatesxh, cstate, xbufh, rmod, out);
}